// round 2
// baseline (speedup 1.0000x reference)
#include <cuda_runtime.h>
#include <cstdint>
#include <cstddef>

// Problem dims
#define Bq 1024
#define Sq 200
#define Hq 256
#define Eq 128
#define Vq 100000

// ---------------- scratch (__device__ globals, module-load allocated) ----------
__device__ float g_WaT_top[Hq * Hq];          // (N=H, K=H)  : Wa[0:H, :]^T
__device__ float g_WaT_bot[Hq * Hq];          // (N=H, K=H)  : Wa[H:2H, :]^T
__device__ float g_hWa[Bq * Hq];              // h @ Wa_top + ba
__device__ float g_encWa[(size_t)Sq * Bq * Hq]; // 209.7 MB
__device__ float g_att[Bq * Sq];
__device__ float g_rnn_in[Bq * (Eq + Hq)];
__device__ float g_gi[Bq * 3 * Hq];
__device__ float g_gh[Bq * 3 * Hq];
__device__ float g_hnew[Bq * Hq];

// ---------------- generic NT SGEMM: C[M,N] = A[M,K] * B[N,K]^T + bias[N] -------
// A row-major (ld=K), B row-major (N,K) (ld=K), C row-major (ld=N).
// M % 128 == 0, K % 16 == 0 required. N guarded (partial last tile OK).
#define BM 128
#define BN 128
#define BKc 16
#define TM 8
#define TN 8

__global__ __launch_bounds__(256, 2)
void sgemm_nt(const float* __restrict__ A, const float* __restrict__ Bm,
              const float* __restrict__ bias, float* __restrict__ C,
              int M, int N, int K) {
    __shared__ float As[BKc][BM + 4];
    __shared__ float Bs[BKc][BN + 4];

    const int tid = threadIdx.x;
    const int bm = blockIdx.y * BM;
    const int bn = blockIdx.x * BN;
    const int tm0 = (tid >> 4) * TM;   // 16 row-groups
    const int tn0 = (tid & 15) * TN;   // 16 col-groups

    float acc[TM][TN];
#pragma unroll
    for (int i = 0; i < TM; i++)
#pragma unroll
        for (int j = 0; j < TN; j++) acc[i][j] = 0.0f;

    for (int kc = 0; kc < K; kc += BKc) {
        __syncthreads();
        // Load A tile: 128 rows x 16 k = 512 float4, 2 per thread
#pragma unroll
        for (int l = 0; l < 2; l++) {
            int q = tid + l * 256;
            int row = q >> 2;
            int kk = (q & 3) * 4;
            float4 va = *(const float4*)(A + (size_t)(bm + row) * K + kc + kk);
            As[kk + 0][row] = va.x;
            As[kk + 1][row] = va.y;
            As[kk + 2][row] = va.z;
            As[kk + 3][row] = va.w;
        }
        // Load B tile (guard N edge)
#pragma unroll
        for (int l = 0; l < 2; l++) {
            int q = tid + l * 256;
            int row = q >> 2;
            int kk = (q & 3) * 4;
            float4 vb = make_float4(0.f, 0.f, 0.f, 0.f);
            if (bn + row < N)
                vb = *(const float4*)(Bm + (size_t)(bn + row) * K + kc + kk);
            Bs[kk + 0][row] = vb.x;
            Bs[kk + 1][row] = vb.y;
            Bs[kk + 2][row] = vb.z;
            Bs[kk + 3][row] = vb.w;
        }
        __syncthreads();

#pragma unroll
        for (int k = 0; k < BKc; k++) {
            float4 a0 = *(const float4*)&As[k][tm0];
            float4 a1 = *(const float4*)&As[k][tm0 + 4];
            float4 b0 = *(const float4*)&Bs[k][tn0];
            float4 b1 = *(const float4*)&Bs[k][tn0 + 4];
            float ra[TM] = {a0.x, a0.y, a0.z, a0.w, a1.x, a1.y, a1.z, a1.w};
            float rb[TN] = {b0.x, b0.y, b0.z, b0.w, b1.x, b1.y, b1.z, b1.w};
#pragma unroll
            for (int i = 0; i < TM; i++)
#pragma unroll
                for (int j = 0; j < TN; j++)
                    acc[i][j] += ra[i] * rb[j];
        }
    }

    // epilogue
#pragma unroll
    for (int i = 0; i < TM; i++) {
        int m = bm + tm0 + i;
        float* crow = C + (size_t)m * N;
#pragma unroll
        for (int j = 0; j < TN; j++) {
            int n = bn + tn0 + j;
            if (n < N) {
                float b = bias ? bias[n] : 0.0f;
                crow[n] = acc[i][j] + b;
            }
        }
    }
}

// ---------------- Wa transpose: split (2H,H) row-major into two (N=H,K=H) ------
__global__ void transpose_wa(const float* __restrict__ Wa,
                             float* __restrict__ top, float* __restrict__ bot) {
    int idx = blockIdx.x * 256 + threadIdx.x;     // 2H*H = 131072
    if (idx >= 2 * Hq * Hq) return;
    int k = idx / Hq;
    int n = idx - k * Hq;
    float val = Wa[k * Hq + n];
    if (k < Hq) top[n * Hq + k] = val;
    else        bot[n * Hq + (k - Hq)] = val;
}

// ---------------- att[b,s] = mask ? v . tanh(encWa[s,b,:] + hWa_c[b,:]) : -1e6 -
__global__ void att_kernel(const float* __restrict__ encWa,
                           const float* __restrict__ hWa_c,
                           const float* __restrict__ v,
                           const int* __restrict__ mask,
                           float* __restrict__ att) {
    int row = blockIdx.x;               // s*B + b
    int s = row / Bq;
    int b = row - s * Bq;
    int j = threadIdx.x;

    float t = tanhf(encWa[(size_t)row * Hq + j] + hWa_c[b * Hq + j]) * v[j];

    // block reduce (256 threads)
    for (int o = 16; o > 0; o >>= 1) t += __shfl_down_sync(0xffffffffu, t, o);
    __shared__ float red[8];
    int lane = j & 31, wid = j >> 5;
    if (lane == 0) red[wid] = t;
    __syncthreads();
    if (wid == 0) {
        float s2 = (lane < 8) ? red[lane] : 0.0f;
        for (int o = 4; o > 0; o >>= 1) s2 += __shfl_down_sync(0xffu, s2, o);
        if (lane == 0)
            att[b * Sq + s] = (mask[b * Sq + s] == 0) ? -1000000.0f : s2;
    }
}

// ---------------- softmax over S per row b (in place) --------------------------
__global__ void softmax_kernel(float* __restrict__ att) {
    int b = blockIdx.x;
    int t = threadIdx.x;
    float x = (t < Sq) ? att[b * Sq + t] : -3.4e38f;

    __shared__ float red[8];
    int lane = t & 31, wid = t >> 5;

    // max reduce
    float m = x;
    for (int o = 16; o > 0; o >>= 1) m = fmaxf(m, __shfl_down_sync(0xffffffffu, m, o));
    if (lane == 0) red[wid] = m;
    __syncthreads();
    if (t == 0) {
        float mm = red[0];
        for (int w = 1; w < 8; w++) mm = fmaxf(mm, red[w]);
        red[0] = mm;
    }
    __syncthreads();
    m = red[0];
    __syncthreads();

    float e = (t < Sq) ? expf(x - m) : 0.0f;
    float sum = e;
    for (int o = 16; o > 0; o >>= 1) sum += __shfl_down_sync(0xffffffffu, sum, o);
    if (lane == 0) red[wid] = sum;
    __syncthreads();
    if (t == 0) {
        float ss = 0.0f;
        for (int w = 0; w < 8; w++) ss += red[w];
        red[0] = ss;
    }
    __syncthreads();
    float denom = red[0];

    if (t < Sq) att[b * Sq + t] = e / denom;
}

// ---------------- weighted sum + embedding gather -> rnn_in --------------------
__global__ void weighted_kernel(const float* __restrict__ att,
                                const float* __restrict__ enc,
                                const float* __restrict__ emb,
                                const int* __restrict__ loc,
                                float* __restrict__ rnn_in) {
    int b = blockIdx.x;
    int h = threadIdx.x;
    float acc = 0.0f;
#pragma unroll 4
    for (int s = 0; s < Sq; s++)
        acc += att[b * Sq + s] * enc[((size_t)s * Bq + b) * Hq + h];
    rnn_in[b * (Eq + Hq) + Eq + h] = acc;
    if (h < Eq)
        rnn_in[b * (Eq + Hq) + h] = emb[(size_t)loc[b] * Eq + h];
}

// ---------------- GRU gates ----------------------------------------------------
__global__ void gru_kernel(const float* __restrict__ gi, const float* __restrict__ gh,
                           const float* __restrict__ h,
                           float* __restrict__ hnew, float* __restrict__ out_h) {
    int b = blockIdx.x;
    int j = threadIdx.x;
    float ir = gi[b * 768 + j];
    float iz = gi[b * 768 + 256 + j];
    float in = gi[b * 768 + 512 + j];
    float hr = gh[b * 768 + j];
    float hz = gh[b * 768 + 256 + j];
    float hn = gh[b * 768 + 512 + j];
    float r = 1.0f / (1.0f + expf(-(ir + hr)));
    float z = 1.0f / (1.0f + expf(-(iz + hz)));
    float n = tanhf(in + r * hn);
    float hv = h[b * Hq + j];
    float hnv = (1.0f - z) * n + z * hv;
    hnew[b * Hq + j] = hnv;
    out_h[b * Hq + j] = hnv;
}

// ---------------- launch -------------------------------------------------------
extern "C" void kernel_launch(void* const* d_in, const int* in_sizes, int n_in,
                              void* d_out, int out_size) {
    const int*   input_loc = (const int*)d_in[0];
    const float* hidden    = (const float*)d_in[1];   // (1,B,H) -> B x H
    const float* enc       = (const float*)d_in[2];   // (S,B,H)
    const int*   mask      = (const int*)d_in[3];     // (B,S)
    const float* emb       = (const float*)d_in[4];   // (V,E)
    const float* Wa        = (const float*)d_in[5];   // (2H,H)
    const float* ba        = (const float*)d_in[6];   // (H)
    const float* v         = (const float*)d_in[7];   // (H)
    const float* W_ih      = (const float*)d_in[8];   // (3H, E+H)  (N,K)
    const float* W_hh      = (const float*)d_in[9];   // (3H, H)    (N,K)
    const float* b_ih      = (const float*)d_in[10];
    const float* b_hh      = (const float*)d_in[11];
    const float* W_out     = (const float*)d_in[12];  // (V, H)     (N,K)
    const float* b_out     = (const float*)d_in[13];
    float* out = (float*)d_out;
    float* out_pred = out;                                  // (B, V)
    float* out_h    = out + (size_t)Bq * Vq;                // (1, B, H)

    float *WaT_top, *WaT_bot, *hWa, *encWa, *att, *rnn_in, *gi, *gh, *hnew;
    cudaGetSymbolAddress((void**)&WaT_top, g_WaT_top);
    cudaGetSymbolAddress((void**)&WaT_bot, g_WaT_bot);
    cudaGetSymbolAddress((void**)&hWa,     g_hWa);
    cudaGetSymbolAddress((void**)&encWa,   g_encWa);
    cudaGetSymbolAddress((void**)&att,     g_att);
    cudaGetSymbolAddress((void**)&rnn_in,  g_rnn_in);
    cudaGetSymbolAddress((void**)&gi,      g_gi);
    cudaGetSymbolAddress((void**)&gh,      g_gh);
    cudaGetSymbolAddress((void**)&hnew,    g_hnew);

    // 1. split+transpose Wa
    transpose_wa<<<512, 256>>>(Wa, WaT_top, WaT_bot);

    // 2. hWa = h @ Wa_top + ba          (M=1024, N=256, K=256)
    sgemm_nt<<<dim3(2, Bq / BM), 256>>>(hidden, WaT_top, ba, hWa, Bq, Hq, Hq);

    // 3. encWa = enc @ Wa_bot           (M=204800, N=256, K=256)
    sgemm_nt<<<dim3(2, (Sq * Bq) / BM), 256>>>(enc, WaT_bot, nullptr, encWa,
                                               Sq * Bq, Hq, Hq);

    // 4. attention scores (fused tanh + v-dot + mask)
    att_kernel<<<Sq * Bq, 256>>>(encWa, hWa, v, mask, att);

    // 5. softmax over S
    softmax_kernel<<<Bq, 256>>>(att);

    // 6. weighted context + embedding gather -> rnn_in (B, E+H)
    weighted_kernel<<<Bq, Hq>>>(att, enc, emb, input_loc, rnn_in);

    // 7. gi = rnn_in @ W_ih^T + b_ih    (M=1024, N=768, K=384)
    sgemm_nt<<<dim3(6, Bq / BM), 256>>>(rnn_in, W_ih, b_ih, gi, Bq, 3 * Hq, Eq + Hq);

    // 8. gh = h @ W_hh^T + b_hh         (M=1024, N=768, K=256)
    sgemm_nt<<<dim3(6, Bq / BM), 256>>>(hidden, W_hh, b_hh, gh, Bq, 3 * Hq, Hq);

    // 9. GRU gates -> h_new (also written to output tail)
    gru_kernel<<<Bq, Hq>>>(gi, gh, hidden, hnew, out_h);

    // 10. pred = h_new @ W_out^T + b_out  (M=1024, N=100000, K=256)
    sgemm_nt<<<dim3((Vq + BN - 1) / BN, Bq / BM), 256>>>(hnew, W_out, b_out,
                                                         out_pred, Bq, Vq, Hq);
}

// round 3
// speedup vs baseline: 2.0363x; 2.0363x over previous
#include <cuda_runtime.h>
#include <cstdint>
#include <cstddef>

// Problem dims
#define Bq 1024
#define Sq 200
#define Hq 256
#define Eq 128
#define Vq 100000

// ---------------- scratch (__device__ globals) ---------------------------------
__device__ float g_WaT_top[Hq * Hq];
__device__ float g_WaT_bot[Hq * Hq];
__device__ float g_hWa[Bq * Hq];
__device__ float g_encWa[(size_t)Sq * Bq * Hq]; // 209.7 MB
__device__ float g_att[Bq * Sq];
__device__ float g_rnn_in[Bq * (Eq + Hq)];
__device__ float g_gi[Bq * 3 * Hq];
__device__ float g_gh[Bq * 3 * Hq];
__device__ float g_hnew[Bq * Hq];

// ---------------- tf32 helpers -------------------------------------------------
__device__ __forceinline__ uint32_t f2tf32(float f) {
    uint32_t u;
    asm("cvt.rna.tf32.f32 %0, %1;" : "=r"(u) : "f"(f));
    return u;
}

__device__ __forceinline__ void mma_tf32(float* c,
                                         uint32_t a0, uint32_t a1, uint32_t a2, uint32_t a3,
                                         uint32_t b0, uint32_t b1) {
    asm volatile(
        "mma.sync.aligned.m16n8k8.row.col.f32.tf32.tf32.f32 "
        "{%0,%1,%2,%3}, {%4,%5,%6,%7}, {%8,%9}, {%0,%1,%2,%3};\n"
        : "+f"(c[0]), "+f"(c[1]), "+f"(c[2]), "+f"(c[3])
        : "r"(a0), "r"(a1), "r"(a2), "r"(a3), "r"(b0), "r"(b1));
}

// ---------------- tf32 NT GEMM: C[M,N] = A[M,K] @ B[N,K]^T + bias --------------
// Block tile 128x256, 8 warps of 64x64, K-chunk 16.
// M % 128 == 0, K % 16 == 0. N ragged OK (B-load + C-store guarded).
// grid: (M/128, ceil(N/256))
#define TBK 16
#define AST 136   // 128 + 8  (stride ≡ 8 mod 32 words → conflict-free frag LDS)
#define BST 264   // 256 + 8

__global__ __launch_bounds__(256, 1)
void gemm_tf32(const float* __restrict__ A, const float* __restrict__ Bm,
               const float* __restrict__ bias, float* __restrict__ C,
               int M, int N, int K) {
    __shared__ uint32_t As[TBK * AST];
    __shared__ uint32_t Bs[TBK * BST];

    const int tid  = threadIdx.x;
    const int lane = tid & 31;
    const int warp = tid >> 5;
    const int wm = (warp >> 2) * 64;   // 2 warps along m
    const int wn = (warp & 3) * 64;    // 4 warps along n
    const int bm = blockIdx.x * 128;
    const int bn = blockIdx.y * 256;
    const int lq = lane >> 2;          // group id 0..7
    const int lr = lane & 3;           // thread-in-group 0..3

    float acc[4][8][4];
#pragma unroll
    for (int i = 0; i < 4; i++)
#pragma unroll
        for (int j = 0; j < 8; j++)
#pragma unroll
            for (int k = 0; k < 4; k++) acc[i][j][k] = 0.0f;

    // staging registers for global->smem
    float4 sa[2], sb[4];
    const int rowA = tid & 127;
    const int kgA0 = tid >> 7;                 // 0/1; kg = kgA0 + 2*i
    const float* Ag = A + (size_t)(bm + rowA) * K;
    const int rowB = tid;
    const bool bvalid = (bn + rowB) < N;
    const float* Bg = Bm + (size_t)(bn + rowB) * K;

#define LOAD_CHUNK(kc)                                                      \
    do {                                                                    \
        _Pragma("unroll")                                                   \
        for (int i = 0; i < 2; i++)                                         \
            sa[i] = *(const float4*)(Ag + (kc) + (kgA0 + 2 * i) * 4);       \
        _Pragma("unroll")                                                   \
        for (int i = 0; i < 4; i++)                                         \
            sb[i] = bvalid ? *(const float4*)(Bg + (kc) + i * 4)            \
                           : make_float4(0.f, 0.f, 0.f, 0.f);               \
    } while (0)

#define STORE_CHUNK()                                                       \
    do {                                                                    \
        _Pragma("unroll")                                                   \
        for (int i = 0; i < 2; i++) {                                       \
            int kg = kgA0 + 2 * i;                                          \
            As[(kg * 4 + 0) * AST + rowA] = f2tf32(sa[i].x);                \
            As[(kg * 4 + 1) * AST + rowA] = f2tf32(sa[i].y);                \
            As[(kg * 4 + 2) * AST + rowA] = f2tf32(sa[i].z);                \
            As[(kg * 4 + 3) * AST + rowA] = f2tf32(sa[i].w);                \
        }                                                                   \
        _Pragma("unroll")                                                   \
        for (int i = 0; i < 4; i++) {                                       \
            Bs[(i * 4 + 0) * BST + rowB] = f2tf32(sb[i].x);                 \
            Bs[(i * 4 + 1) * BST + rowB] = f2tf32(sb[i].y);                 \
            Bs[(i * 4 + 2) * BST + rowB] = f2tf32(sb[i].z);                 \
            Bs[(i * 4 + 3) * BST + rowB] = f2tf32(sb[i].w);                 \
        }                                                                   \
    } while (0)

    LOAD_CHUNK(0);
    STORE_CHUNK();
    __syncthreads();

    const int nchunk = K / TBK;
    for (int c = 0; c < nchunk; c++) {
        if (c + 1 < nchunk) LOAD_CHUNK((c + 1) * TBK);

#pragma unroll
        for (int ks = 0; ks < 2; ks++) {
            const int k0 = ks * 8;
            uint32_t bf[8][2];
#pragma unroll
            for (int nf = 0; nf < 8; nf++) {
                int col = wn + nf * 8 + lq;
                bf[nf][0] = Bs[(k0 + lr) * BST + col];
                bf[nf][1] = Bs[(k0 + 4 + lr) * BST + col];
            }
#pragma unroll
            for (int mf = 0; mf < 4; mf++) {
                int r = wm + mf * 16 + lq;
                uint32_t a0 = As[(k0 + lr) * AST + r];
                uint32_t a1 = As[(k0 + lr) * AST + r + 8];
                uint32_t a2 = As[(k0 + 4 + lr) * AST + r];
                uint32_t a3 = As[(k0 + 4 + lr) * AST + r + 8];
#pragma unroll
                for (int nf = 0; nf < 8; nf++)
                    mma_tf32(acc[mf][nf], a0, a1, a2, a3, bf[nf][0], bf[nf][1]);
            }
        }
        __syncthreads();
        if (c + 1 < nchunk) {
            STORE_CHUNK();
            __syncthreads();
        }
    }

    // epilogue: each c-frag holds rows {r, r+8}, cols {col, col+1}
#pragma unroll
    for (int mf = 0; mf < 4; mf++) {
        int r0 = bm + wm + mf * 16 + lq;
#pragma unroll
        for (int nf = 0; nf < 8; nf++) {
            int col = bn + wn + nf * 8 + lr * 2;
            if (col < N) {
                float b0 = bias ? bias[col] : 0.0f;
                float b1 = bias ? bias[col + 1] : 0.0f;
                float2 v0 = make_float2(acc[mf][nf][0] + b0, acc[mf][nf][1] + b1);
                float2 v1 = make_float2(acc[mf][nf][2] + b0, acc[mf][nf][3] + b1);
                *(float2*)(C + (size_t)r0 * N + col) = v0;
                *(float2*)(C + (size_t)(r0 + 8) * N + col) = v1;
            }
        }
    }
#undef LOAD_CHUNK
#undef STORE_CHUNK
}

// ---------------- fp32 SGEMM for the small GEMMs (unchanged from R1) -----------
#define BM 128
#define BN 128
#define BKc 16
#define TM 8
#define TN 8

__global__ __launch_bounds__(256, 2)
void sgemm_nt(const float* __restrict__ A, const float* __restrict__ Bm,
              const float* __restrict__ bias, float* __restrict__ C,
              int M, int N, int K) {
    __shared__ float As[BKc][BM + 4];
    __shared__ float Bs[BKc][BN + 4];

    const int tid = threadIdx.x;
    const int bm = blockIdx.y * BM;
    const int bn = blockIdx.x * BN;
    const int tm0 = (tid >> 4) * TM;
    const int tn0 = (tid & 15) * TN;

    float acc[TM][TN];
#pragma unroll
    for (int i = 0; i < TM; i++)
#pragma unroll
        for (int j = 0; j < TN; j++) acc[i][j] = 0.0f;

    for (int kc = 0; kc < K; kc += BKc) {
        __syncthreads();
#pragma unroll
        for (int l = 0; l < 2; l++) {
            int q = tid + l * 256;
            int row = q >> 2;
            int kk = (q & 3) * 4;
            float4 va = *(const float4*)(A + (size_t)(bm + row) * K + kc + kk);
            As[kk + 0][row] = va.x;
            As[kk + 1][row] = va.y;
            As[kk + 2][row] = va.z;
            As[kk + 3][row] = va.w;
        }
#pragma unroll
        for (int l = 0; l < 2; l++) {
            int q = tid + l * 256;
            int row = q >> 2;
            int kk = (q & 3) * 4;
            float4 vb = make_float4(0.f, 0.f, 0.f, 0.f);
            if (bn + row < N)
                vb = *(const float4*)(Bm + (size_t)(bn + row) * K + kc + kk);
            Bs[kk + 0][row] = vb.x;
            Bs[kk + 1][row] = vb.y;
            Bs[kk + 2][row] = vb.z;
            Bs[kk + 3][row] = vb.w;
        }
        __syncthreads();

#pragma unroll
        for (int k = 0; k < BKc; k++) {
            float4 a0 = *(const float4*)&As[k][tm0];
            float4 a1 = *(const float4*)&As[k][tm0 + 4];
            float4 b0 = *(const float4*)&Bs[k][tn0];
            float4 b1 = *(const float4*)&Bs[k][tn0 + 4];
            float ra[TM] = {a0.x, a0.y, a0.z, a0.w, a1.x, a1.y, a1.z, a1.w};
            float rb[TN] = {b0.x, b0.y, b0.z, b0.w, b1.x, b1.y, b1.z, b1.w};
#pragma unroll
            for (int i = 0; i < TM; i++)
#pragma unroll
                for (int j = 0; j < TN; j++)
                    acc[i][j] += ra[i] * rb[j];
        }
    }

#pragma unroll
    for (int i = 0; i < TM; i++) {
        int m = bm + tm0 + i;
        float* crow = C + (size_t)m * N;
#pragma unroll
        for (int j = 0; j < TN; j++) {
            int n = bn + tn0 + j;
            if (n < N) {
                float b = bias ? bias[n] : 0.0f;
                crow[n] = acc[i][j] + b;
            }
        }
    }
}

// ---------------- Wa transpose -------------------------------------------------
__global__ void transpose_wa(const float* __restrict__ Wa,
                             float* __restrict__ top, float* __restrict__ bot) {
    int idx = blockIdx.x * 256 + threadIdx.x;
    if (idx >= 2 * Hq * Hq) return;
    int k = idx / Hq;
    int n = idx - k * Hq;
    float val = Wa[k * Hq + n];
    if (k < Hq) top[n * Hq + k] = val;
    else        bot[n * Hq + (k - Hq)] = val;
}

// ---------------- att: warp per row, vectorized --------------------------------
__global__ __launch_bounds__(256)
void att_kernel(const float* __restrict__ encWa,
                const float* __restrict__ hWa_c,
                const float* __restrict__ v,
                const int* __restrict__ mask,
                float* __restrict__ att) {
    int row  = blockIdx.x * 8 + (threadIdx.x >> 5);   // s*B + b, < S*B
    int lane = threadIdx.x & 31;
    int s = row / Bq;
    int b = row - s * Bq;

    const float4* e  = (const float4*)(encWa + (size_t)row * Hq);
    const float4* hh = (const float4*)(hWa_c + (size_t)b * Hq);
    const float4* vv = (const float4*)v;

    float t = 0.0f;
#pragma unroll
    for (int i = 0; i < 2; i++) {
        int j = lane + i * 32;
        float4 ev = e[j], hv = hh[j], vf = vv[j];
        t += tanhf(ev.x + hv.x) * vf.x;
        t += tanhf(ev.y + hv.y) * vf.y;
        t += tanhf(ev.z + hv.z) * vf.z;
        t += tanhf(ev.w + hv.w) * vf.w;
    }
#pragma unroll
    for (int o = 16; o > 0; o >>= 1) t += __shfl_down_sync(0xffffffffu, t, o);
    if (lane == 0)
        att[b * Sq + s] = (mask[b * Sq + s] == 0) ? -1000000.0f : t;
}

// ---------------- softmax over S per row b (in place) --------------------------
__global__ void softmax_kernel(float* __restrict__ att) {
    int b = blockIdx.x;
    int t = threadIdx.x;
    float x = (t < Sq) ? att[b * Sq + t] : -3.4e38f;

    __shared__ float red[8];
    int lane = t & 31, wid = t >> 5;

    float m = x;
    for (int o = 16; o > 0; o >>= 1) m = fmaxf(m, __shfl_down_sync(0xffffffffu, m, o));
    if (lane == 0) red[wid] = m;
    __syncthreads();
    if (t == 0) {
        float mm = red[0];
        for (int w = 1; w < 8; w++) mm = fmaxf(mm, red[w]);
        red[0] = mm;
    }
    __syncthreads();
    m = red[0];
    __syncthreads();

    float e = (t < Sq) ? expf(x - m) : 0.0f;
    float sum = e;
    for (int o = 16; o > 0; o >>= 1) sum += __shfl_down_sync(0xffffffffu, sum, o);
    if (lane == 0) red[wid] = sum;
    __syncthreads();
    if (t == 0) {
        float ss = 0.0f;
        for (int w = 0; w < 8; w++) ss += red[w];
        red[0] = ss;
    }
    __syncthreads();
    float denom = red[0];

    if (t < Sq) att[b * Sq + t] = e / denom;
}

// ---------------- weighted sum + embedding gather -> rnn_in --------------------
__global__ void weighted_kernel(const float* __restrict__ att,
                                const float* __restrict__ enc,
                                const float* __restrict__ emb,
                                const int* __restrict__ loc,
                                float* __restrict__ rnn_in) {
    int b = blockIdx.x;
    int h = threadIdx.x;
    float acc = 0.0f;
#pragma unroll 4
    for (int s = 0; s < Sq; s++)
        acc += att[b * Sq + s] * enc[((size_t)s * Bq + b) * Hq + h];
    rnn_in[b * (Eq + Hq) + Eq + h] = acc;
    if (h < Eq)
        rnn_in[b * (Eq + Hq) + h] = emb[(size_t)loc[b] * Eq + h];
}

// ---------------- GRU gates ----------------------------------------------------
__global__ void gru_kernel(const float* __restrict__ gi, const float* __restrict__ gh,
                           const float* __restrict__ h,
                           float* __restrict__ hnew, float* __restrict__ out_h) {
    int b = blockIdx.x;
    int j = threadIdx.x;
    float ir = gi[b * 768 + j];
    float iz = gi[b * 768 + 256 + j];
    float in = gi[b * 768 + 512 + j];
    float hr = gh[b * 768 + j];
    float hz = gh[b * 768 + 256 + j];
    float hn = gh[b * 768 + 512 + j];
    float r = 1.0f / (1.0f + expf(-(ir + hr)));
    float z = 1.0f / (1.0f + expf(-(iz + hz)));
    float n = tanhf(in + r * hn);
    float hv = h[b * Hq + j];
    float hnv = (1.0f - z) * n + z * hv;
    hnew[b * Hq + j] = hnv;
    out_h[b * Hq + j] = hnv;
}

// ---------------- launch -------------------------------------------------------
extern "C" void kernel_launch(void* const* d_in, const int* in_sizes, int n_in,
                              void* d_out, int out_size) {
    const int*   input_loc = (const int*)d_in[0];
    const float* hidden    = (const float*)d_in[1];
    const float* enc       = (const float*)d_in[2];
    const int*   mask      = (const int*)d_in[3];
    const float* emb       = (const float*)d_in[4];
    const float* Wa        = (const float*)d_in[5];
    const float* ba        = (const float*)d_in[6];
    const float* v         = (const float*)d_in[7];
    const float* W_ih      = (const float*)d_in[8];
    const float* W_hh      = (const float*)d_in[9];
    const float* b_ih      = (const float*)d_in[10];
    const float* b_hh      = (const float*)d_in[11];
    const float* W_out     = (const float*)d_in[12];
    const float* b_out     = (const float*)d_in[13];
    float* out = (float*)d_out;
    float* out_pred = out;
    float* out_h    = out + (size_t)Bq * Vq;

    float *WaT_top, *WaT_bot, *hWa, *encWa, *att, *rnn_in, *gi, *gh, *hnew;
    cudaGetSymbolAddress((void**)&WaT_top, g_WaT_top);
    cudaGetSymbolAddress((void**)&WaT_bot, g_WaT_bot);
    cudaGetSymbolAddress((void**)&hWa,     g_hWa);
    cudaGetSymbolAddress((void**)&encWa,   g_encWa);
    cudaGetSymbolAddress((void**)&att,     g_att);
    cudaGetSymbolAddress((void**)&rnn_in,  g_rnn_in);
    cudaGetSymbolAddress((void**)&gi,      g_gi);
    cudaGetSymbolAddress((void**)&gh,      g_gh);
    cudaGetSymbolAddress((void**)&hnew,    g_hnew);

    // 1. split+transpose Wa
    transpose_wa<<<512, 256>>>(Wa, WaT_top, WaT_bot);

    // 2. hWa = h @ Wa_top + ba          (1024 x 256 x 256, fp32)
    sgemm_nt<<<dim3(2, Bq / BM), 256>>>(hidden, WaT_top, ba, hWa, Bq, Hq, Hq);

    // 3. encWa = enc @ Wa_bot           (204800 x 256 x 256, tf32 tensor)
    gemm_tf32<<<dim3((Sq * Bq) / 128, 1), 256>>>(enc, WaT_bot, nullptr, encWa,
                                                 Sq * Bq, Hq, Hq);

    // 4. attention scores (warp/row)
    att_kernel<<<(Sq * Bq) / 8, 256>>>(encWa, hWa, v, mask, att);

    // 5. softmax over S
    softmax_kernel<<<Bq, 256>>>(att);

    // 6. weighted context + embedding gather
    weighted_kernel<<<Bq, Hq>>>(att, enc, emb, input_loc, rnn_in);

    // 7. gi = rnn_in @ W_ih^T + b_ih    (fp32)
    sgemm_nt<<<dim3(6, Bq / BM), 256>>>(rnn_in, W_ih, b_ih, gi, Bq, 3 * Hq, Eq + Hq);

    // 8. gh = h @ W_hh^T + b_hh         (fp32)
    sgemm_nt<<<dim3(6, Bq / BM), 256>>>(hidden, W_hh, b_hh, gh, Bq, 3 * Hq, Hq);

    // 9. GRU gates -> h_new
    gru_kernel<<<Bq, Hq>>>(gi, gh, hidden, hnew, out_h);

    // 10. pred = h_new @ W_out^T + b_out  (1024 x 100000 x 256, tf32 tensor)
    //     grid x = m-tiles so the 8 blocks sharing a W_out tile are adjacent.
    gemm_tf32<<<dim3(Bq / 128, (Vq + 255) / 256), 256>>>(hnew, W_out, b_out,
                                                         out_pred, Bq, Vq, Hq);
}

// round 5
// speedup vs baseline: 2.5831x; 1.2686x over previous
#include <cuda_runtime.h>
#include <cuda_fp16.h>
#include <cstdint>
#include <cstddef>

// Problem dims
#define Bq 1024
#define Sq 200
#define Hq 256
#define Eq 128
#define Vq 100000

// ---------------- scratch (__device__ globals) ---------------------------------
__device__ float g_WaT_top[Hq * Hq];
__device__ float g_WaT_bot[Hq * Hq];
__device__ float g_hWa[Bq * Hq];
__device__ float g_att[Bq * Sq];
__device__ float g_rnn_in[Bq * (Eq + Hq)];
__device__ float g_gi[Bq * 3 * Hq];
__device__ float g_gh[Bq * 3 * Hq];
__device__ float g_hnew[Bq * Hq];

// ---------------- helpers ------------------------------------------------------
__device__ __forceinline__ uint32_t f2h2(float x, float y) {
    __half2 h = __floats2half2_rn(x, y);
    return *(uint32_t*)&h;
}

__device__ __forceinline__ void mma_fp16(float* c,
                                         uint32_t a0, uint32_t a1, uint32_t a2, uint32_t a3,
                                         uint32_t b0, uint32_t b1) {
    asm volatile(
        "mma.sync.aligned.m16n8k16.row.col.f32.f16.f16.f32 "
        "{%0,%1,%2,%3}, {%4,%5,%6,%7}, {%8,%9}, {%0,%1,%2,%3};\n"
        : "+f"(c[0]), "+f"(c[1]), "+f"(c[2]), "+f"(c[3])
        : "r"(a0), "r"(a1), "r"(a2), "r"(a3), "r"(b0), "r"(b1));
}

// swizzled half2 index inside a tile row (stride 12 half2, 8 data slots)
__device__ __forceinline__ int sidx(int row, int k2) {
    return row * 12 + ((k2 + (row >> 3)) & 7);
}

// ---------------- fp16 NT GEMM: C[M,N] = A[M,K] @ B[N,K]^T (+bias) -------------
// fp32 in/out, fp16 compute, fp32 accumulate. Block 128x256, 8 warps 64x64,
// K-chunk 16, double-buffered smem. M%128==0, K%16==0. N ragged OK.
// FUSE==1: no C store; instead att[b,s] = mask? v . tanh(row + hWa[b,:]) : -1e6
// (requires N==256, bn==0, row index = s*Bq + b).
template <int FUSE>
__global__ __launch_bounds__(256, 1)
void gemm_fp16(const float* __restrict__ A, const float* __restrict__ Bm,
               const float* __restrict__ bias, float* __restrict__ C,
               int M, int N, int K,
               const float* __restrict__ hWa, const float* __restrict__ vvec,
               const int* __restrict__ mask, float* __restrict__ att) {
    __shared__ uint32_t As[2][128 * 12];
    __shared__ uint32_t Bs[2][256 * 12];
    __shared__ float rowsum[128];

    const int tid  = threadIdx.x;
    const int lane = tid & 31;
    const int warp = tid >> 5;
    const int wm = (warp >> 2) * 64;
    const int wn = (warp & 3) * 64;
    const int bm = blockIdx.x * 128;
    const int bn = blockIdx.y * 256;
    const int lq = lane >> 2;
    const int lr = lane & 3;

    if (FUSE && tid < 128) rowsum[tid] = 0.0f;

    float acc[4][8][4];
#pragma unroll
    for (int i = 0; i < 4; i++)
#pragma unroll
        for (int j = 0; j < 8; j++)
#pragma unroll
            for (int k = 0; k < 4; k++) acc[i][j][k] = 0.0f;

    // global staging
    float4 sa[2], sb[4];
    const int rowA = tid >> 1;
    const int khA  = tid & 1;                  // which 8-float half of the k-chunk
    const float* Ag = A + (size_t)(bm + rowA) * K + khA * 8;
    const int rowB = tid;
    const bool bvalid = (bn + rowB) < N;
    const float* Bg = Bm + (size_t)(bn + rowB) * K;

#define LOADG(kc)                                                           \
    do {                                                                    \
        sa[0] = *(const float4*)(Ag + (kc));                                \
        sa[1] = *(const float4*)(Ag + (kc) + 4);                            \
        _Pragma("unroll")                                                   \
        for (int i = 0; i < 4; i++)                                         \
            sb[i] = bvalid ? *(const float4*)(Bg + (kc) + i * 4)            \
                           : make_float4(0.f, 0.f, 0.f, 0.f);               \
    } while (0)

#define STORE(p)                                                            \
    do {                                                                    \
        As[p][sidx(rowA, khA * 4 + 0)] = f2h2(sa[0].x, sa[0].y);            \
        As[p][sidx(rowA, khA * 4 + 1)] = f2h2(sa[0].z, sa[0].w);            \
        As[p][sidx(rowA, khA * 4 + 2)] = f2h2(sa[1].x, sa[1].y);            \
        As[p][sidx(rowA, khA * 4 + 3)] = f2h2(sa[1].z, sa[1].w);            \
        _Pragma("unroll")                                                   \
        for (int i = 0; i < 4; i++) {                                       \
            Bs[p][sidx(rowB, i * 2 + 0)] = f2h2(sb[i].x, sb[i].y);          \
            Bs[p][sidx(rowB, i * 2 + 1)] = f2h2(sb[i].z, sb[i].w);          \
        }                                                                   \
    } while (0)

    LOADG(0);
    STORE(0);
    __syncthreads();

    const int nchunk = K / 16;
    for (int c = 0; c < nchunk; c++) {
        const int p = c & 1;
        if (c + 1 < nchunk) LOADG((c + 1) * 16);

        uint32_t bf[8][2];
#pragma unroll
        for (int nf = 0; nf < 8; nf++) {
            int col = wn + nf * 8 + lq;
            bf[nf][0] = Bs[p][sidx(col, lr)];
            bf[nf][1] = Bs[p][sidx(col, 4 + lr)];
        }
#pragma unroll
        for (int mf = 0; mf < 4; mf++) {
            int r = wm + mf * 16 + lq;
            uint32_t a0 = As[p][sidx(r, lr)];
            uint32_t a1 = As[p][sidx(r + 8, lr)];
            uint32_t a2 = As[p][sidx(r, 4 + lr)];
            uint32_t a3 = As[p][sidx(r + 8, 4 + lr)];
#pragma unroll
            for (int nf = 0; nf < 8; nf++)
                mma_fp16(acc[mf][nf], a0, a1, a2, a3, bf[nf][0], bf[nf][1]);
        }

        if (c + 1 < nchunk) STORE((c + 1) & 1);
        __syncthreads();
    }
#undef LOADG
#undef STORE

    if (FUSE) {
        // att epilogue: per-row v . tanh(row + hWa[b,:]) with mask
#pragma unroll
        for (int mf = 0; mf < 4; mf++) {
            int r0g = bm + wm + mf * 16 + lq;
            int b0 = r0g & (Bq - 1);
            int b1 = (r0g + 8) & (Bq - 1);
            float p0 = 0.0f, p1 = 0.0f;
#pragma unroll
            for (int nf = 0; nf < 8; nf++) {
#pragma unroll
                for (int c2 = 0; c2 < 2; c2++) {
                    int col = wn + nf * 8 + lr * 2 + c2;
                    float vv = vvec[col];
                    p0 += tanhf(acc[mf][nf][c2]     + hWa[b0 * Hq + col]) * vv;
                    p1 += tanhf(acc[mf][nf][2 + c2] + hWa[b1 * Hq + col]) * vv;
                }
            }
            // reduce over lr (lanes xor 1, 2)
            p0 += __shfl_xor_sync(0xffffffffu, p0, 1);
            p0 += __shfl_xor_sync(0xffffffffu, p0, 2);
            p1 += __shfl_xor_sync(0xffffffffu, p1, 1);
            p1 += __shfl_xor_sync(0xffffffffu, p1, 2);
            if (lr == 0) {
                atomicAdd(&rowsum[wm + mf * 16 + lq], p0);
                atomicAdd(&rowsum[wm + mf * 16 + lq + 8], p1);
            }
        }
        __syncthreads();
        if (tid < 128) {
            int row = bm + tid;            // = s*Bq + b
            int s = row >> 10;
            int b = row & (Bq - 1);
            att[b * Sq + s] = (mask[b * Sq + s] == 0) ? -1000000.0f : rowsum[tid];
        }
    } else {
#pragma unroll
        for (int mf = 0; mf < 4; mf++) {
            int r0 = bm + wm + mf * 16 + lq;
#pragma unroll
            for (int nf = 0; nf < 8; nf++) {
                int col = bn + wn + nf * 8 + lr * 2;
                if (col < N) {
                    float b0 = bias ? bias[col] : 0.0f;
                    float b1 = bias ? bias[col + 1] : 0.0f;
                    *(float2*)(C + (size_t)r0 * N + col) =
                        make_float2(acc[mf][nf][0] + b0, acc[mf][nf][1] + b1);
                    *(float2*)(C + (size_t)(r0 + 8) * N + col) =
                        make_float2(acc[mf][nf][2] + b0, acc[mf][nf][3] + b1);
                }
            }
        }
    }
}

// ---------------- Wa transpose -------------------------------------------------
__global__ void transpose_wa(const float* __restrict__ Wa,
                             float* __restrict__ top, float* __restrict__ bot) {
    int idx = blockIdx.x * 256 + threadIdx.x;
    if (idx >= 2 * Hq * Hq) return;
    int k = idx / Hq;
    int n = idx - k * Hq;
    float val = Wa[k * Hq + n];
    if (k < Hq) top[n * Hq + k] = val;
    else        bot[n * Hq + (k - Hq)] = val;
}

// ---------------- softmax over S per row b (in place) --------------------------
__global__ void softmax_kernel(float* __restrict__ att) {
    int b = blockIdx.x;
    int t = threadIdx.x;
    float x = (t < Sq) ? att[b * Sq + t] : -3.4e38f;

    __shared__ float red[8];
    int lane = t & 31, wid = t >> 5;

    float m = x;
    for (int o = 16; o > 0; o >>= 1) m = fmaxf(m, __shfl_down_sync(0xffffffffu, m, o));
    if (lane == 0) red[wid] = m;
    __syncthreads();
    if (t == 0) {
        float mm = red[0];
        for (int w = 1; w < 8; w++) mm = fmaxf(mm, red[w]);
        red[0] = mm;
    }
    __syncthreads();
    m = red[0];
    __syncthreads();

    float e = (t < Sq) ? expf(x - m) : 0.0f;
    float sum = e;
    for (int o = 16; o > 0; o >>= 1) sum += __shfl_down_sync(0xffffffffu, sum, o);
    if (lane == 0) red[wid] = sum;
    __syncthreads();
    if (t == 0) {
        float ss = 0.0f;
        for (int w = 0; w < 8; w++) ss += red[w];
        red[0] = ss;
    }
    __syncthreads();
    float denom = red[0];

    if (t < Sq) att[b * Sq + t] = e / denom;
}

// ---------------- weighted sum + embedding gather -> rnn_in --------------------
__global__ __launch_bounds__(256)
void weighted_kernel(const float* __restrict__ att,
                     const float* __restrict__ enc,
                     const float* __restrict__ emb,
                     const int* __restrict__ loc,
                     float* __restrict__ rnn_in) {
    int b = blockIdx.x;
    int t = threadIdx.x;
    __shared__ float satt[Sq];
    __shared__ float4 red4[256];
    if (t < Sq) satt[t] = att[b * Sq + t];
    __syncthreads();

    int sp = t >> 6;        // 0..3
    int hq = t & 63;        // float4 index within H
    const float4* enc4 = (const float4*)enc;
    float4 acc = make_float4(0.f, 0.f, 0.f, 0.f);
    for (int s = sp; s < Sq; s += 4) {
        float w = satt[s];
        float4 e = enc4[((size_t)s * Bq + b) * 64 + hq];
        acc.x += w * e.x; acc.y += w * e.y; acc.z += w * e.z; acc.w += w * e.w;
    }
    red4[t] = acc;
    __syncthreads();

    float4* rnn4 = (float4*)(rnn_in + (size_t)b * (Eq + Hq));
    if (t < 64) {
        float4 a0 = red4[t], a1 = red4[64 + t], a2 = red4[128 + t], a3 = red4[192 + t];
        rnn4[32 + t] = make_float4(a0.x + a1.x + a2.x + a3.x,
                                   a0.y + a1.y + a2.y + a3.y,
                                   a0.z + a1.z + a2.z + a3.z,
                                   a0.w + a1.w + a2.w + a3.w);
    } else if (t < 96) {
        rnn4[t - 64] = ((const float4*)emb)[(size_t)loc[b] * 32 + (t - 64)];
    }
}

// ---------------- GRU gates ----------------------------------------------------
__global__ void gru_kernel(const float* __restrict__ gi, const float* __restrict__ gh,
                           const float* __restrict__ h,
                           float* __restrict__ hnew, float* __restrict__ out_h) {
    int b = blockIdx.x;
    int j = threadIdx.x;
    float ir = gi[b * 768 + j];
    float iz = gi[b * 768 + 256 + j];
    float in = gi[b * 768 + 512 + j];
    float hr = gh[b * 768 + j];
    float hz = gh[b * 768 + 256 + j];
    float hn = gh[b * 768 + 512 + j];
    float r = 1.0f / (1.0f + expf(-(ir + hr)));
    float z = 1.0f / (1.0f + expf(-(iz + hz)));
    float n = tanhf(in + r * hn);
    float hv = h[b * Hq + j];
    float hnv = (1.0f - z) * n + z * hv;
    hnew[b * Hq + j] = hnv;
    out_h[b * Hq + j] = hnv;
}

// ---------------- launch -------------------------------------------------------
extern "C" void kernel_launch(void* const* d_in, const int* in_sizes, int n_in,
                              void* d_out, int out_size) {
    const int*   input_loc = (const int*)d_in[0];
    const float* hidden    = (const float*)d_in[1];
    const float* enc       = (const float*)d_in[2];
    const int*   mask      = (const int*)d_in[3];
    const float* emb       = (const float*)d_in[4];
    const float* Wa        = (const float*)d_in[5];
    const float* ba        = (const float*)d_in[6];
    const float* v         = (const float*)d_in[7];
    const float* W_ih      = (const float*)d_in[8];
    const float* W_hh      = (const float*)d_in[9];
    const float* b_ih      = (const float*)d_in[10];
    const float* b_hh      = (const float*)d_in[11];
    const float* W_out     = (const float*)d_in[12];
    const float* b_out     = (const float*)d_in[13];
    float* out = (float*)d_out;
    float* out_pred = out;
    float* out_h    = out + (size_t)Bq * Vq;

    float *WaT_top, *WaT_bot, *hWa, *att, *rnn_in, *gi, *gh, *hnew;
    cudaGetSymbolAddress((void**)&WaT_top, g_WaT_top);
    cudaGetSymbolAddress((void**)&WaT_bot, g_WaT_bot);
    cudaGetSymbolAddress((void**)&hWa,     g_hWa);
    cudaGetSymbolAddress((void**)&att,     g_att);
    cudaGetSymbolAddress((void**)&rnn_in,  g_rnn_in);
    cudaGetSymbolAddress((void**)&gi,      g_gi);
    cudaGetSymbolAddress((void**)&gh,      g_gh);
    cudaGetSymbolAddress((void**)&hnew,    g_hnew);

    // 1. split+transpose Wa
    transpose_wa<<<512, 256>>>(Wa, WaT_top, WaT_bot);

    // 2. hWa = h @ Wa_top + ba          (1024 x 256 x 256)
    gemm_fp16<0><<<dim3(Bq / 128, 1), 256>>>(hidden, WaT_top, ba, hWa,
                                             Bq, Hq, Hq,
                                             nullptr, nullptr, nullptr, nullptr);

    // 3+4. fused: att = mask ? v . tanh(enc@Wa_bot + hWa) : -1e6
    gemm_fp16<1><<<dim3((Sq * Bq) / 128, 1), 256>>>(enc, WaT_bot, nullptr, nullptr,
                                                    Sq * Bq, Hq, Hq,
                                                    hWa, v, mask, att);

    // 5. softmax over S
    softmax_kernel<<<Bq, 256>>>(att);

    // 6. weighted context + embedding gather
    weighted_kernel<<<Bq, 256>>>(att, enc, emb, input_loc, rnn_in);

    // 7. gi = rnn_in @ W_ih^T + b_ih    (1024 x 768 x 384)
    gemm_fp16<0><<<dim3(Bq / 128, 3), 256>>>(rnn_in, W_ih, b_ih, gi,
                                             Bq, 3 * Hq, Eq + Hq,
                                             nullptr, nullptr, nullptr, nullptr);

    // 8. gh = h @ W_hh^T + b_hh         (1024 x 768 x 256)
    gemm_fp16<0><<<dim3(Bq / 128, 3), 256>>>(hidden, W_hh, b_hh, gh,
                                             Bq, 3 * Hq, Hq,
                                             nullptr, nullptr, nullptr, nullptr);

    // 9. GRU gates -> h_new
    gru_kernel<<<Bq, Hq>>>(gi, gh, hidden, hnew, out_h);

    // 10. pred = h_new @ W_out^T + b_out  (1024 x 100000 x 256)
    gemm_fp16<0><<<dim3(Bq / 128, (Vq + 255) / 256), 256>>>(hnew, W_out, b_out,
                                                            out_pred, Bq, Vq, Hq,
                                                            nullptr, nullptr, nullptr, nullptr);
}

// round 8
// speedup vs baseline: 2.8208x; 1.0920x over previous
#include <cuda_runtime.h>
#include <cuda_fp16.h>
#include <cstdint>
#include <cstddef>

// Problem dims
#define Bq 1024
#define Sq 200
#define Hq 256
#define Eq 128
#define Vq 100000

// ---------------- scratch (__device__ globals) ---------------------------------
__device__ float g_WaT_top[Hq * Hq];
__device__ float g_WaT_bot[Hq * Hq];
__device__ float g_hWa[Bq * Hq];
__device__ float g_att[Bq * Sq];
__device__ float g_rnn_in[Bq * (Eq + Hq)];
__device__ float g_gi[Bq * 3 * Hq];
__device__ float g_gh[Bq * 3 * Hq];
__device__ float g_hnew[Bq * Hq];

// ---------------- helpers ------------------------------------------------------
__device__ __forceinline__ uint32_t f2h2(float x, float y) {
    __half2 h = __floats2half2_rn(x, y);
    return *(uint32_t*)&h;
}

__device__ __forceinline__ uint32_t smem_u32(const void* p) {
    uint32_t a;
    asm("{ .reg .u64 t; cvta.to.shared.u64 t, %1; cvt.u32.u64 %0, t; }"
        : "=r"(a) : "l"(p));
    return a;
}

__device__ __forceinline__ void mma_fp16(float* c,
                                         uint32_t a0, uint32_t a1, uint32_t a2, uint32_t a3,
                                         uint32_t b0, uint32_t b1) {
    asm volatile(
        "mma.sync.aligned.m16n8k16.row.col.f32.f16.f16.f32 "
        "{%0,%1,%2,%3}, {%4,%5,%6,%7}, {%8,%9}, {%0,%1,%2,%3};\n"
        : "+f"(c[0]), "+f"(c[1]), "+f"(c[2]), "+f"(c[3])
        : "r"(a0), "r"(a1), "r"(a2), "r"(a3), "r"(b0), "r"(b1));
}

#define LDMX4(r0, r1, r2, r3, a)                                                \
    asm volatile("ldmatrix.sync.aligned.m8n8.x4.shared.b16 {%0,%1,%2,%3}, [%4];" \
                 : "=r"(r0), "=r"(r1), "=r"(r2), "=r"(r3) : "r"(a))

// ---------------- fp16 NT GEMM via ldmatrix + mma.sync -------------------------
// C[M,N] = A[M,K] @ B[N,K]^T (+bias). fp32 in/out, fp16 mma, fp32 accum.
// Block tile 128x256 (8 warps of 64x64), K-chunk 32, double-buffered dynamic smem.
// Rows stored with 80-byte stride (20 words): bank-conflict-free ldmatrix & STS.
// M%128==0, K%32==0, N ragged OK.
// FUSE==1: att epilogue (N==256, bn==0, global row = s*Bq + b).
#define GA0 0
#define GA1 10240
#define GB0 20480
#define GB1 40960
#define GTOT 61440

template <int FUSE>
__global__ __launch_bounds__(256, 1)
void mma_gemm(const float* __restrict__ A, const float* __restrict__ Bm,
              const float* __restrict__ bias, float* __restrict__ C,
              int M, int N, int K,
              const float* __restrict__ hWa, const float* __restrict__ vvec,
              const int* __restrict__ mask, float* __restrict__ att) {
    extern __shared__ char smem[];
    const uint32_t sbase = smem_u32(smem);

    const int tid  = threadIdx.x;
    const int lane = tid & 31;
    const int warp = tid >> 5;
    const int wm = (warp >> 2) * 64;
    const int wn = (warp & 3) * 64;
    const int bm = blockIdx.x * 128;
    const int bn = blockIdx.y * 256;
    const int lq = lane >> 2;
    const int lr = lane & 3;

    __shared__ float rowsum[128];
    if (FUSE && tid < 128) rowsum[tid] = 0.0f;

    // per-lane ldmatrix byte offsets (within a buffer)
    const int rin = lane & 7;
    uint32_t a_l[4], b_l[4];
    {
        const int r8   = (lane >> 3) & 1;   // A: +8 rows for matrices 1,3
        const int kh_a = (lane >> 4) & 1;   // A: k-half for matrices 2,3
        const int n8   = (lane >> 4) & 1;   // B: +8 cols for matrices 2,3
        const int kh_b = (lane >> 3) & 1;   // B: k-half for matrices 1,3
#pragma unroll
        for (int mf = 0; mf < 4; mf++)
            a_l[mf] = (uint32_t)((wm + mf * 16 + r8 * 8 + rin) * 80 + kh_a * 16);
#pragma unroll
        for (int p2 = 0; p2 < 4; p2++)
            b_l[p2] = (uint32_t)((wn + p2 * 16 + n8 * 8 + rin) * 80 + kh_b * 16);
    }

    float acc[4][8][4];
#pragma unroll
    for (int i = 0; i < 4; i++)
#pragma unroll
        for (int j = 0; j < 8; j++)
#pragma unroll
            for (int k = 0; k < 4; k++) acc[i][j][k] = 0.0f;

    // global load roles
    const int  browg  = bn + tid;
    const bool bvalid = browg < N;
    const float4* Bg  = (const float4*)(Bm + (size_t)browg * K);
    const int  arow = tid >> 1;
    const int  ah   = tid & 1;
    const float4* Ag = (const float4*)(A + (size_t)(bm + arow) * K) + ah * 4;

    float4 sb[8], sa[4];

#define LOADG(c)                                                            \
    do {                                                                    \
        _Pragma("unroll")                                                   \
        for (int i = 0; i < 8; i++)                                         \
            sb[i] = bvalid ? Bg[(c) * 8 + i] : make_float4(0.f, 0.f, 0.f, 0.f); \
        _Pragma("unroll")                                                   \
        for (int i = 0; i < 4; i++)                                         \
            sa[i] = Ag[(c) * 8 + i];                                        \
    } while (0)

#define STS(p)                                                              \
    do {                                                                    \
        char* bB = smem + ((p) ? GB1 : GB0) + tid * 80;                     \
        _Pragma("unroll")                                                   \
        for (int i = 0; i < 4; i++) {                                       \
            uint4 h;                                                        \
            h.x = f2h2(sb[2 * i].x, sb[2 * i].y);                           \
            h.y = f2h2(sb[2 * i].z, sb[2 * i].w);                           \
            h.z = f2h2(sb[2 * i + 1].x, sb[2 * i + 1].y);                   \
            h.w = f2h2(sb[2 * i + 1].z, sb[2 * i + 1].w);                   \
            *(uint4*)(bB + i * 16) = h;                                     \
        }                                                                   \
        char* bA = smem + ((p) ? GA1 : GA0) + arow * 80 + ah * 32;          \
        _Pragma("unroll")                                                   \
        for (int i = 0; i < 2; i++) {                                       \
            uint4 h;                                                        \
            h.x = f2h2(sa[2 * i].x, sa[2 * i].y);                           \
            h.y = f2h2(sa[2 * i].z, sa[2 * i].w);                           \
            h.z = f2h2(sa[2 * i + 1].x, sa[2 * i + 1].y);                   \
            h.w = f2h2(sa[2 * i + 1].z, sa[2 * i + 1].w);                   \
            *(uint4*)(bA + i * 16) = h;                                     \
        }                                                                   \
    } while (0)

    LOADG(0);
    STS(0);
    __syncthreads();

    const int nch = K / 32;
    for (int c = 0; c < nch; c++) {
        const int p = c & 1;
        if (c + 1 < nch) LOADG(c + 1);

        const uint32_t aA = sbase + (p ? GA1 : GA0);
        const uint32_t aB = sbase + (p ? GB1 : GB0);

#pragma unroll
        for (int ks = 0; ks < 2; ks++) {
            uint32_t bf[8][2];
#pragma unroll
            for (int p2 = 0; p2 < 4; p2++)
                LDMX4(bf[2 * p2][0], bf[2 * p2][1], bf[2 * p2 + 1][0], bf[2 * p2 + 1][1],
                      aB + b_l[p2] + ks * 32);
#pragma unroll
            for (int mf = 0; mf < 4; mf++) {
                uint32_t a0, a1, a2, a3;
                LDMX4(a0, a1, a2, a3, aA + a_l[mf] + ks * 32);
#pragma unroll
                for (int nf = 0; nf < 8; nf++)
                    mma_fp16(acc[mf][nf], a0, a1, a2, a3, bf[nf][0], bf[nf][1]);
            }
        }

        if (c + 1 < nch) STS((c + 1) & 1);
        __syncthreads();
    }
#undef LOADG
#undef STS

    if (FUSE) {
        // att epilogue: per-row v . tanh(row + hWa[b,:]) with mask
#pragma unroll
        for (int mf = 0; mf < 4; mf++) {
            int r0g = bm + wm + mf * 16 + lq;
            int b0 = r0g & (Bq - 1);
            int b1 = (r0g + 8) & (Bq - 1);
            float p0 = 0.0f, p1 = 0.0f;
#pragma unroll
            for (int nf = 0; nf < 8; nf++) {
#pragma unroll
                for (int c2 = 0; c2 < 2; c2++) {
                    int col = wn + nf * 8 + lr * 2 + c2;
                    float vv = vvec[col];
                    p0 += tanhf(acc[mf][nf][c2]     + hWa[b0 * Hq + col]) * vv;
                    p1 += tanhf(acc[mf][nf][2 + c2] + hWa[b1 * Hq + col]) * vv;
                }
            }
            p0 += __shfl_xor_sync(0xffffffffu, p0, 1);
            p0 += __shfl_xor_sync(0xffffffffu, p0, 2);
            p1 += __shfl_xor_sync(0xffffffffu, p1, 1);
            p1 += __shfl_xor_sync(0xffffffffu, p1, 2);
            if (lr == 0) {
                atomicAdd(&rowsum[wm + mf * 16 + lq], p0);
                atomicAdd(&rowsum[wm + mf * 16 + lq + 8], p1);
            }
        }
        __syncthreads();
        if (tid < 128) {
            int row = bm + tid;            // = s*Bq + b
            int s = row >> 10;
            int b = row & (Bq - 1);
            att[b * Sq + s] = (mask[b * Sq + s] == 0) ? -1000000.0f : rowsum[tid];
        }
    } else {
#pragma unroll
        for (int mf = 0; mf < 4; mf++) {
            int r0 = bm + wm + mf * 16 + lq;
#pragma unroll
            for (int nf = 0; nf < 8; nf++) {
                int col = bn + wn + nf * 8 + lr * 2;
                if (col < N) {
                    float b0 = bias ? bias[col] : 0.0f;
                    float b1 = bias ? bias[col + 1] : 0.0f;
                    *(float2*)(C + (size_t)r0 * N + col) =
                        make_float2(acc[mf][nf][0] + b0, acc[mf][nf][1] + b1);
                    *(float2*)(C + (size_t)(r0 + 8) * N + col) =
                        make_float2(acc[mf][nf][2] + b0, acc[mf][nf][3] + b1);
                }
            }
        }
    }
}

// ---------------- Wa transpose -------------------------------------------------
__global__ void transpose_wa(const float* __restrict__ Wa,
                             float* __restrict__ top, float* __restrict__ bot) {
    int idx = blockIdx.x * 256 + threadIdx.x;
    if (idx >= 2 * Hq * Hq) return;
    int k = idx / Hq;
    int n = idx - k * Hq;
    float val = Wa[k * Hq + n];
    if (k < Hq) top[n * Hq + k] = val;
    else        bot[n * Hq + (k - Hq)] = val;
}

// ---------------- softmax over S per row b (in place) --------------------------
__global__ void softmax_kernel(float* __restrict__ att) {
    int b = blockIdx.x;
    int t = threadIdx.x;
    float x = (t < Sq) ? att[b * Sq + t] : -3.4e38f;

    __shared__ float red[8];
    int lane = t & 31, wid = t >> 5;

    float m = x;
    for (int o = 16; o > 0; o >>= 1) m = fmaxf(m, __shfl_down_sync(0xffffffffu, m, o));
    if (lane == 0) red[wid] = m;
    __syncthreads();
    if (t == 0) {
        float mm = red[0];
        for (int w = 1; w < 8; w++) mm = fmaxf(mm, red[w]);
        red[0] = mm;
    }
    __syncthreads();
    m = red[0];
    __syncthreads();

    float e = (t < Sq) ? expf(x - m) : 0.0f;
    float sum = e;
    for (int o = 16; o > 0; o >>= 1) sum += __shfl_down_sync(0xffffffffu, sum, o);
    if (lane == 0) red[wid] = sum;
    __syncthreads();
    if (t == 0) {
        float ss = 0.0f;
        for (int w = 0; w < 8; w++) ss += red[w];
        red[0] = ss;
    }
    __syncthreads();
    float denom = red[0];

    if (t < Sq) att[b * Sq + t] = e / denom;
}

// ---------------- weighted sum + embedding gather -> rnn_in --------------------
__global__ __launch_bounds__(256)
void weighted_kernel(const float* __restrict__ att,
                     const float* __restrict__ enc,
                     const float* __restrict__ emb,
                     const int* __restrict__ loc,
                     float* __restrict__ rnn_in) {
    int b = blockIdx.x;
    int t = threadIdx.x;
    __shared__ float satt[Sq];
    __shared__ float4 red4[256];
    if (t < Sq) satt[t] = att[b * Sq + t];
    __syncthreads();

    int sp = t >> 6;
    int hq = t & 63;
    const float4* enc4 = (const float4*)enc;
    float4 acc = make_float4(0.f, 0.f, 0.f, 0.f);
    for (int s = sp; s < Sq; s += 4) {
        float w = satt[s];
        float4 e = enc4[((size_t)s * Bq + b) * 64 + hq];
        acc.x += w * e.x; acc.y += w * e.y; acc.z += w * e.z; acc.w += w * e.w;
    }
    red4[t] = acc;
    __syncthreads();

    float4* rnn4 = (float4*)(rnn_in + (size_t)b * (Eq + Hq));
    if (t < 64) {
        float4 a0 = red4[t], a1 = red4[64 + t], a2 = red4[128 + t], a3 = red4[192 + t];
        rnn4[32 + t] = make_float4(a0.x + a1.x + a2.x + a3.x,
                                   a0.y + a1.y + a2.y + a3.y,
                                   a0.z + a1.z + a2.z + a3.z,
                                   a0.w + a1.w + a2.w + a3.w);
    } else if (t < 96) {
        rnn4[t - 64] = ((const float4*)emb)[(size_t)loc[b] * 32 + (t - 64)];
    }
}

// ---------------- GRU gates ----------------------------------------------------
__global__ void gru_kernel(const float* __restrict__ gi, const float* __restrict__ gh,
                           const float* __restrict__ h,
                           float* __restrict__ hnew, float* __restrict__ out_h) {
    int b = blockIdx.x;
    int j = threadIdx.x;
    float ir = gi[b * 768 + j];
    float iz = gi[b * 768 + 256 + j];
    float in = gi[b * 768 + 512 + j];
    float hr = gh[b * 768 + j];
    float hz = gh[b * 768 + 256 + j];
    float hn = gh[b * 768 + 512 + j];
    float r = 1.0f / (1.0f + expf(-(ir + hr)));
    float z = 1.0f / (1.0f + expf(-(iz + hz)));
    float n = tanhf(in + r * hn);
    float hv = h[b * Hq + j];
    float hnv = (1.0f - z) * n + z * hv;
    hnew[b * Hq + j] = hnv;
    out_h[b * Hq + j] = hnv;
}

// ---------------- launch -------------------------------------------------------
extern "C" void kernel_launch(void* const* d_in, const int* in_sizes, int n_in,
                              void* d_out, int out_size) {
    const int*   input_loc = (const int*)d_in[0];
    const float* hidden    = (const float*)d_in[1];
    const float* enc       = (const float*)d_in[2];
    const int*   mask      = (const int*)d_in[3];
    const float* emb       = (const float*)d_in[4];
    const float* Wa        = (const float*)d_in[5];
    const float* ba        = (const float*)d_in[6];
    const float* v         = (const float*)d_in[7];
    const float* W_ih      = (const float*)d_in[8];
    const float* W_hh      = (const float*)d_in[9];
    const float* b_ih      = (const float*)d_in[10];
    const float* b_hh      = (const float*)d_in[11];
    const float* W_out     = (const float*)d_in[12];
    const float* b_out     = (const float*)d_in[13];
    float* out = (float*)d_out;
    float* out_pred = out;
    float* out_h    = out + (size_t)Bq * Vq;

    float *WaT_top, *WaT_bot, *hWa, *att, *rnn_in, *gi, *gh, *hnew;
    cudaGetSymbolAddress((void**)&WaT_top, g_WaT_top);
    cudaGetSymbolAddress((void**)&WaT_bot, g_WaT_bot);
    cudaGetSymbolAddress((void**)&hWa,     g_hWa);
    cudaGetSymbolAddress((void**)&att,     g_att);
    cudaGetSymbolAddress((void**)&rnn_in,  g_rnn_in);
    cudaGetSymbolAddress((void**)&gi,      g_gi);
    cudaGetSymbolAddress((void**)&gh,      g_gh);
    cudaGetSymbolAddress((void**)&hnew,    g_hnew);

    cudaFuncSetAttribute(mma_gemm<0>, cudaFuncAttributeMaxDynamicSharedMemorySize, GTOT);
    cudaFuncSetAttribute(mma_gemm<1>, cudaFuncAttributeMaxDynamicSharedMemorySize, GTOT);

    // 1. split+transpose Wa
    transpose_wa<<<512, 256>>>(Wa, WaT_top, WaT_bot);

    // 2. hWa = h @ Wa_top + ba          (1024 x 256 x 256)
    mma_gemm<0><<<dim3(Bq / 128, 1), 256, GTOT>>>(
        hidden, WaT_top, ba, hWa, Bq, Hq, Hq,
        nullptr, nullptr, nullptr, nullptr);

    // 3+4. fused: att = mask ? v . tanh(enc@Wa_bot + hWa) : -1e6
    mma_gemm<1><<<dim3((Sq * Bq) / 128, 1), 256, GTOT>>>(
        enc, WaT_bot, nullptr, nullptr, Sq * Bq, Hq, Hq,
        hWa, v, mask, att);

    // 5. softmax over S
    softmax_kernel<<<Bq, 256>>>(att);

    // 6. weighted context + embedding gather
    weighted_kernel<<<Bq, 256>>>(att, enc, emb, input_loc, rnn_in);

    // 7. gi = rnn_in @ W_ih^T + b_ih    (1024 x 768 x 384)
    mma_gemm<0><<<dim3(Bq / 128, 3), 256, GTOT>>>(
        rnn_in, W_ih, b_ih, gi, Bq, 3 * Hq, Eq + Hq,
        nullptr, nullptr, nullptr, nullptr);

    // 8. gh = h @ W_hh^T + b_hh         (1024 x 768 x 256)
    mma_gemm<0><<<dim3(Bq / 128, 3), 256, GTOT>>>(
        hidden, W_hh, b_hh, gh, Bq, 3 * Hq, Hq,
        nullptr, nullptr, nullptr, nullptr);

    // 9. GRU gates -> h_new
    gru_kernel<<<Bq, Hq>>>(gi, gh, hidden, hnew, out_h);

    // 10. pred = h_new @ W_out^T + b_out  (1024 x 100000 x 256)
    //     grid.x = m-tiles so the 8 CTAs sharing a W_out tile run adjacently.
    mma_gemm<0><<<dim3(Bq / 128, (Vq + 255) / 256), 256, GTOT>>>(
        hnew, W_out, b_out, out_pred, Bq, Vq, Hq,
        nullptr, nullptr, nullptr, nullptr);
}

// round 9
// speedup vs baseline: 4.0327x; 1.4296x over previous
#include <cuda_runtime.h>
#include <cuda_fp16.h>
#include <cstdint>
#include <cstddef>

// Problem dims
#define Bq 1024
#define Sq 200
#define Hq 256
#define Eq 128
#define Vq 100000

// ---------------- scratch (__device__ globals) ---------------------------------
__device__ __half g_enc_h[(size_t)Sq * Bq * Hq];   // 52.4 MB
__device__ __half g_Wout_h[(size_t)Vq * Hq];       // 51.2 MB
__device__ __half g_WaTtop_h[Hq * Hq];
__device__ __half g_WaTbot_h[Hq * Hq];
__device__ __half g_h_h[Bq * Hq];
__device__ __half g_Wih_h[3 * Hq * (Eq + Hq)];
__device__ __half g_Whh_h[3 * Hq * Hq];
__device__ __half g_rnnin_h[Bq * (Eq + Hq)];
__device__ __half g_hnew_h[Bq * Hq];
__device__ float  g_hWa[Bq * Hq];
__device__ float  g_att[Bq * Sq];
__device__ float  g_gi[Bq * 3 * Hq];
__device__ float  g_gh[Bq * 3 * Hq];

// ---------------- helpers ------------------------------------------------------
__device__ __forceinline__ uint32_t f2h2(float x, float y) {
    __half2 h = __floats2half2_rn(x, y);
    return *(uint32_t*)&h;
}

__device__ __forceinline__ uint32_t smem_u32(const void* p) {
    uint32_t a;
    asm("{ .reg .u64 t; cvta.to.shared.u64 t, %1; cvt.u32.u64 %0, t; }"
        : "=r"(a) : "l"(p));
    return a;
}

__device__ __forceinline__ void mma_fp16(float* c,
                                         uint32_t a0, uint32_t a1, uint32_t a2, uint32_t a3,
                                         uint32_t b0, uint32_t b1) {
    asm volatile(
        "mma.sync.aligned.m16n8k16.row.col.f32.f16.f16.f32 "
        "{%0,%1,%2,%3}, {%4,%5,%6,%7}, {%8,%9}, {%0,%1,%2,%3};\n"
        : "+f"(c[0]), "+f"(c[1]), "+f"(c[2]), "+f"(c[3])
        : "r"(a0), "r"(a1), "r"(a2), "r"(a3), "r"(b0), "r"(b1));
}

#define LDMX4(r0, r1, r2, r3, a)                                                \
    asm volatile("ldmatrix.sync.aligned.m8n8.x4.shared.b16 {%0,%1,%2,%3}, [%4];" \
                 : "=r"(r0), "=r"(r1), "=r"(r2), "=r"(r3) : "r"(a))

#define CPA16(dst, src, pred)                                                   \
    asm volatile("cp.async.cg.shared.global [%0], [%1], 16, %2;"                \
                 :: "r"(dst), "l"(src), "r"((pred) ? 16 : 0) : "memory")
#define CPA_COMMIT() asm volatile("cp.async.commit_group;" ::: "memory")
#define CPA_WAIT1()  asm volatile("cp.async.wait_group 1;" ::: "memory")

// ---------------- fp16 NT GEMM: C[M,N] = A[M,K] @ B[N,K]^T (+bias) -------------
// fp16 in, fp32 accumulate/out. Block 128x256 (8 warps of 64x64), K-chunk 32,
// 3-stage cp.async pipeline (2 chunks in flight). Rows at 80-byte stride:
// conflict-free ldmatrix. M%128==0, K%32==0, N ragged OK.
// FUSE==1: att epilogue (N==256, bn==0, global row = s*Bq + b).
#define ST_A 10240                 // 128 rows * 80 B
#define ST_B 20480                 // 256 rows * 80 B
#define STG  (ST_A + ST_B)         // 30720
#define GTOT (3 * STG)             // 92160

template <int FUSE>
__global__ __launch_bounds__(256, 1)
void mma_gemm(const __half* __restrict__ A, const __half* __restrict__ Bm,
              const float* __restrict__ bias, float* __restrict__ C,
              int M, int N, int K,
              const float* __restrict__ hWa, const float* __restrict__ vvec,
              const int* __restrict__ mask, float* __restrict__ att) {
    extern __shared__ char smem[];
    const uint32_t sbase = smem_u32(smem);

    const int tid  = threadIdx.x;
    const int lane = tid & 31;
    const int warp = tid >> 5;
    const int wm = (warp >> 2) * 64;
    const int wn = (warp & 3) * 64;
    const int bm = blockIdx.x * 128;
    const int bn = blockIdx.y * 256;
    const int lq = lane >> 2;
    const int lr = lane & 3;

    __shared__ float rowsum[128];
    if (FUSE && tid < 128) rowsum[tid] = 0.0f;

    // per-lane ldmatrix byte offsets (within a stage)
    const int rin = lane & 7;
    uint32_t a_l[4], b_l[4];
    {
        const int r8   = (lane >> 3) & 1;
        const int kh_a = (lane >> 4) & 1;
        const int n8   = (lane >> 4) & 1;
        const int kh_b = (lane >> 3) & 1;
#pragma unroll
        for (int mf = 0; mf < 4; mf++)
            a_l[mf] = (uint32_t)((wm + mf * 16 + r8 * 8 + rin) * 80 + kh_a * 16);
#pragma unroll
        for (int p2 = 0; p2 < 4; p2++)
            b_l[p2] = (uint32_t)((wn + p2 * 16 + n8 * 8 + rin) * 80 + kh_b * 16);
    }

    float acc[4][8][4];
#pragma unroll
    for (int i = 0; i < 4; i++)
#pragma unroll
        for (int j = 0; j < 8; j++)
#pragma unroll
            for (int k = 0; k < 4; k++) acc[i][j][k] = 0.0f;

    const int nch = K / 32;

#define ISSUE(c)                                                            \
    do {                                                                    \
        const int kc = (c) * 32;                                            \
        const uint32_t sa0 = sbase + ((c) % 3) * STG;                       \
        const uint32_t sb0 = sa0 + ST_A;                                    \
        _Pragma("unroll")                                                   \
        for (int l = 0; l < 2; l++) {                                       \
            int q = tid + l * 256;                                          \
            int row = q >> 2, seg = q & 3;                                  \
            CPA16(sa0 + row * 80 + seg * 16,                                \
                  A + (size_t)(bm + row) * K + kc + seg * 8, true);         \
        }                                                                   \
        _Pragma("unroll")                                                   \
        for (int l = 0; l < 4; l++) {                                       \
            int q = tid + l * 256;                                          \
            int row = q >> 2, seg = q & 3;                                  \
            CPA16(sb0 + row * 80 + seg * 16,                                \
                  Bm + (size_t)(bn + row) * K + kc + seg * 8,               \
                  (bn + row) < N);                                          \
        }                                                                   \
    } while (0)

    // prologue: 2 chunks in flight
    ISSUE(0);
    CPA_COMMIT();
    if (nch > 1) ISSUE(1);
    CPA_COMMIT();

    for (int c = 0; c < nch; c++) {
        CPA_WAIT1();
        __syncthreads();
        if (c + 2 < nch) ISSUE(c + 2);
        CPA_COMMIT();

        const uint32_t aA = sbase + (c % 3) * STG;
        const uint32_t aB = aA + ST_A;

#pragma unroll
        for (int ks = 0; ks < 2; ks++) {
            uint32_t bf[8][2];
#pragma unroll
            for (int p2 = 0; p2 < 4; p2++)
                LDMX4(bf[2 * p2][0], bf[2 * p2][1], bf[2 * p2 + 1][0], bf[2 * p2 + 1][1],
                      aB + b_l[p2] + ks * 32);
#pragma unroll
            for (int mf = 0; mf < 4; mf++) {
                uint32_t a0, a1, a2, a3;
                LDMX4(a0, a1, a2, a3, aA + a_l[mf] + ks * 32);
#pragma unroll
                for (int nf = 0; nf < 8; nf++)
                    mma_fp16(acc[mf][nf], a0, a1, a2, a3, bf[nf][0], bf[nf][1]);
            }
        }
    }
#undef ISSUE

    if (FUSE) {
#pragma unroll
        for (int mf = 0; mf < 4; mf++) {
            int r0g = bm + wm + mf * 16 + lq;
            int b0 = r0g & (Bq - 1);
            int b1 = (r0g + 8) & (Bq - 1);
            float p0 = 0.0f, p1 = 0.0f;
#pragma unroll
            for (int nf = 0; nf < 8; nf++) {
#pragma unroll
                for (int c2 = 0; c2 < 2; c2++) {
                    int col = wn + nf * 8 + lr * 2 + c2;
                    float vv = vvec[col];
                    p0 += tanhf(acc[mf][nf][c2]     + hWa[b0 * Hq + col]) * vv;
                    p1 += tanhf(acc[mf][nf][2 + c2] + hWa[b1 * Hq + col]) * vv;
                }
            }
            p0 += __shfl_xor_sync(0xffffffffu, p0, 1);
            p0 += __shfl_xor_sync(0xffffffffu, p0, 2);
            p1 += __shfl_xor_sync(0xffffffffu, p1, 1);
            p1 += __shfl_xor_sync(0xffffffffu, p1, 2);
            if (lr == 0) {
                atomicAdd(&rowsum[wm + mf * 16 + lq], p0);
                atomicAdd(&rowsum[wm + mf * 16 + lq + 8], p1);
            }
        }
        __syncthreads();
        if (tid < 128) {
            int row = bm + tid;            // = s*Bq + b
            int s = row >> 10;
            int b = row & (Bq - 1);
            att[b * Sq + s] = (mask[b * Sq + s] == 0) ? -1000000.0f : rowsum[tid];
        }
    } else {
#pragma unroll
        for (int mf = 0; mf < 4; mf++) {
            int r0 = bm + wm + mf * 16 + lq;
#pragma unroll
            for (int nf = 0; nf < 8; nf++) {
                int col = bn + wn + nf * 8 + lr * 2;
                if (col < N) {
                    float b0 = bias ? bias[col] : 0.0f;
                    float b1 = bias ? bias[col + 1] : 0.0f;
                    *(float2*)(C + (size_t)r0 * N + col) =
                        make_float2(acc[mf][nf][0] + b0, acc[mf][nf][1] + b1);
                    *(float2*)(C + (size_t)(r0 + 8) * N + col) =
                        make_float2(acc[mf][nf][2] + b0, acc[mf][nf][3] + b1);
                }
            }
        }
    }
}

// ---------------- fp32 -> fp16 convert (n % 4 == 0) ----------------------------
__global__ void f32to16(const float* __restrict__ in, __half* __restrict__ out, int n4) {
    int i = blockIdx.x * 256 + threadIdx.x;
    if (i < n4) {
        float4 f = ((const float4*)in)[i];
        uint2 u;
        u.x = f2h2(f.x, f.y);
        u.y = f2h2(f.z, f.w);
        ((uint2*)out)[i] = u;
    }
}

// ---------------- Wa transpose -> half -----------------------------------------
__global__ void transpose_wa(const float* __restrict__ Wa,
                             __half* __restrict__ top, __half* __restrict__ bot) {
    int idx = blockIdx.x * 256 + threadIdx.x;
    if (idx >= 2 * Hq * Hq) return;
    int k = idx / Hq;
    int n = idx - k * Hq;
    __half val = __float2half_rn(Wa[k * Hq + n]);
    if (k < Hq) top[n * Hq + k] = val;
    else        bot[n * Hq + (k - Hq)] = val;
}

// ---------------- softmax over S per row b (in place) --------------------------
__global__ void softmax_kernel(float* __restrict__ att) {
    int b = blockIdx.x;
    int t = threadIdx.x;
    float x = (t < Sq) ? att[b * Sq + t] : -3.4e38f;

    __shared__ float red[8];
    int lane = t & 31, wid = t >> 5;

    float m = x;
    for (int o = 16; o > 0; o >>= 1) m = fmaxf(m, __shfl_down_sync(0xffffffffu, m, o));
    if (lane == 0) red[wid] = m;
    __syncthreads();
    if (t == 0) {
        float mm = red[0];
        for (int w = 1; w < 8; w++) mm = fmaxf(mm, red[w]);
        red[0] = mm;
    }
    __syncthreads();
    m = red[0];
    __syncthreads();

    float e = (t < Sq) ? expf(x - m) : 0.0f;
    float sum = e;
    for (int o = 16; o > 0; o >>= 1) sum += __shfl_down_sync(0xffffffffu, sum, o);
    if (lane == 0) red[wid] = sum;
    __syncthreads();
    if (t == 0) {
        float ss = 0.0f;
        for (int w = 0; w < 8; w++) ss += red[w];
        red[0] = ss;
    }
    __syncthreads();
    float denom = red[0];

    if (t < Sq) att[b * Sq + t] = e / denom;
}

// ---------------- weighted sum + embedding gather -> rnn_in (half) -------------
__global__ __launch_bounds__(256)
void weighted_kernel(const float* __restrict__ att,
                     const __half* __restrict__ enc_h,
                     const float* __restrict__ emb,
                     const int* __restrict__ loc,
                     __half* __restrict__ rnn_h) {
    int b = blockIdx.x;
    int t = threadIdx.x;
    __shared__ float satt[Sq];
    __shared__ float4 red4[256];
    if (t < Sq) satt[t] = att[b * Sq + t];
    __syncthreads();

    int sp = t >> 6;        // 0..3
    int hq = t & 63;        // 4-half group within H (64 groups)
    const uint2* enc2 = (const uint2*)enc_h;
    float4 acc = make_float4(0.f, 0.f, 0.f, 0.f);
    for (int s = sp; s < Sq; s += 4) {
        float w = satt[s];
        uint2 u = enc2[((size_t)s * Bq + b) * 64 + hq];
        float2 f0 = __half22float2(*(__half2*)&u.x);
        float2 f1 = __half22float2(*(__half2*)&u.y);
        acc.x += w * f0.x; acc.y += w * f0.y; acc.z += w * f1.x; acc.w += w * f1.y;
    }
    red4[t] = acc;
    __syncthreads();

    uint2* rnn2 = (uint2*)(rnn_h + (size_t)b * (Eq + Hq));
    if (t < 64) {
        float4 a0 = red4[t], a1 = red4[64 + t], a2 = red4[128 + t], a3 = red4[192 + t];
        float x = a0.x + a1.x + a2.x + a3.x;
        float y = a0.y + a1.y + a2.y + a3.y;
        float z = a0.z + a1.z + a2.z + a3.z;
        float w = a0.w + a1.w + a2.w + a3.w;
        uint2 u;
        u.x = f2h2(x, y);
        u.y = f2h2(z, w);
        rnn2[32 + t] = u;                           // context at offset Eq = 128 halves
    } else if (t < 96) {
        float4 f = ((const float4*)emb)[(size_t)loc[b] * 32 + (t - 64)];
        uint2 u;
        u.x = f2h2(f.x, f.y);
        u.y = f2h2(f.z, f.w);
        rnn2[t - 64] = u;
    }
}

// ---------------- GRU gates ----------------------------------------------------
__global__ void gru_kernel(const float* __restrict__ gi, const float* __restrict__ gh,
                           const float* __restrict__ h,
                           __half* __restrict__ hnew_h, float* __restrict__ out_h) {
    int b = blockIdx.x;
    int j = threadIdx.x;
    float ir = gi[b * 768 + j];
    float iz = gi[b * 768 + 256 + j];
    float in = gi[b * 768 + 512 + j];
    float hr = gh[b * 768 + j];
    float hz = gh[b * 768 + 256 + j];
    float hn = gh[b * 768 + 512 + j];
    float r = 1.0f / (1.0f + expf(-(ir + hr)));
    float z = 1.0f / (1.0f + expf(-(iz + hz)));
    float n = tanhf(in + r * hn);
    float hv = h[b * Hq + j];
    float hnv = (1.0f - z) * n + z * hv;
    hnew_h[b * Hq + j] = __float2half_rn(hnv);
    out_h[b * Hq + j] = hnv;
}

// ---------------- launch -------------------------------------------------------
extern "C" void kernel_launch(void* const* d_in, const int* in_sizes, int n_in,
                              void* d_out, int out_size) {
    const int*   input_loc = (const int*)d_in[0];
    const float* hidden    = (const float*)d_in[1];
    const float* enc       = (const float*)d_in[2];
    const int*   mask      = (const int*)d_in[3];
    const float* emb       = (const float*)d_in[4];
    const float* Wa        = (const float*)d_in[5];
    const float* ba        = (const float*)d_in[6];
    const float* v         = (const float*)d_in[7];
    const float* W_ih      = (const float*)d_in[8];
    const float* W_hh      = (const float*)d_in[9];
    const float* b_ih      = (const float*)d_in[10];
    const float* b_hh      = (const float*)d_in[11];
    const float* W_out     = (const float*)d_in[12];
    const float* b_out     = (const float*)d_in[13];
    float* out = (float*)d_out;
    float* out_pred = out;
    float* out_h    = out + (size_t)Bq * Vq;

    __half *enc_h, *Wout_h, *WaTtop_h, *WaTbot_h, *h_h, *Wih_h, *Whh_h, *rnnin_h, *hnew_h;
    float  *hWa, *att, *gi, *gh;
    cudaGetSymbolAddress((void**)&enc_h,    g_enc_h);
    cudaGetSymbolAddress((void**)&Wout_h,   g_Wout_h);
    cudaGetSymbolAddress((void**)&WaTtop_h, g_WaTtop_h);
    cudaGetSymbolAddress((void**)&WaTbot_h, g_WaTbot_h);
    cudaGetSymbolAddress((void**)&h_h,      g_h_h);
    cudaGetSymbolAddress((void**)&Wih_h,    g_Wih_h);
    cudaGetSymbolAddress((void**)&Whh_h,    g_Whh_h);
    cudaGetSymbolAddress((void**)&rnnin_h,  g_rnnin_h);
    cudaGetSymbolAddress((void**)&hnew_h,   g_hnew_h);
    cudaGetSymbolAddress((void**)&hWa,      g_hWa);
    cudaGetSymbolAddress((void**)&att,      g_att);
    cudaGetSymbolAddress((void**)&gi,       g_gi);
    cudaGetSymbolAddress((void**)&gh,       g_gh);

    cudaFuncSetAttribute(mma_gemm<0>, cudaFuncAttributeMaxDynamicSharedMemorySize, GTOT);
    cudaFuncSetAttribute(mma_gemm<1>, cudaFuncAttributeMaxDynamicSharedMemorySize, GTOT);

    // 0. conversions to fp16
    {
        int n4;
        n4 = (Sq * Bq * Hq) / 4;  f32to16<<<(n4 + 255) / 256, 256>>>(enc, enc_h, n4);
        n4 = (Vq * Hq) / 4;       f32to16<<<(n4 + 255) / 256, 256>>>(W_out, Wout_h, n4);
        n4 = (Bq * Hq) / 4;       f32to16<<<(n4 + 255) / 256, 256>>>(hidden, h_h, n4);
        n4 = (3 * Hq * (Eq + Hq)) / 4; f32to16<<<(n4 + 255) / 256, 256>>>(W_ih, Wih_h, n4);
        n4 = (3 * Hq * Hq) / 4;   f32to16<<<(n4 + 255) / 256, 256>>>(W_hh, Whh_h, n4);
    }
    transpose_wa<<<512, 256>>>(Wa, WaTtop_h, WaTbot_h);

    // 2. hWa = h @ Wa_top + ba          (1024 x 256 x 256)
    mma_gemm<0><<<dim3(Bq / 128, 1), 256, GTOT>>>(
        h_h, WaTtop_h, ba, hWa, Bq, Hq, Hq,
        nullptr, nullptr, nullptr, nullptr);

    // 3+4. fused: att = mask ? v . tanh(enc@Wa_bot + hWa) : -1e6
    mma_gemm<1><<<dim3((Sq * Bq) / 128, 1), 256, GTOT>>>(
        enc_h, WaTbot_h, nullptr, nullptr, Sq * Bq, Hq, Hq,
        hWa, v, mask, att);

    // 5. softmax over S
    softmax_kernel<<<Bq, 256>>>(att);

    // 6. weighted context + embedding gather -> rnn_in (half)
    weighted_kernel<<<Bq, 256>>>(att, enc_h, emb, input_loc, rnnin_h);

    // 7. gi = rnn_in @ W_ih^T + b_ih    (1024 x 768 x 384)
    mma_gemm<0><<<dim3(Bq / 128, 3), 256, GTOT>>>(
        rnnin_h, Wih_h, b_ih, gi, Bq, 3 * Hq, Eq + Hq,
        nullptr, nullptr, nullptr, nullptr);

    // 8. gh = h @ W_hh^T + b_hh         (1024 x 768 x 256)
    mma_gemm<0><<<dim3(Bq / 128, 3), 256, GTOT>>>(
        h_h, Whh_h, b_hh, gh, Bq, 3 * Hq, Hq,
        nullptr, nullptr, nullptr, nullptr);

    // 9. GRU gates -> h_new (half for pred GEMM, fp32 to output)
    gru_kernel<<<Bq, Hq>>>(gi, gh, hidden, hnew_h, out_h);

    // 10. pred = h_new @ W_out^T + b_out  (1024 x 100000 x 256)
    //     grid.x = m-tiles so the 8 CTAs sharing a W_out tile run adjacently.
    mma_gemm<0><<<dim3(Bq / 128, (Vq + 255) / 256), 256, GTOT>>>(
        hnew_h, Wout_h, b_out, out_pred, Bq, Vq, Hq,
        nullptr, nullptr, nullptr, nullptr);
}

// round 10
// speedup vs baseline: 4.1020x; 1.0172x over previous
#include <cuda_runtime.h>
#include <cuda_fp16.h>
#include <cstdint>
#include <cstddef>

// Problem dims
#define Bq 1024
#define Sq 200
#define Hq 256
#define Eq 128
#define Vq 100000

// ---------------- scratch (__device__ globals) ---------------------------------
__device__ __half g_enc_h[(size_t)Sq * Bq * Hq];   // 52.4 MB
__device__ __half g_Wout_h[(size_t)Vq * Hq];       // 51.2 MB
__device__ __half g_WaTtop_h[Hq * Hq];
__device__ __half g_WaTbot_h[Hq * Hq];
__device__ __half g_h_h[Bq * Hq];
__device__ __half g_Wih_h[3 * Hq * (Eq + Hq)];
__device__ __half g_Whh_h[3 * Hq * Hq];
__device__ __half g_rnnin_h[Bq * (Eq + Hq)];
__device__ __half g_hnew_h[Bq * Hq];
__device__ float  g_hWa[Bq * Hq];
__device__ float  g_att[Bq * Sq];
__device__ float  g_gi[Bq * 3 * Hq];
__device__ float  g_gh[Bq * 3 * Hq];

// ---------------- helpers ------------------------------------------------------
__device__ __forceinline__ uint32_t f2h2(float x, float y) {
    __half2 h = __floats2half2_rn(x, y);
    return *(uint32_t*)&h;
}

__device__ __forceinline__ uint32_t smem_u32(const void* p) {
    uint32_t a;
    asm("{ .reg .u64 t; cvta.to.shared.u64 t, %1; cvt.u32.u64 %0, t; }"
        : "=r"(a) : "l"(p));
    return a;
}

__device__ __forceinline__ void mma_fp16(float* c,
                                         uint32_t a0, uint32_t a1, uint32_t a2, uint32_t a3,
                                         uint32_t b0, uint32_t b1) {
    asm volatile(
        "mma.sync.aligned.m16n8k16.row.col.f32.f16.f16.f32 "
        "{%0,%1,%2,%3}, {%4,%5,%6,%7}, {%8,%9}, {%0,%1,%2,%3};\n"
        : "+f"(c[0]), "+f"(c[1]), "+f"(c[2]), "+f"(c[3])
        : "r"(a0), "r"(a1), "r"(a2), "r"(a3), "r"(b0), "r"(b1));
}

#define LDMX4(r0, r1, r2, r3, a)                                                \
    asm volatile("ldmatrix.sync.aligned.m8n8.x4.shared.b16 {%0,%1,%2,%3}, [%4];" \
                 : "=r"(r0), "=r"(r1), "=r"(r2), "=r"(r3) : "r"(a))

#define CPA16(dst, src, pred)                                                   \
    asm volatile("cp.async.cg.shared.global [%0], [%1], 16, %2;"                \
                 :: "r"(dst), "l"(src), "r"((pred) ? 16 : 0) : "memory")
#define CPA_COMMIT() asm volatile("cp.async.commit_group;" ::: "memory")
#define CPA_WAIT1()  asm volatile("cp.async.wait_group 1;" ::: "memory")

// ---------------- fp16 NT GEMM: C[M,N] = A[M,K] @ B[N,K]^T (+bias) -------------
// fp16 in, fp32 accumulate/out. Block 128x256 (8 warps of 64x64), K-chunk 32,
// 3-stage cp.async pipeline. Rows at 80-byte stride: conflict-free ldmatrix.
// M%128==0, K%32==0, N ragged OK.
// FUSE==1: att epilogue (N==256, bn==0, global row = s*Bq + b).
// blockIdx.z==1 selects the second (A1,B1,bias1,C1,K1) parameter set.
#define ST_A 10240                 // 128 rows * 80 B
#define ST_B 20480                 // 256 rows * 80 B
#define STG  (ST_A + ST_B)         // 30720
#define GTOT (3 * STG)             // 92160

template <int FUSE>
__global__ __launch_bounds__(256, 1)
void mma_gemm(const __half* __restrict__ A, const __half* __restrict__ Bm,
              const float* __restrict__ bias, float* __restrict__ C,
              int M, int N, int K,
              const float* __restrict__ hWa, const float* __restrict__ vvec,
              const int* __restrict__ mask, float* __restrict__ att,
              const __half* A1, const __half* B1,
              const float* bias1, float* C1, int K1) {
    extern __shared__ char smem[];
    const uint32_t sbase = smem_u32(smem);

    // dual-parameter select (gridDim.z==1 for normal launches)
    const __half* Ap   = A;
    const __half* Bp   = Bm;
    const float*  bsp  = bias;
    float*        Cp   = C;
    int           Kp   = K;
    if (blockIdx.z) { Ap = A1; Bp = B1; bsp = bias1; Cp = C1; Kp = K1; }

    const int tid  = threadIdx.x;
    const int lane = tid & 31;
    const int warp = tid >> 5;
    const int wm = (warp >> 2) * 64;
    const int wn = (warp & 3) * 64;
    const int bm = blockIdx.x * 128;
    const int bn = blockIdx.y * 256;
    const int lq = lane >> 2;
    const int lr = lane & 3;

    __shared__ float rowsum[128];
    if (FUSE && tid < 128) rowsum[tid] = 0.0f;

    // per-lane ldmatrix byte offsets (within a stage)
    const int rin = lane & 7;
    uint32_t a_l[4], b_l[4];
    {
        const int r8   = (lane >> 3) & 1;
        const int kh_a = (lane >> 4) & 1;
        const int n8   = (lane >> 4) & 1;
        const int kh_b = (lane >> 3) & 1;
#pragma unroll
        for (int mf = 0; mf < 4; mf++)
            a_l[mf] = (uint32_t)((wm + mf * 16 + r8 * 8 + rin) * 80 + kh_a * 16);
#pragma unroll
        for (int p2 = 0; p2 < 4; p2++)
            b_l[p2] = (uint32_t)((wn + p2 * 16 + n8 * 8 + rin) * 80 + kh_b * 16);
    }

    float acc[4][8][4];
#pragma unroll
    for (int i = 0; i < 4; i++)
#pragma unroll
        for (int j = 0; j < 8; j++)
#pragma unroll
            for (int k = 0; k < 4; k++) acc[i][j][k] = 0.0f;

    const int nch = Kp / 32;

#define ISSUE(c)                                                            \
    do {                                                                    \
        const int kc = (c) * 32;                                            \
        const uint32_t sa0 = sbase + ((c) % 3) * STG;                       \
        const uint32_t sb0 = sa0 + ST_A;                                    \
        _Pragma("unroll")                                                   \
        for (int l = 0; l < 2; l++) {                                       \
            int q = tid + l * 256;                                          \
            int row = q >> 2, seg = q & 3;                                  \
            CPA16(sa0 + row * 80 + seg * 16,                                \
                  Ap + (size_t)(bm + row) * Kp + kc + seg * 8, true);       \
        }                                                                   \
        _Pragma("unroll")                                                   \
        for (int l = 0; l < 4; l++) {                                       \
            int q = tid + l * 256;                                          \
            int row = q >> 2, seg = q & 3;                                  \
            CPA16(sb0 + row * 80 + seg * 16,                                \
                  Bp + (size_t)(bn + row) * Kp + kc + seg * 8,              \
                  (bn + row) < N);                                          \
        }                                                                   \
    } while (0)

    // prologue: 2 chunks in flight
    ISSUE(0);
    CPA_COMMIT();
    if (nch > 1) ISSUE(1);
    CPA_COMMIT();

    for (int c = 0; c < nch; c++) {
        CPA_WAIT1();
        __syncthreads();
        if (c + 2 < nch) ISSUE(c + 2);
        CPA_COMMIT();

        const uint32_t aA = sbase + (c % 3) * STG;
        const uint32_t aB = aA + ST_A;

#pragma unroll
        for (int ks = 0; ks < 2; ks++) {
            uint32_t bf[8][2];
#pragma unroll
            for (int p2 = 0; p2 < 4; p2++)
                LDMX4(bf[2 * p2][0], bf[2 * p2][1], bf[2 * p2 + 1][0], bf[2 * p2 + 1][1],
                      aB + b_l[p2] + ks * 32);
#pragma unroll
            for (int mf = 0; mf < 4; mf++) {
                uint32_t a0, a1, a2, a3;
                LDMX4(a0, a1, a2, a3, aA + a_l[mf] + ks * 32);
#pragma unroll
                for (int nf = 0; nf < 8; nf++)
                    mma_fp16(acc[mf][nf], a0, a1, a2, a3, bf[nf][0], bf[nf][1]);
            }
        }
    }
#undef ISSUE

    if (FUSE) {
#pragma unroll
        for (int mf = 0; mf < 4; mf++) {
            int r0g = bm + wm + mf * 16 + lq;
            int b0 = r0g & (Bq - 1);
            int b1 = (r0g + 8) & (Bq - 1);
            float p0 = 0.0f, p1 = 0.0f;
#pragma unroll
            for (int nf = 0; nf < 8; nf++) {
#pragma unroll
                for (int c2 = 0; c2 < 2; c2++) {
                    int col = wn + nf * 8 + lr * 2 + c2;
                    float vv = vvec[col];
                    p0 += tanhf(acc[mf][nf][c2]     + hWa[b0 * Hq + col]) * vv;
                    p1 += tanhf(acc[mf][nf][2 + c2] + hWa[b1 * Hq + col]) * vv;
                }
            }
            p0 += __shfl_xor_sync(0xffffffffu, p0, 1);
            p0 += __shfl_xor_sync(0xffffffffu, p0, 2);
            p1 += __shfl_xor_sync(0xffffffffu, p1, 1);
            p1 += __shfl_xor_sync(0xffffffffu, p1, 2);
            if (lr == 0) {
                atomicAdd(&rowsum[wm + mf * 16 + lq], p0);
                atomicAdd(&rowsum[wm + mf * 16 + lq + 8], p1);
            }
        }
        __syncthreads();
        if (tid < 128) {
            int row = bm + tid;            // = s*Bq + b
            int s = row >> 10;
            int b = row & (Bq - 1);
            att[b * Sq + s] = (mask[b * Sq + s] == 0) ? -1000000.0f : rowsum[tid];
        }
    } else {
#pragma unroll
        for (int mf = 0; mf < 4; mf++) {
            int r0 = bm + wm + mf * 16 + lq;
#pragma unroll
            for (int nf = 0; nf < 8; nf++) {
                int col = bn + wn + nf * 8 + lr * 2;
                if (col < N) {
                    float b0 = bsp ? bsp[col] : 0.0f;
                    float b1 = bsp ? bsp[col + 1] : 0.0f;
                    *(float2*)(Cp + (size_t)r0 * N + col) =
                        make_float2(acc[mf][nf][0] + b0, acc[mf][nf][1] + b1);
                    *(float2*)(Cp + (size_t)(r0 + 8) * N + col) =
                        make_float2(acc[mf][nf][2] + b0, acc[mf][nf][3] + b1);
                }
            }
        }
    }
}

// ---------------- fp32 -> fp16 convert (n % 4 == 0) ----------------------------
__global__ void f32to16(const float* __restrict__ in, __half* __restrict__ out, int n4) {
    int i = blockIdx.x * 256 + threadIdx.x;
    if (i < n4) {
        float4 f = ((const float4*)in)[i];
        uint2 u;
        u.x = f2h2(f.x, f.y);
        u.y = f2h2(f.z, f.w);
        ((uint2*)out)[i] = u;
    }
}

// ---------------- Wa transpose -> half -----------------------------------------
__global__ void transpose_wa(const float* __restrict__ Wa,
                             __half* __restrict__ top, __half* __restrict__ bot) {
    int idx = blockIdx.x * 256 + threadIdx.x;
    if (idx >= 2 * Hq * Hq) return;
    int k = idx / Hq;
    int n = idx - k * Hq;
    __half val = __float2half_rn(Wa[k * Hq + n]);
    if (k < Hq) top[n * Hq + k] = val;
    else        bot[n * Hq + (k - Hq)] = val;
}

// ---------------- fused softmax + weighted sum + emb gather -> rnn_in ----------
__global__ __launch_bounds__(256)
void softmax_weighted(const float* __restrict__ att,
                      const __half* __restrict__ enc_h,
                      const float* __restrict__ emb,
                      const int* __restrict__ loc,
                      __half* __restrict__ rnn_h) {
    int b = blockIdx.x;
    int t = threadIdx.x;
    __shared__ float satt[Sq];
    __shared__ float red[8];
    __shared__ float4 red4[256];

    float x = (t < Sq) ? att[b * Sq + t] : -3.4e38f;
    int lane = t & 31, w = t >> 5;

    // max
    float m = x;
    for (int o = 16; o > 0; o >>= 1) m = fmaxf(m, __shfl_down_sync(0xffffffffu, m, o));
    if (lane == 0) red[w] = m;
    __syncthreads();
    if (t == 0) {
        float mm = red[0];
        for (int i = 1; i < 8; i++) mm = fmaxf(mm, red[i]);
        red[0] = mm;
    }
    __syncthreads();
    m = red[0];
    __syncthreads();

    // sum
    float e = (t < Sq) ? expf(x - m) : 0.0f;
    float s = e;
    for (int o = 16; o > 0; o >>= 1) s += __shfl_down_sync(0xffffffffu, s, o);
    if (lane == 0) red[w] = s;
    __syncthreads();
    if (t == 0) {
        float ss = 0.0f;
        for (int i = 0; i < 8; i++) ss += red[i];
        red[0] = ss;
    }
    __syncthreads();
    float denom = red[0];
    if (t < Sq) satt[t] = e / denom;
    __syncthreads();

    // weighted sum over S + embedding gather
    int sp = t >> 6;        // 0..3
    int hq = t & 63;        // 4-half group within H
    const uint2* enc2 = (const uint2*)enc_h;
    float4 acc = make_float4(0.f, 0.f, 0.f, 0.f);
    for (int si = sp; si < Sq; si += 4) {
        float ww = satt[si];
        uint2 u = enc2[((size_t)si * Bq + b) * 64 + hq];
        float2 f0 = __half22float2(*(__half2*)&u.x);
        float2 f1 = __half22float2(*(__half2*)&u.y);
        acc.x += ww * f0.x; acc.y += ww * f0.y; acc.z += ww * f1.x; acc.w += ww * f1.y;
    }
    red4[t] = acc;
    __syncthreads();

    uint2* rnn2 = (uint2*)(rnn_h + (size_t)b * (Eq + Hq));
    if (t < 64) {
        float4 a0 = red4[t], a1 = red4[64 + t], a2 = red4[128 + t], a3 = red4[192 + t];
        uint2 u;
        u.x = f2h2(a0.x + a1.x + a2.x + a3.x, a0.y + a1.y + a2.y + a3.y);
        u.y = f2h2(a0.z + a1.z + a2.z + a3.z, a0.w + a1.w + a2.w + a3.w);
        rnn2[32 + t] = u;
    } else if (t < 96) {
        float4 f = ((const float4*)emb)[(size_t)loc[b] * 32 + (t - 64)];
        uint2 u;
        u.x = f2h2(f.x, f.y);
        u.y = f2h2(f.z, f.w);
        rnn2[t - 64] = u;
    }
}

// ---------------- GRU gates ----------------------------------------------------
__global__ void gru_kernel(const float* __restrict__ gi, const float* __restrict__ gh,
                           const float* __restrict__ h,
                           __half* __restrict__ hnew_h, float* __restrict__ out_h) {
    int b = blockIdx.x;
    int j = threadIdx.x;
    float ir = gi[b * 768 + j];
    float iz = gi[b * 768 + 256 + j];
    float in = gi[b * 768 + 512 + j];
    float hr = gh[b * 768 + j];
    float hz = gh[b * 768 + 256 + j];
    float hn = gh[b * 768 + 512 + j];
    float r = 1.0f / (1.0f + expf(-(ir + hr)));
    float z = 1.0f / (1.0f + expf(-(iz + hz)));
    float n = tanhf(in + r * hn);
    float hv = h[b * Hq + j];
    float hnv = (1.0f - z) * n + z * hv;
    hnew_h[b * Hq + j] = __float2half_rn(hnv);
    out_h[b * Hq + j] = hnv;
}

// ---------------- launch -------------------------------------------------------
extern "C" void kernel_launch(void* const* d_in, const int* in_sizes, int n_in,
                              void* d_out, int out_size) {
    const int*   input_loc = (const int*)d_in[0];
    const float* hidden    = (const float*)d_in[1];
    const float* enc       = (const float*)d_in[2];
    const int*   mask      = (const int*)d_in[3];
    const float* emb       = (const float*)d_in[4];
    const float* Wa        = (const float*)d_in[5];
    const float* ba        = (const float*)d_in[6];
    const float* v         = (const float*)d_in[7];
    const float* W_ih      = (const float*)d_in[8];
    const float* W_hh      = (const float*)d_in[9];
    const float* b_ih      = (const float*)d_in[10];
    const float* b_hh      = (const float*)d_in[11];
    const float* W_out     = (const float*)d_in[12];
    const float* b_out     = (const float*)d_in[13];
    float* out = (float*)d_out;
    float* out_pred = out;
    float* out_h    = out + (size_t)Bq * Vq;

    __half *enc_h, *Wout_h, *WaTtop_h, *WaTbot_h, *h_h, *Wih_h, *Whh_h, *rnnin_h, *hnew_h;
    float  *hWa, *att, *gi, *gh;
    cudaGetSymbolAddress((void**)&enc_h,    g_enc_h);
    cudaGetSymbolAddress((void**)&Wout_h,   g_Wout_h);
    cudaGetSymbolAddress((void**)&WaTtop_h, g_WaTtop_h);
    cudaGetSymbolAddress((void**)&WaTbot_h, g_WaTbot_h);
    cudaGetSymbolAddress((void**)&h_h,      g_h_h);
    cudaGetSymbolAddress((void**)&Wih_h,    g_Wih_h);
    cudaGetSymbolAddress((void**)&Whh_h,    g_Whh_h);
    cudaGetSymbolAddress((void**)&rnnin_h,  g_rnnin_h);
    cudaGetSymbolAddress((void**)&hnew_h,   g_hnew_h);
    cudaGetSymbolAddress((void**)&hWa,      g_hWa);
    cudaGetSymbolAddress((void**)&att,      g_att);
    cudaGetSymbolAddress((void**)&gi,       g_gi);
    cudaGetSymbolAddress((void**)&gh,       g_gh);

    cudaFuncSetAttribute(mma_gemm<0>, cudaFuncAttributeMaxDynamicSharedMemorySize, GTOT);
    cudaFuncSetAttribute(mma_gemm<1>, cudaFuncAttributeMaxDynamicSharedMemorySize, GTOT);

    // one-time stream/event resources (same launch sequence every call)
    static cudaStream_t s1 = nullptr, s2 = nullptr;
    static cudaEvent_t evFork = nullptr, evEnc = nullptr, evW2 = nullptr, evW = nullptr;
    if (!s1) {
        cudaStreamCreateWithFlags(&s1, cudaStreamNonBlocking);
        cudaStreamCreateWithFlags(&s2, cudaStreamNonBlocking);
        cudaEventCreateWithFlags(&evFork, cudaEventDisableTiming);
        cudaEventCreateWithFlags(&evEnc,  cudaEventDisableTiming);
        cudaEventCreateWithFlags(&evW2,   cudaEventDisableTiming);
        cudaEventCreateWithFlags(&evW,    cudaEventDisableTiming);
    }

    // fork
    cudaEventRecord(evFork, 0);
    cudaStreamWaitEvent(s1, evFork, 0);
    cudaStreamWaitEvent(s2, evFork, 0);

    // s1: enc conversion (needed by fused att GEMM + weighted)
    {
        int n4 = (Sq * Bq * Hq) / 4;
        f32to16<<<(n4 + 255) / 256, 256, 0, s1>>>(enc, enc_h, n4);
        cudaEventRecord(evEnc, s1);
    }
    // s2: GRU weights, then W_out (needed late)
    {
        int n4 = (3 * Hq * (Eq + Hq)) / 4;
        f32to16<<<(n4 + 255) / 256, 256, 0, s2>>>(W_ih, Wih_h, n4);
        n4 = (3 * Hq * Hq) / 4;
        f32to16<<<(n4 + 255) / 256, 256, 0, s2>>>(W_hh, Whh_h, n4);
        cudaEventRecord(evW2, s2);
        n4 = (Vq * Hq) / 4;
        f32to16<<<(n4 + 255) / 256, 256, 0, s2>>>(W_out, Wout_h, n4);
        cudaEventRecord(evW, s2);
    }

    // s0: hidden conv + Wa transpose + hWa GEMM (overlaps enc conversion)
    {
        int n4 = (Bq * Hq) / 4;
        f32to16<<<(n4 + 255) / 256, 256>>>(hidden, h_h, n4);
    }
    transpose_wa<<<512, 256>>>(Wa, WaTtop_h, WaTbot_h);

    // 2. hWa = h @ Wa_top + ba          (1024 x 256 x 256)
    mma_gemm<0><<<dim3(Bq / 128, 1), 256, GTOT>>>(
        h_h, WaTtop_h, ba, hWa, Bq, Hq, Hq,
        nullptr, nullptr, nullptr, nullptr,
        nullptr, nullptr, nullptr, nullptr, 0);

    // join enc, then fused att GEMM
    cudaStreamWaitEvent(0, evEnc, 0);

    // 3+4. fused: att = mask ? v . tanh(enc@Wa_bot + hWa) : -1e6
    mma_gemm<1><<<dim3((Sq * Bq) / 128, 1), 256, GTOT>>>(
        enc_h, WaTbot_h, nullptr, nullptr, Sq * Bq, Hq, Hq,
        hWa, v, mask, att,
        nullptr, nullptr, nullptr, nullptr, 0);

    // 5+6. fused softmax + weighted context + embedding gather
    softmax_weighted<<<Bq, 256>>>(att, enc_h, emb, input_loc, rnnin_h);

    // join GRU weights; 7+8. dual GEMM: z=0 gi (K=384), z=1 gh (K=256)
    cudaStreamWaitEvent(0, evW2, 0);
    mma_gemm<0><<<dim3(Bq / 128, 3, 2), 256, GTOT>>>(
        rnnin_h, Wih_h, b_ih, gi, Bq, 3 * Hq, Eq + Hq,
        nullptr, nullptr, nullptr, nullptr,
        h_h, Whh_h, b_hh, gh, Hq);

    // 9. GRU gates -> h_new (half for pred GEMM, fp32 to output)
    gru_kernel<<<Bq, Hq>>>(gi, gh, hidden, hnew_h, out_h);

    // join W_out; 10. pred = h_new @ W_out^T + b_out  (1024 x 100000 x 256)
    cudaStreamWaitEvent(0, evW, 0);
    mma_gemm<0><<<dim3(Bq / 128, (Vq + 255) / 256), 256, GTOT>>>(
        hnew_h, Wout_h, b_out, out_pred, Bq, Vq, Hq,
        nullptr, nullptr, nullptr, nullptr,
        nullptr, nullptr, nullptr, nullptr, 0);
}

// round 11
// speedup vs baseline: 4.1808x; 1.0192x over previous
#include <cuda_runtime.h>
#include <cuda_fp16.h>
#include <cstdint>
#include <cstddef>

// Problem dims
#define Bq 1024
#define Sq 200
#define Hq 256
#define Eq 128
#define Vq 100000

// ---------------- scratch (__device__ globals) ---------------------------------
__device__ __half g_enc_h[(size_t)Sq * Bq * Hq];   // 52.4 MB
__device__ __half g_Wout_h[(size_t)Vq * Hq];       // 51.2 MB
__device__ __half g_WaTtop_h[Hq * Hq];
__device__ __half g_WaTbot_h[Hq * Hq];
__device__ __half g_h_h[Bq * Hq];
__device__ __half g_Wih_h[3 * Hq * (Eq + Hq)];
__device__ __half g_Whh_h[3 * Hq * Hq];
__device__ __half g_rnnin_h[Bq * (Eq + Hq)];
__device__ __half g_hnew_h[Bq * Hq];
__device__ float  g_hWa[Bq * Hq];
__device__ float  g_att[Bq * Sq];
__device__ float  g_gi[Bq * 3 * Hq];
__device__ float  g_gh[Bq * 3 * Hq];

// ---------------- helpers ------------------------------------------------------
__device__ __forceinline__ uint32_t f2h2(float x, float y) {
    __half2 h = __floats2half2_rn(x, y);
    return *(uint32_t*)&h;
}

__device__ __forceinline__ uint32_t smem_u32(const void* p) {
    uint32_t a;
    asm("{ .reg .u64 t; cvta.to.shared.u64 t, %1; cvt.u32.u64 %0, t; }"
        : "=r"(a) : "l"(p));
    return a;
}

__device__ __forceinline__ void mma_fp16(float* c,
                                         uint32_t a0, uint32_t a1, uint32_t a2, uint32_t a3,
                                         uint32_t b0, uint32_t b1) {
    asm volatile(
        "mma.sync.aligned.m16n8k16.row.col.f32.f16.f16.f32 "
        "{%0,%1,%2,%3}, {%4,%5,%6,%7}, {%8,%9}, {%0,%1,%2,%3};\n"
        : "+f"(c[0]), "+f"(c[1]), "+f"(c[2]), "+f"(c[3])
        : "r"(a0), "r"(a1), "r"(a2), "r"(a3), "r"(b0), "r"(b1));
}

#define LDMX4(r0, r1, r2, r3, a)                                                \
    asm volatile("ldmatrix.sync.aligned.m8n8.x4.shared.b16 {%0,%1,%2,%3}, [%4];" \
                 : "=r"(r0), "=r"(r1), "=r"(r2), "=r"(r3) : "r"(a))

#define CPA16(dst, src, pred)                                                   \
    asm volatile("cp.async.cg.shared.global [%0], [%1], 16, %2;"                \
                 :: "r"(dst), "l"(src), "r"((pred) ? 16 : 0) : "memory")
#define CPA_COMMIT() asm volatile("cp.async.commit_group;" ::: "memory")
#define CPA_WAIT1()  asm volatile("cp.async.wait_group 1;" ::: "memory")

// ---------------- fp16 NT GEMM: C[M,N] = A[M,K] @ B[N,K]^T (+bias) -------------
// fp16 in, fp32 accumulate/out. Block 128x256 (8 warps of 64x64), K-chunk 32,
// 3-stage cp.async pipeline. Rows at 80-byte stride: conflict-free ldmatrix.
// M%128==0, K%32==0, N ragged OK. bm0 = m-tile offset (for sliced launches).
// FUSE==1: att epilogue (N==256, bn==0, global row = s*Bq + b).
#define ST_A 10240                 // 128 rows * 80 B
#define ST_B 20480                 // 256 rows * 80 B
#define STG  (ST_A + ST_B)         // 30720
#define GTOT (3 * STG)             // 92160

template <int FUSE>
__global__ __launch_bounds__(256, 1)
void mma_gemm(const __half* __restrict__ A, const __half* __restrict__ Bm,
              const float* __restrict__ bias, float* __restrict__ C,
              int M, int N, int K, int bm0,
              const float* __restrict__ hWa, const float* __restrict__ vvec,
              const int* __restrict__ mask, float* __restrict__ att) {
    extern __shared__ char smem[];
    const uint32_t sbase = smem_u32(smem);

    const int tid  = threadIdx.x;
    const int lane = tid & 31;
    const int warp = tid >> 5;
    const int wm = (warp >> 2) * 64;
    const int wn = (warp & 3) * 64;
    const int bm = (blockIdx.x + bm0) * 128;
    const int bn = blockIdx.y * 256;
    const int lq = lane >> 2;
    const int lr = lane & 3;

    __shared__ float rowsum[128];
    if (FUSE && tid < 128) rowsum[tid] = 0.0f;

    // per-lane ldmatrix byte offsets (within a stage)
    const int rin = lane & 7;
    uint32_t a_l[4], b_l[4];
    {
        const int r8   = (lane >> 3) & 1;
        const int kh_a = (lane >> 4) & 1;
        const int n8   = (lane >> 4) & 1;
        const int kh_b = (lane >> 3) & 1;
#pragma unroll
        for (int mf = 0; mf < 4; mf++)
            a_l[mf] = (uint32_t)((wm + mf * 16 + r8 * 8 + rin) * 80 + kh_a * 16);
#pragma unroll
        for (int p2 = 0; p2 < 4; p2++)
            b_l[p2] = (uint32_t)((wn + p2 * 16 + n8 * 8 + rin) * 80 + kh_b * 16);
    }

    float acc[4][8][4];
#pragma unroll
    for (int i = 0; i < 4; i++)
#pragma unroll
        for (int j = 0; j < 8; j++)
#pragma unroll
            for (int k = 0; k < 4; k++) acc[i][j][k] = 0.0f;

    const int nch = K / 32;

#define ISSUE(c)                                                            \
    do {                                                                    \
        const int kc = (c) * 32;                                            \
        const uint32_t sa0 = sbase + ((c) % 3) * STG;                       \
        const uint32_t sb0 = sa0 + ST_A;                                    \
        _Pragma("unroll")                                                   \
        for (int l = 0; l < 2; l++) {                                       \
            int q = tid + l * 256;                                          \
            int row = q >> 2, seg = q & 3;                                  \
            CPA16(sa0 + row * 80 + seg * 16,                                \
                  A + (size_t)(bm + row) * K + kc + seg * 8, true);         \
        }                                                                   \
        _Pragma("unroll")                                                   \
        for (int l = 0; l < 4; l++) {                                       \
            int q = tid + l * 256;                                          \
            int row = q >> 2, seg = q & 3;                                  \
            CPA16(sb0 + row * 80 + seg * 16,                                \
                  Bm + (size_t)(bn + row) * K + kc + seg * 8,               \
                  (bn + row) < N);                                          \
        }                                                                   \
    } while (0)

    // prologue: 2 chunks in flight
    ISSUE(0);
    CPA_COMMIT();
    if (nch > 1) ISSUE(1);
    CPA_COMMIT();

    for (int c = 0; c < nch; c++) {
        CPA_WAIT1();
        __syncthreads();
        if (c + 2 < nch) ISSUE(c + 2);
        CPA_COMMIT();

        const uint32_t aA = sbase + (c % 3) * STG;
        const uint32_t aB = aA + ST_A;

#pragma unroll
        for (int ks = 0; ks < 2; ks++) {
            uint32_t bf[8][2];
#pragma unroll
            for (int p2 = 0; p2 < 4; p2++)
                LDMX4(bf[2 * p2][0], bf[2 * p2][1], bf[2 * p2 + 1][0], bf[2 * p2 + 1][1],
                      aB + b_l[p2] + ks * 32);
#pragma unroll
            for (int mf = 0; mf < 4; mf++) {
                uint32_t a0, a1, a2, a3;
                LDMX4(a0, a1, a2, a3, aA + a_l[mf] + ks * 32);
#pragma unroll
                for (int nf = 0; nf < 8; nf++)
                    mma_fp16(acc[mf][nf], a0, a1, a2, a3, bf[nf][0], bf[nf][1]);
            }
        }
    }
#undef ISSUE

    if (FUSE) {
#pragma unroll
        for (int mf = 0; mf < 4; mf++) {
            int r0g = bm + wm + mf * 16 + lq;
            int b0 = r0g & (Bq - 1);
            int b1 = (r0g + 8) & (Bq - 1);
            float p0 = 0.0f, p1 = 0.0f;
#pragma unroll
            for (int nf = 0; nf < 8; nf++) {
#pragma unroll
                for (int c2 = 0; c2 < 2; c2++) {
                    int col = wn + nf * 8 + lr * 2 + c2;
                    float vv = vvec[col];
                    p0 += tanhf(acc[mf][nf][c2]     + hWa[b0 * Hq + col]) * vv;
                    p1 += tanhf(acc[mf][nf][2 + c2] + hWa[b1 * Hq + col]) * vv;
                }
            }
            p0 += __shfl_xor_sync(0xffffffffu, p0, 1);
            p0 += __shfl_xor_sync(0xffffffffu, p0, 2);
            p1 += __shfl_xor_sync(0xffffffffu, p1, 1);
            p1 += __shfl_xor_sync(0xffffffffu, p1, 2);
            if (lr == 0) {
                atomicAdd(&rowsum[wm + mf * 16 + lq], p0);
                atomicAdd(&rowsum[wm + mf * 16 + lq + 8], p1);
            }
        }
        __syncthreads();
        if (tid < 128) {
            int row = bm + tid;            // = s*Bq + b
            int s = row >> 10;
            int b = row & (Bq - 1);
            att[b * Sq + s] = (mask[b * Sq + s] == 0) ? -1000000.0f : rowsum[tid];
        }
    } else {
#pragma unroll
        for (int mf = 0; mf < 4; mf++) {
            int r0 = bm + wm + mf * 16 + lq;
#pragma unroll
            for (int nf = 0; nf < 8; nf++) {
                int col = bn + wn + nf * 8 + lr * 2;
                if (col < N) {
                    float b0 = bias ? bias[col] : 0.0f;
                    float b1 = bias ? bias[col + 1] : 0.0f;
                    *(float2*)(C + (size_t)r0 * N + col) =
                        make_float2(acc[mf][nf][0] + b0, acc[mf][nf][1] + b1);
                    *(float2*)(C + (size_t)(r0 + 8) * N + col) =
                        make_float2(acc[mf][nf][2] + b0, acc[mf][nf][3] + b1);
                }
            }
        }
    }
}

// ---------------- fp32 -> fp16 convert (n % 4 == 0) ----------------------------
__global__ void f32to16(const float* __restrict__ in, __half* __restrict__ out, int n4) {
    int i = blockIdx.x * 256 + threadIdx.x;
    if (i < n4) {
        float4 f = ((const float4*)in)[i];
        uint2 u;
        u.x = f2h2(f.x, f.y);
        u.y = f2h2(f.z, f.w);
        ((uint2*)out)[i] = u;
    }
}

// ---------------- Wa transpose -> half -----------------------------------------
__global__ void transpose_wa(const float* __restrict__ Wa,
                             __half* __restrict__ top, __half* __restrict__ bot) {
    int idx = blockIdx.x * 256 + threadIdx.x;
    if (idx >= 2 * Hq * Hq) return;
    int k = idx / Hq;
    int n = idx - k * Hq;
    __half val = __float2half_rn(Wa[k * Hq + n]);
    if (k < Hq) top[n * Hq + k] = val;
    else        bot[n * Hq + (k - Hq)] = val;
}

// ---------------- fused softmax + weighted sum + emb gather -> rnn_in ----------
__global__ __launch_bounds__(256)
void softmax_weighted(const float* __restrict__ att,
                      const __half* __restrict__ enc_h,
                      const float* __restrict__ emb,
                      const int* __restrict__ loc,
                      __half* __restrict__ rnn_h) {
    int b = blockIdx.x;
    int t = threadIdx.x;
    __shared__ float satt[Sq];
    __shared__ float red[8];
    __shared__ float4 red4[256];

    float x = (t < Sq) ? att[b * Sq + t] : -3.4e38f;
    int lane = t & 31, w = t >> 5;

    float m = x;
    for (int o = 16; o > 0; o >>= 1) m = fmaxf(m, __shfl_down_sync(0xffffffffu, m, o));
    if (lane == 0) red[w] = m;
    __syncthreads();
    if (t == 0) {
        float mm = red[0];
        for (int i = 1; i < 8; i++) mm = fmaxf(mm, red[i]);
        red[0] = mm;
    }
    __syncthreads();
    m = red[0];
    __syncthreads();

    float e = (t < Sq) ? expf(x - m) : 0.0f;
    float s = e;
    for (int o = 16; o > 0; o >>= 1) s += __shfl_down_sync(0xffffffffu, s, o);
    if (lane == 0) red[w] = s;
    __syncthreads();
    if (t == 0) {
        float ss = 0.0f;
        for (int i = 0; i < 8; i++) ss += red[i];
        red[0] = ss;
    }
    __syncthreads();
    float denom = red[0];
    if (t < Sq) satt[t] = e / denom;
    __syncthreads();

    int sp = t >> 6;
    int hq = t & 63;
    const uint2* enc2 = (const uint2*)enc_h;
    float4 acc = make_float4(0.f, 0.f, 0.f, 0.f);
    for (int si = sp; si < Sq; si += 4) {
        float ww = satt[si];
        uint2 u = enc2[((size_t)si * Bq + b) * 64 + hq];
        float2 f0 = __half22float2(*(__half2*)&u.x);
        float2 f1 = __half22float2(*(__half2*)&u.y);
        acc.x += ww * f0.x; acc.y += ww * f0.y; acc.z += ww * f1.x; acc.w += ww * f1.y;
    }
    red4[t] = acc;
    __syncthreads();

    uint2* rnn2 = (uint2*)(rnn_h + (size_t)b * (Eq + Hq));
    if (t < 64) {
        float4 a0 = red4[t], a1 = red4[64 + t], a2 = red4[128 + t], a3 = red4[192 + t];
        uint2 u;
        u.x = f2h2(a0.x + a1.x + a2.x + a3.x, a0.y + a1.y + a2.y + a3.y);
        u.y = f2h2(a0.z + a1.z + a2.z + a3.z, a0.w + a1.w + a2.w + a3.w);
        rnn2[32 + t] = u;
    } else if (t < 96) {
        float4 f = ((const float4*)emb)[(size_t)loc[b] * 32 + (t - 64)];
        uint2 u;
        u.x = f2h2(f.x, f.y);
        u.y = f2h2(f.z, f.w);
        rnn2[t - 64] = u;
    }
}

// ---------------- GRU gates ----------------------------------------------------
__global__ void gru_kernel(const float* __restrict__ gi, const float* __restrict__ gh,
                           const float* __restrict__ h,
                           __half* __restrict__ hnew_h, float* __restrict__ out_h) {
    int b = blockIdx.x;
    int j = threadIdx.x;
    float ir = gi[b * 768 + j];
    float iz = gi[b * 768 + 256 + j];
    float in = gi[b * 768 + 512 + j];
    float hr = gh[b * 768 + j];
    float hz = gh[b * 768 + 256 + j];
    float hn = gh[b * 768 + 512 + j];
    float r = 1.0f / (1.0f + expf(-(ir + hr)));
    float z = 1.0f / (1.0f + expf(-(iz + hz)));
    float n = tanhf(in + r * hn);
    float hv = h[b * Hq + j];
    float hnv = (1.0f - z) * n + z * hv;
    hnew_h[b * Hq + j] = __float2half_rn(hnv);
    out_h[b * Hq + j] = hnv;
}

// ---------------- launch -------------------------------------------------------
extern "C" void kernel_launch(void* const* d_in, const int* in_sizes, int n_in,
                              void* d_out, int out_size) {
    const int*   input_loc = (const int*)d_in[0];
    const float* hidden    = (const float*)d_in[1];
    const float* enc       = (const float*)d_in[2];
    const int*   mask      = (const int*)d_in[3];
    const float* emb       = (const float*)d_in[4];
    const float* Wa        = (const float*)d_in[5];
    const float* ba        = (const float*)d_in[6];
    const float* v         = (const float*)d_in[7];
    const float* W_ih      = (const float*)d_in[8];
    const float* W_hh      = (const float*)d_in[9];
    const float* b_ih      = (const float*)d_in[10];
    const float* b_hh      = (const float*)d_in[11];
    const float* W_out     = (const float*)d_in[12];
    const float* b_out     = (const float*)d_in[13];
    float* out = (float*)d_out;
    float* out_pred = out;
    float* out_h    = out + (size_t)Bq * Vq;

    __half *enc_h, *Wout_h, *WaTtop_h, *WaTbot_h, *h_h, *Wih_h, *Whh_h, *rnnin_h, *hnew_h;
    float  *hWa, *att, *gi, *gh;
    cudaGetSymbolAddress((void**)&enc_h,    g_enc_h);
    cudaGetSymbolAddress((void**)&Wout_h,   g_Wout_h);
    cudaGetSymbolAddress((void**)&WaTtop_h, g_WaTtop_h);
    cudaGetSymbolAddress((void**)&WaTbot_h, g_WaTbot_h);
    cudaGetSymbolAddress((void**)&h_h,      g_h_h);
    cudaGetSymbolAddress((void**)&Wih_h,    g_Wih_h);
    cudaGetSymbolAddress((void**)&Whh_h,    g_Whh_h);
    cudaGetSymbolAddress((void**)&rnnin_h,  g_rnnin_h);
    cudaGetSymbolAddress((void**)&hnew_h,   g_hnew_h);
    cudaGetSymbolAddress((void**)&hWa,      g_hWa);
    cudaGetSymbolAddress((void**)&att,      g_att);
    cudaGetSymbolAddress((void**)&gi,       g_gi);
    cudaGetSymbolAddress((void**)&gh,       g_gh);

    cudaFuncSetAttribute(mma_gemm<0>, cudaFuncAttributeMaxDynamicSharedMemorySize, GTOT);
    cudaFuncSetAttribute(mma_gemm<1>, cudaFuncAttributeMaxDynamicSharedMemorySize, GTOT);

    // one-time stream/event resources (same launch sequence every call)
    static cudaStream_t s1 = nullptr, s2 = nullptr;
    static cudaEvent_t evFork = nullptr, evHh = nullptr, evGh = nullptr, evW = nullptr;
    static cudaEvent_t evEnc[4] = {nullptr, nullptr, nullptr, nullptr};
    if (!s1) {
        cudaStreamCreateWithFlags(&s1, cudaStreamNonBlocking);
        cudaStreamCreateWithFlags(&s2, cudaStreamNonBlocking);
        cudaEventCreateWithFlags(&evFork, cudaEventDisableTiming);
        cudaEventCreateWithFlags(&evHh,   cudaEventDisableTiming);
        cudaEventCreateWithFlags(&evGh,   cudaEventDisableTiming);
        cudaEventCreateWithFlags(&evW,    cudaEventDisableTiming);
        for (int i = 0; i < 4; i++)
            cudaEventCreateWithFlags(&evEnc[i], cudaEventDisableTiming);
    }

    // fork
    cudaEventRecord(evFork, 0);
    cudaStreamWaitEvent(s1, evFork, 0);
    cudaStreamWaitEvent(s2, evFork, 0);

    // s1: enc conversion in 4 slices (row-major s-slices)
    {
        const int n4s = (Sq * Bq * Hq) / 4 / 4;   // float4 per slice
        for (int i = 0; i < 4; i++) {
            f32to16<<<(n4s + 255) / 256, 256, 0, s1>>>(
                enc + (size_t)i * n4s * 4, enc_h + (size_t)i * n4s * 4, n4s);
            cudaEventRecord(evEnc[i], s1);
        }
    }

    // s0: hidden conv (evHh) + Wa transpose + hWa GEMM
    {
        int n4 = (Bq * Hq) / 4;
        f32to16<<<(n4 + 255) / 256, 256>>>(hidden, h_h, n4);
        cudaEventRecord(evHh, 0);
    }
    transpose_wa<<<512, 256>>>(Wa, WaTtop_h, WaTbot_h);
    mma_gemm<0><<<dim3(Bq / 128, 1), 256, GTOT>>>(
        h_h, WaTtop_h, ba, hWa, Bq, Hq, Hq, 0,
        nullptr, nullptr, nullptr, nullptr);

    // s2: GRU weight conversions, early gh GEMM, then W_out conversion
    {
        int n4 = (3 * Hq * (Eq + Hq)) / 4;
        f32to16<<<(n4 + 255) / 256, 256, 0, s2>>>(W_ih, Wih_h, n4);
        n4 = (3 * Hq * Hq) / 4;
        f32to16<<<(n4 + 255) / 256, 256, 0, s2>>>(W_hh, Whh_h, n4);
        cudaStreamWaitEvent(s2, evHh, 0);
        mma_gemm<0><<<dim3(Bq / 128, 3), 256, GTOT, s2>>>(
            h_h, Whh_h, b_hh, gh, Bq, 3 * Hq, Hq, 0,
            nullptr, nullptr, nullptr, nullptr);
        cudaEventRecord(evGh, s2);
        n4 = (Vq * Hq) / 4;
        f32to16<<<(n4 + 255) / 256, 256, 0, s2>>>(W_out, Wout_h, n4);
        cudaEventRecord(evW, s2);
    }

    // s0: att GEMM in 4 m-tile slices pipelined against enc conversion
    for (int i = 0; i < 4; i++) {
        cudaStreamWaitEvent(0, evEnc[i], 0);
        mma_gemm<1><<<dim3(400, 1), 256, GTOT>>>(
            enc_h, WaTbot_h, nullptr, nullptr, Sq * Bq, Hq, Hq, i * 400,
            hWa, v, mask, att);
    }

    // softmax + weighted context + embedding gather
    softmax_weighted<<<Bq, 256>>>(att, enc_h, emb, input_loc, rnnin_h);

    // gi = rnn_in @ W_ih^T + b_ih
    mma_gemm<0><<<dim3(Bq / 128, 3), 256, GTOT>>>(
        rnnin_h, Wih_h, b_ih, gi, Bq, 3 * Hq, Eq + Hq, 0,
        nullptr, nullptr, nullptr, nullptr);

    // GRU gates (join gh)
    cudaStreamWaitEvent(0, evGh, 0);
    gru_kernel<<<Bq, Hq>>>(gi, gh, hidden, hnew_h, out_h);

    // pred = h_new @ W_out^T + b_out (join W_out conversion)
    cudaStreamWaitEvent(0, evW, 0);
    mma_gemm<0><<<dim3(Bq / 128, (Vq + 255) / 256), 256, GTOT>>>(
        hnew_h, Wout_h, b_out, out_pred, Bq, Vq, Hq, 0,
        nullptr, nullptr, nullptr, nullptr);
}

// round 13
// speedup vs baseline: 4.5748x; 1.0942x over previous
#include <cuda_runtime.h>
#include <cuda_fp16.h>
#include <cstdint>
#include <cstddef>

// Problem dims
#define Bq 1024
#define Sq 200
#define Hq 256
#define Eq 128
#define Vq 100000
#define SLICE_S   50            // s per slice
#define SLICE_CAP (SLICE_S * Bq)   // 51200 rows max per slice

// ---------------- scratch (__device__ globals) ---------------------------------
__device__ __half g_enc_h[(size_t)Sq * Bq * Hq];   // 52.4 MB
__device__ __half g_Wout_h[(size_t)Vq * Hq];       // 51.2 MB
__device__ __half g_WaTtop_h[Hq * Hq];
__device__ __half g_WaTbot_h[Hq * Hq];
__device__ __half g_h_h[Bq * Hq];
__device__ __half g_Wih_h[3 * Hq * (Eq + Hq)];
__device__ __half g_Whh_h[3 * Hq * Hq];
__device__ __half g_rnnin_h[Bq * (Eq + Hq)];
__device__ __half g_hnew_h[Bq * Hq];
__device__ float  g_hWa[Bq * Hq];
__device__ float  g_att[Bq * Sq];
__device__ float  g_gi[Bq * 3 * Hq];
__device__ float  g_gh[Bq * 3 * Hq];
__device__ int    g_idx[4 * SLICE_CAP];
__device__ int    g_cnt[4];

// ---------------- helpers ------------------------------------------------------
__device__ __forceinline__ uint32_t f2h2(float x, float y) {
    __half2 h = __floats2half2_rn(x, y);
    return *(uint32_t*)&h;
}

__device__ __forceinline__ uint32_t smem_u32(const void* p) {
    uint32_t a;
    asm("{ .reg .u64 t; cvta.to.shared.u64 t, %1; cvt.u32.u64 %0, t; }"
        : "=r"(a) : "l"(p));
    return a;
}

__device__ __forceinline__ void mma_fp16(float* c,
                                         uint32_t a0, uint32_t a1, uint32_t a2, uint32_t a3,
                                         uint32_t b0, uint32_t b1) {
    asm volatile(
        "mma.sync.aligned.m16n8k16.row.col.f32.f16.f16.f32 "
        "{%0,%1,%2,%3}, {%4,%5,%6,%7}, {%8,%9}, {%0,%1,%2,%3};\n"
        : "+f"(c[0]), "+f"(c[1]), "+f"(c[2]), "+f"(c[3])
        : "r"(a0), "r"(a1), "r"(a2), "r"(a3), "r"(b0), "r"(b1));
}

#define LDMX4(r0, r1, r2, r3, a)                                                \
    asm volatile("ldmatrix.sync.aligned.m8n8.x4.shared.b16 {%0,%1,%2,%3}, [%4];" \
                 : "=r"(r0), "=r"(r1), "=r"(r2), "=r"(r3) : "r"(a))

#define CPA16(dst, src, pred)                                                   \
    asm volatile("cp.async.cg.shared.global [%0], [%1], 16, %2;"                \
                 :: "r"(dst), "l"(src), "r"((pred) ? 16 : 0) : "memory")
#define CPA_COMMIT() asm volatile("cp.async.commit_group;" ::: "memory")
#define CPA_WAIT1()  asm volatile("cp.async.wait_group 1;" ::: "memory")

// ---------------- fp16 NT GEMM: C[M,N] = A[M,K] @ B[N,K]^T (+bias) -------------
// fp16 in, fp32 accumulate/out. Block 128x256 (8 warps of 64x64), K-chunk 32,
// 3-stage cp.async pipeline. Rows at 80-byte stride: conflict-free ldmatrix.
// M%128==0, K%32==0, N ragged OK.
// FUSE==1: mask-compacted att rows. A-rows gathered via idxp[0..*cntp);
// epilogue writes att[b*Sq+s] = v . tanh(row + hWa[b,:]) for real rows only.
#define ST_A 10240                 // 128 rows * 80 B
#define ST_B 20480                 // 256 rows * 80 B
#define STG  (ST_A + ST_B)         // 30720
#define GTOT (3 * STG)             // 92160

template <int FUSE>
__global__ __launch_bounds__(256, 1)
void mma_gemm(const __half* __restrict__ A, const __half* __restrict__ Bm,
              const float* __restrict__ bias, float* __restrict__ C,
              int M, int N, int K,
              const float* __restrict__ hWa, const float* __restrict__ vvec,
              float* __restrict__ att,
              const int* __restrict__ idxp, const int* __restrict__ cntp) {
    extern __shared__ char smem[];
    const uint32_t sbase = smem_u32(smem);

    const int tid  = threadIdx.x;
    const int lane = tid & 31;
    const int warp = tid >> 5;
    const int wm = (warp >> 2) * 64;
    const int wn = (warp & 3) * 64;
    const int bm = blockIdx.x * 128;
    const int bn = blockIdx.y * 256;
    const int lq = lane >> 2;
    const int lr = lane & 3;

    __shared__ float rowsum[128];
    __shared__ int   sidx[128];

    int cnt_v = 0;
    if (FUSE) {
        cnt_v = *cntp;
        if (bm >= cnt_v) return;
        if (tid < 128) {
            int g = bm + tid;
            sidx[tid] = (g < cnt_v) ? idxp[g] : idxp[0];
            rowsum[tid] = 0.0f;
        }
        __syncthreads();
    }

    // per-thread A source row bases (gathered for FUSE)
    size_t aoffs[2];
    {
        int r0 = tid >> 2;
        if (FUSE) {
            aoffs[0] = (size_t)sidx[r0] * K;
            aoffs[1] = (size_t)sidx[r0 + 64] * K;
        } else {
            aoffs[0] = (size_t)(bm + r0) * K;
            aoffs[1] = (size_t)(bm + r0 + 64) * K;
        }
    }

    // per-lane ldmatrix byte offsets (within a stage)
    const int rin = lane & 7;
    uint32_t a_l[4], b_l[4];
    {
        const int r8   = (lane >> 3) & 1;
        const int kh_a = (lane >> 4) & 1;
        const int n8   = (lane >> 4) & 1;
        const int kh_b = (lane >> 3) & 1;
#pragma unroll
        for (int mf = 0; mf < 4; mf++)
            a_l[mf] = (uint32_t)((wm + mf * 16 + r8 * 8 + rin) * 80 + kh_a * 16);
#pragma unroll
        for (int p2 = 0; p2 < 4; p2++)
            b_l[p2] = (uint32_t)((wn + p2 * 16 + n8 * 8 + rin) * 80 + kh_b * 16);
    }

    float acc[4][8][4];
#pragma unroll
    for (int i = 0; i < 4; i++)
#pragma unroll
        for (int j = 0; j < 8; j++)
#pragma unroll
            for (int k = 0; k < 4; k++) acc[i][j][k] = 0.0f;

    const int nch = K / 32;

#define ISSUE(c)                                                            \
    do {                                                                    \
        const int kc = (c) * 32;                                            \
        const uint32_t sa0 = sbase + ((c) % 3) * STG;                       \
        const uint32_t sb0 = sa0 + ST_A;                                    \
        _Pragma("unroll")                                                   \
        for (int l = 0; l < 2; l++) {                                       \
            int q = tid + l * 256;                                          \
            int row = q >> 2, seg = q & 3;                                  \
            CPA16(sa0 + row * 80 + seg * 16,                                \
                  A + aoffs[l] + kc + seg * 8, true);                       \
        }                                                                   \
        _Pragma("unroll")                                                   \
        for (int l = 0; l < 4; l++) {                                       \
            int q = tid + l * 256;                                          \
            int row = q >> 2, seg = q & 3;                                  \
            CPA16(sb0 + row * 80 + seg * 16,                                \
                  Bm + (size_t)(bn + row) * K + kc + seg * 8,               \
                  (bn + row) < N);                                          \
        }                                                                   \
    } while (0)

    // prologue: 2 chunks in flight
    ISSUE(0);
    CPA_COMMIT();
    if (nch > 1) ISSUE(1);
    CPA_COMMIT();

    for (int c = 0; c < nch; c++) {
        CPA_WAIT1();
        __syncthreads();
        if (c + 2 < nch) ISSUE(c + 2);
        CPA_COMMIT();

        const uint32_t aA = sbase + (c % 3) * STG;
        const uint32_t aB = aA + ST_A;

#pragma unroll
        for (int ks = 0; ks < 2; ks++) {
            uint32_t bf[8][2];
#pragma unroll
            for (int p2 = 0; p2 < 4; p2++)
                LDMX4(bf[2 * p2][0], bf[2 * p2][1], bf[2 * p2 + 1][0], bf[2 * p2 + 1][1],
                      aB + b_l[p2] + ks * 32);
#pragma unroll
            for (int mf = 0; mf < 4; mf++) {
                uint32_t a0, a1, a2, a3;
                LDMX4(a0, a1, a2, a3, aA + a_l[mf] + ks * 32);
#pragma unroll
                for (int nf = 0; nf < 8; nf++)
                    mma_fp16(acc[mf][nf], a0, a1, a2, a3, bf[nf][0], bf[nf][1]);
            }
        }
    }
#undef ISSUE

    if (FUSE) {
        // att epilogue: per-row v . tanh(row + hWa[b,:]); rows from sidx
#pragma unroll
        for (int mf = 0; mf < 4; mf++) {
            int l0 = wm + mf * 16 + lq;
            int b0 = sidx[l0] & (Bq - 1);
            int b1 = sidx[l0 + 8] & (Bq - 1);
            float p0 = 0.0f, p1 = 0.0f;
#pragma unroll
            for (int nf = 0; nf < 8; nf++) {
#pragma unroll
                for (int c2 = 0; c2 < 2; c2++) {
                    int col = wn + nf * 8 + lr * 2 + c2;
                    float vv = vvec[col];
                    p0 += tanhf(acc[mf][nf][c2]     + hWa[b0 * Hq + col]) * vv;
                    p1 += tanhf(acc[mf][nf][2 + c2] + hWa[b1 * Hq + col]) * vv;
                }
            }
            p0 += __shfl_xor_sync(0xffffffffu, p0, 1);
            p0 += __shfl_xor_sync(0xffffffffu, p0, 2);
            p1 += __shfl_xor_sync(0xffffffffu, p1, 1);
            p1 += __shfl_xor_sync(0xffffffffu, p1, 2);
            if (lr == 0) {
                atomicAdd(&rowsum[l0], p0);
                atomicAdd(&rowsum[l0 + 8], p1);
            }
        }
        __syncthreads();
        if (tid < 128 && (bm + tid) < cnt_v) {
            int row = sidx[tid];           // = s*Bq + b
            int s = row >> 10;
            int b = row & (Bq - 1);
            att[b * Sq + s] = rowsum[tid];
        }
    } else {
#pragma unroll
        for (int mf = 0; mf < 4; mf++) {
            int r0 = bm + wm + mf * 16 + lq;
#pragma unroll
            for (int nf = 0; nf < 8; nf++) {
                int col = bn + wn + nf * 8 + lr * 2;
                if (col < N) {
                    float b0 = bias ? bias[col] : 0.0f;
                    float b1 = bias ? bias[col + 1] : 0.0f;
                    *(float2*)(C + (size_t)r0 * N + col) =
                        make_float2(acc[mf][nf][0] + b0, acc[mf][nf][1] + b1);
                    *(float2*)(C + (size_t)(r0 + 8) * N + col) =
                        make_float2(acc[mf][nf][2] + b0, acc[mf][nf][3] + b1);
                }
            }
        }
    }
}

// ---------------- reset: att = -1e6, counters = 0 ------------------------------
__global__ void reset_att(float* __restrict__ att, int* __restrict__ cnt) {
    int i = blockIdx.x * 256 + threadIdx.x;
    if (i < Bq * Sq) att[i] = -1000000.0f;
    if (i < 4) cnt[i] = 0;
}

// ---------------- mask stream-compaction (per s-slice lists) -------------------
// grid 800 x 256; block covers one s (256 consecutive b) -> slice uniform.
__global__ void scan_mask(const int* __restrict__ mask,
                          int* __restrict__ idx, int* __restrict__ cnt) {
    int i = blockIdx.x * 256 + threadIdx.x;       // row id = s*Bq + b
    int s = i >> 10;
    int b = i & (Bq - 1);
    bool keep = mask[b * Sq + s] != 0;

    int lane = threadIdx.x & 31, w = threadIdx.x >> 5;
    unsigned bal = __ballot_sync(0xffffffffu, keep);
    int wcnt = __popc(bal);

    __shared__ int wbase[8];
    __shared__ int btot;
    __shared__ int bbase;
    if (threadIdx.x == 0) btot = 0;
    __syncthreads();
    if (lane == 0) wbase[w] = atomicAdd(&btot, wcnt);
    __syncthreads();
    if (threadIdx.x == 0) bbase = atomicAdd(&cnt[s / SLICE_S], btot);
    __syncthreads();
    if (keep) {
        int off = bbase + wbase[w] + __popc(bal & ((1u << lane) - 1u));
        idx[(s / SLICE_S) * SLICE_CAP + off] = i;
    }
}

// ---------------- fp32 -> fp16 convert (n % 4 == 0) ----------------------------
__global__ void f32to16(const float* __restrict__ in, __half* __restrict__ out, int n4) {
    int i = blockIdx.x * 256 + threadIdx.x;
    if (i < n4) {
        float4 f = ((const float4*)in)[i];
        uint2 u;
        u.x = f2h2(f.x, f.y);
        u.y = f2h2(f.z, f.w);
        ((uint2*)out)[i] = u;
    }
}

// ---------------- Wa transpose -> half -----------------------------------------
__global__ void transpose_wa(const float* __restrict__ Wa,
                             __half* __restrict__ top, __half* __restrict__ bot) {
    int idx = blockIdx.x * 256 + threadIdx.x;
    if (idx >= 2 * Hq * Hq) return;
    int k = idx / Hq;
    int n = idx - k * Hq;
    __half val = __float2half_rn(Wa[k * Hq + n]);
    if (k < Hq) top[n * Hq + k] = val;
    else        bot[n * Hq + (k - Hq)] = val;
}

// ---------------- fused softmax + weighted sum + emb gather -> rnn_in ----------
__global__ __launch_bounds__(256)
void softmax_weighted(const float* __restrict__ att,
                      const __half* __restrict__ enc_h,
                      const float* __restrict__ emb,
                      const int* __restrict__ loc,
                      __half* __restrict__ rnn_h) {
    int b = blockIdx.x;
    int t = threadIdx.x;
    __shared__ float satt[Sq];
    __shared__ float red[8];
    __shared__ float4 red4[256];

    float x = (t < Sq) ? att[b * Sq + t] : -3.4e38f;
    int lane = t & 31, w = t >> 5;

    float m = x;
    for (int o = 16; o > 0; o >>= 1) m = fmaxf(m, __shfl_down_sync(0xffffffffu, m, o));
    if (lane == 0) red[w] = m;
    __syncthreads();
    if (t == 0) {
        float mm = red[0];
        for (int i = 1; i < 8; i++) mm = fmaxf(mm, red[i]);
        red[0] = mm;
    }
    __syncthreads();
    m = red[0];
    __syncthreads();

    float e = (t < Sq) ? expf(x - m) : 0.0f;
    float s = e;
    for (int o = 16; o > 0; o >>= 1) s += __shfl_down_sync(0xffffffffu, s, o);
    if (lane == 0) red[w] = s;
    __syncthreads();
    if (t == 0) {
        float ss = 0.0f;
        for (int i = 0; i < 8; i++) ss += red[i];
        red[0] = ss;
    }
    __syncthreads();
    float denom = red[0];
    if (t < Sq) satt[t] = e / denom;
    __syncthreads();

    int sp = t >> 6;
    int hq = t & 63;
    const uint2* enc2 = (const uint2*)enc_h;
    float4 acc = make_float4(0.f, 0.f, 0.f, 0.f);
    for (int si = sp; si < Sq; si += 4) {
        float ww = satt[si];
        uint2 u = enc2[((size_t)si * Bq + b) * 64 + hq];
        float2 f0 = __half22float2(*(__half2*)&u.x);
        float2 f1 = __half22float2(*(__half2*)&u.y);
        acc.x += ww * f0.x; acc.y += ww * f0.y; acc.z += ww * f1.x; acc.w += ww * f1.y;
    }
    red4[t] = acc;
    __syncthreads();

    uint2* rnn2 = (uint2*)(rnn_h + (size_t)b * (Eq + Hq));
    if (t < 64) {
        float4 a0 = red4[t], a1 = red4[64 + t], a2 = red4[128 + t], a3 = red4[192 + t];
        uint2 u;
        u.x = f2h2(a0.x + a1.x + a2.x + a3.x, a0.y + a1.y + a2.y + a3.y);
        u.y = f2h2(a0.z + a1.z + a2.z + a3.z, a0.w + a1.w + a2.w + a3.w);
        rnn2[32 + t] = u;
    } else if (t < 96) {
        float4 f = ((const float4*)emb)[(size_t)loc[b] * 32 + (t - 64)];
        uint2 u;
        u.x = f2h2(f.x, f.y);
        u.y = f2h2(f.z, f.w);
        rnn2[t - 64] = u;
    }
}

// ---------------- GRU gates ----------------------------------------------------
__global__ void gru_kernel(const float* __restrict__ gi, const float* __restrict__ gh,
                           const float* __restrict__ h,
                           __half* __restrict__ hnew_h, float* __restrict__ out_h) {
    int b = blockIdx.x;
    int j = threadIdx.x;
    float ir = gi[b * 768 + j];
    float iz = gi[b * 768 + 256 + j];
    float in = gi[b * 768 + 512 + j];
    float hr = gh[b * 768 + j];
    float hz = gh[b * 768 + 256 + j];
    float hn = gh[b * 768 + 512 + j];
    float r = 1.0f / (1.0f + expf(-(ir + hr)));
    float z = 1.0f / (1.0f + expf(-(iz + hz)));
    float n = tanhf(in + r * hn);
    float hv = h[b * Hq + j];
    float hnv = (1.0f - z) * n + z * hv;
    hnew_h[b * Hq + j] = __float2half_rn(hnv);
    out_h[b * Hq + j] = hnv;
}

// ---------------- launch -------------------------------------------------------
extern "C" void kernel_launch(void* const* d_in, const int* in_sizes, int n_in,
                              void* d_out, int out_size) {
    const int*   input_loc = (const int*)d_in[0];
    const float* hidden    = (const float*)d_in[1];
    const float* enc       = (const float*)d_in[2];
    const int*   mask      = (const int*)d_in[3];
    const float* emb       = (const float*)d_in[4];
    const float* Wa        = (const float*)d_in[5];
    const float* ba        = (const float*)d_in[6];
    const float* v         = (const float*)d_in[7];
    const float* W_ih      = (const float*)d_in[8];
    const float* W_hh      = (const float*)d_in[9];
    const float* b_ih      = (const float*)d_in[10];
    const float* b_hh      = (const float*)d_in[11];
    const float* W_out     = (const float*)d_in[12];
    const float* b_out     = (const float*)d_in[13];
    float* out = (float*)d_out;
    float* out_pred = out;
    float* out_h    = out + (size_t)Bq * Vq;

    __half *enc_h, *Wout_h, *WaTtop_h, *WaTbot_h, *h_h, *Wih_h, *Whh_h, *rnnin_h, *hnew_h;
    float  *hWa, *att, *gi, *gh;
    int    *idx, *cnt;
    cudaGetSymbolAddress((void**)&enc_h,    g_enc_h);
    cudaGetSymbolAddress((void**)&Wout_h,   g_Wout_h);
    cudaGetSymbolAddress((void**)&WaTtop_h, g_WaTtop_h);
    cudaGetSymbolAddress((void**)&WaTbot_h, g_WaTbot_h);
    cudaGetSymbolAddress((void**)&h_h,      g_h_h);
    cudaGetSymbolAddress((void**)&Wih_h,    g_Wih_h);
    cudaGetSymbolAddress((void**)&Whh_h,    g_Whh_h);
    cudaGetSymbolAddress((void**)&rnnin_h,  g_rnnin_h);
    cudaGetSymbolAddress((void**)&hnew_h,   g_hnew_h);
    cudaGetSymbolAddress((void**)&hWa,      g_hWa);
    cudaGetSymbolAddress((void**)&att,      g_att);
    cudaGetSymbolAddress((void**)&gi,       g_gi);
    cudaGetSymbolAddress((void**)&gh,       g_gh);
    cudaGetSymbolAddress((void**)&idx,      g_idx);
    cudaGetSymbolAddress((void**)&cnt,      g_cnt);

    cudaFuncSetAttribute(mma_gemm<0>, cudaFuncAttributeMaxDynamicSharedMemorySize, GTOT);
    cudaFuncSetAttribute(mma_gemm<1>, cudaFuncAttributeMaxDynamicSharedMemorySize, GTOT);

    // one-time stream/event resources (same launch sequence every call)
    static cudaStream_t s1 = nullptr, s2 = nullptr;
    static cudaEvent_t evFork = nullptr, evHh = nullptr, evGh = nullptr, evW = nullptr;
    static cudaEvent_t evEnc[4] = {nullptr, nullptr, nullptr, nullptr};
    if (!s1) {
        cudaStreamCreateWithFlags(&s1, cudaStreamNonBlocking);
        cudaStreamCreateWithFlags(&s2, cudaStreamNonBlocking);
        cudaEventCreateWithFlags(&evFork, cudaEventDisableTiming);
        cudaEventCreateWithFlags(&evHh,   cudaEventDisableTiming);
        cudaEventCreateWithFlags(&evGh,   cudaEventDisableTiming);
        cudaEventCreateWithFlags(&evW,    cudaEventDisableTiming);
        for (int i = 0; i < 4; i++)
            cudaEventCreateWithFlags(&evEnc[i], cudaEventDisableTiming);
    }

    // fork
    cudaEventRecord(evFork, 0);
    cudaStreamWaitEvent(s1, evFork, 0);
    cudaStreamWaitEvent(s2, evFork, 0);

    // s1: enc conversion in 4 slices (s-major row slices)
    {
        const int n4s = (Sq * Bq * Hq) / 4 / 4;
        for (int i = 0; i < 4; i++) {
            f32to16<<<(n4s + 255) / 256, 256, 0, s1>>>(
                enc + (size_t)i * n4s * 4, enc_h + (size_t)i * n4s * 4, n4s);
            cudaEventRecord(evEnc[i], s1);
        }
    }

    // s0: mask compaction + att init + hidden conv + transpose + hWa GEMM
    reset_att<<<(Bq * Sq + 255) / 256, 256>>>(att, cnt);
    scan_mask<<<(Sq * Bq) / 256, 256>>>(mask, idx, cnt);
    {
        int n4 = (Bq * Hq) / 4;
        f32to16<<<(n4 + 255) / 256, 256>>>(hidden, h_h, n4);
        cudaEventRecord(evHh, 0);
    }
    transpose_wa<<<512, 256>>>(Wa, WaTtop_h, WaTbot_h);
    mma_gemm<0><<<dim3(Bq / 128, 1), 256, GTOT>>>(
        h_h, WaTtop_h, ba, hWa, Bq, Hq, Hq,
        nullptr, nullptr, nullptr, nullptr, nullptr);

    // s2: GRU weight conversions, early gh GEMM, then W_out conversion
    {
        int n4 = (3 * Hq * (Eq + Hq)) / 4;
        f32to16<<<(n4 + 255) / 256, 256, 0, s2>>>(W_ih, Wih_h, n4);
        n4 = (3 * Hq * Hq) / 4;
        f32to16<<<(n4 + 255) / 256, 256, 0, s2>>>(W_hh, Whh_h, n4);
        cudaStreamWaitEvent(s2, evHh, 0);
        mma_gemm<0><<<dim3(Bq / 128, 3), 256, GTOT, s2>>>(
            h_h, Whh_h, b_hh, gh, Bq, 3 * Hq, Hq,
            nullptr, nullptr, nullptr, nullptr, nullptr);
        cudaEventRecord(evGh, s2);
        n4 = (Vq * Hq) / 4;
        f32to16<<<(n4 + 255) / 256, 256, 0, s2>>>(W_out, Wout_h, n4);
        cudaEventRecord(evW, s2);
    }

    // s0: mask-compacted att GEMM per slice (fixed grid, early-exit on count)
    for (int i = 0; i < 4; i++) {
        cudaStreamWaitEvent(0, evEnc[i], 0);
        mma_gemm<1><<<dim3(SLICE_CAP / 128, 1), 256, GTOT>>>(
            enc_h, WaTbot_h, nullptr, nullptr, SLICE_CAP, Hq, Hq,
            hWa, v, att, idx + i * SLICE_CAP, cnt + i);
    }

    // softmax + weighted context + embedding gather
    softmax_weighted<<<Bq, 256>>>(att, enc_h, emb, input_loc, rnnin_h);

    // gi = rnn_in @ W_ih^T + b_ih
    mma_gemm<0><<<dim3(Bq / 128, 3), 256, GTOT>>>(
        rnnin_h, Wih_h, b_ih, gi, Bq, 3 * Hq, Eq + Hq,
        nullptr, nullptr, nullptr, nullptr, nullptr);

    // GRU gates (join gh)
    cudaStreamWaitEvent(0, evGh, 0);
    gru_kernel<<<Bq, Hq>>>(gi, gh, hidden, hnew_h, out_h);

    // pred = h_new @ W_out^T + b_out (join W_out conversion)
    cudaStreamWaitEvent(0, evW, 0);
    mma_gemm<0><<<dim3(Bq / 128, (Vq + 255) / 256), 256, GTOT>>>(
        hnew_h, Wout_h, b_out, out_pred, Bq, Vq, Hq,
        nullptr, nullptr, nullptr, nullptr, nullptr);
}

// round 14
// speedup vs baseline: 4.5809x; 1.0013x over previous
#include <cuda_runtime.h>
#include <cuda_fp16.h>
#include <cstdint>
#include <cstddef>

// Problem dims
#define Bq 1024
#define Sq 200
#define Hq 256
#define Eq 128
#define Vq 100000
#define SLICE_S   50            // s per slice
#define SLICE_CAP (SLICE_S * Bq)   // 51200 rows max per slice

// ---------------- scratch (__device__ globals) ---------------------------------
__device__ __half g_enc_h[(size_t)Sq * Bq * Hq];   // 52.4 MB
__device__ __half g_Wout_h[(size_t)Vq * Hq];       // 51.2 MB
__device__ __half g_WaTtop_h[Hq * Hq];
__device__ __half g_WaTbot_h[Hq * Hq];
__device__ __half g_h_h[Bq * Hq];
__device__ __half g_Wih_h[3 * Hq * (Eq + Hq)];
__device__ __half g_Whh_h[3 * Hq * Hq];
__device__ __half g_rnnin_h[Bq * (Eq + Hq)];
__device__ __half g_hnew_h[Bq * Hq];
__device__ float  g_hWa[Bq * Hq];
__device__ float  g_att[Bq * Sq];
__device__ float  g_gi[Bq * 3 * Hq];
__device__ float  g_gh[Bq * 3 * Hq];
__device__ int    g_idx[4 * SLICE_CAP];
__device__ int    g_cnt[4];

// ---------------- helpers ------------------------------------------------------
__device__ __forceinline__ uint32_t f2h2(float x, float y) {
    __half2 h = __floats2half2_rn(x, y);
    return *(uint32_t*)&h;
}

__device__ __forceinline__ uint32_t smem_u32(const void* p) {
    uint32_t a;
    asm("{ .reg .u64 t; cvta.to.shared.u64 t, %1; cvt.u32.u64 %0, t; }"
        : "=r"(a) : "l"(p));
    return a;
}

__device__ __forceinline__ void mma_fp16(float* c,
                                         uint32_t a0, uint32_t a1, uint32_t a2, uint32_t a3,
                                         uint32_t b0, uint32_t b1) {
    asm volatile(
        "mma.sync.aligned.m16n8k16.row.col.f32.f16.f16.f32 "
        "{%0,%1,%2,%3}, {%4,%5,%6,%7}, {%8,%9}, {%0,%1,%2,%3};\n"
        : "+f"(c[0]), "+f"(c[1]), "+f"(c[2]), "+f"(c[3])
        : "r"(a0), "r"(a1), "r"(a2), "r"(a3), "r"(b0), "r"(b1));
}

#define LDMX4(r0, r1, r2, r3, a)                                                \
    asm volatile("ldmatrix.sync.aligned.m8n8.x4.shared.b16 {%0,%1,%2,%3}, [%4];" \
                 : "=r"(r0), "=r"(r1), "=r"(r2), "=r"(r3) : "r"(a))

#define CPA16(dst, src, pred)                                                   \
    asm volatile("cp.async.cg.shared.global [%0], [%1], 16, %2;"                \
                 :: "r"(dst), "l"(src), "r"((pred) ? 16 : 0) : "memory")
#define CPA_COMMIT() asm volatile("cp.async.commit_group;" ::: "memory")
#define CPA_WAIT3()  asm volatile("cp.async.wait_group 3;" ::: "memory")

// ---------------- fp16 NT GEMM: C[M,N] = A[M,K] @ B[N,K]^T (+bias) -------------
// fp16 in, fp32 accumulate/out. Block 128x256 (8 warps of 64x64), K-chunk 32,
// 5-stage cp.async pipeline with 4 chunks in flight (latency ~3 chunk-computes
// of cover). Rows at 80-byte stride: conflict-free ldmatrix.
// M%128==0, K%32==0, N ragged OK.
// FUSE==1: mask-compacted att rows. A-rows gathered via idxp[0..*cntp);
// epilogue writes att[b*Sq+s] = v . tanh(row + hWa[b,:]) for real rows only.
#define ST_A 10240                 // 128 rows * 80 B
#define ST_B 20480                 // 256 rows * 80 B
#define STG  (ST_A + ST_B)         // 30720
#define NSTAGE 5
#define GTOT (NSTAGE * STG)        // 153600

template <int FUSE>
__global__ __launch_bounds__(256, 1)
void mma_gemm(const __half* __restrict__ A, const __half* __restrict__ Bm,
              const float* __restrict__ bias, float* __restrict__ C,
              int M, int N, int K,
              const float* __restrict__ hWa, const float* __restrict__ vvec,
              float* __restrict__ att,
              const int* __restrict__ idxp, const int* __restrict__ cntp) {
    extern __shared__ char smem[];
    const uint32_t sbase = smem_u32(smem);

    const int tid  = threadIdx.x;
    const int lane = tid & 31;
    const int warp = tid >> 5;
    const int wm = (warp >> 2) * 64;
    const int wn = (warp & 3) * 64;
    const int bm = blockIdx.x * 128;
    const int bn = blockIdx.y * 256;
    const int lq = lane >> 2;
    const int lr = lane & 3;

    __shared__ float rowsum[128];
    __shared__ int   sidx[128];

    int cnt_v = 0;
    if (FUSE) {
        cnt_v = *cntp;
        if (bm >= cnt_v) return;
        if (tid < 128) {
            int g = bm + tid;
            sidx[tid] = (g < cnt_v) ? idxp[g] : idxp[0];
            rowsum[tid] = 0.0f;
        }
        __syncthreads();
    }

    // per-thread A source row bases (gathered for FUSE)
    size_t aoffs[2];
    {
        int r0 = tid >> 2;
        if (FUSE) {
            aoffs[0] = (size_t)sidx[r0] * K;
            aoffs[1] = (size_t)sidx[r0 + 64] * K;
        } else {
            aoffs[0] = (size_t)(bm + r0) * K;
            aoffs[1] = (size_t)(bm + r0 + 64) * K;
        }
    }

    // per-lane ldmatrix byte offsets (within a stage)
    const int rin = lane & 7;
    uint32_t a_l[4], b_l[4];
    {
        const int r8   = (lane >> 3) & 1;
        const int kh_a = (lane >> 4) & 1;
        const int n8   = (lane >> 4) & 1;
        const int kh_b = (lane >> 3) & 1;
#pragma unroll
        for (int mf = 0; mf < 4; mf++)
            a_l[mf] = (uint32_t)((wm + mf * 16 + r8 * 8 + rin) * 80 + kh_a * 16);
#pragma unroll
        for (int p2 = 0; p2 < 4; p2++)
            b_l[p2] = (uint32_t)((wn + p2 * 16 + n8 * 8 + rin) * 80 + kh_b * 16);
    }

    float acc[4][8][4];
#pragma unroll
    for (int i = 0; i < 4; i++)
#pragma unroll
        for (int j = 0; j < 8; j++)
#pragma unroll
            for (int k = 0; k < 4; k++) acc[i][j][k] = 0.0f;

    const int nch = K / 32;

#define ISSUE(c)                                                            \
    do {                                                                    \
        const int kc = (c) * 32;                                            \
        const uint32_t sa0 = sbase + ((c) % NSTAGE) * STG;                  \
        const uint32_t sb0 = sa0 + ST_A;                                    \
        _Pragma("unroll")                                                   \
        for (int l = 0; l < 2; l++) {                                       \
            int q = tid + l * 256;                                          \
            int row = q >> 2, seg = q & 3;                                  \
            CPA16(sa0 + row * 80 + seg * 16,                                \
                  A + aoffs[l] + kc + seg * 8, true);                       \
        }                                                                   \
        _Pragma("unroll")                                                   \
        for (int l = 0; l < 4; l++) {                                       \
            int q = tid + l * 256;                                          \
            int row = q >> 2, seg = q & 3;                                  \
            CPA16(sb0 + row * 80 + seg * 16,                                \
                  Bm + (size_t)(bn + row) * K + kc + seg * 8,               \
                  (bn + row) < N);                                          \
        }                                                                   \
    } while (0)

    // prologue: 4 chunks in flight
#pragma unroll
    for (int i = 0; i < 4; i++) {
        if (i < nch) ISSUE(i);
        CPA_COMMIT();
    }

    for (int c = 0; c < nch; c++) {
        CPA_WAIT3();
        __syncthreads();
        if (c + 4 < nch) ISSUE(c + 4);
        CPA_COMMIT();

        const uint32_t aA = sbase + (c % NSTAGE) * STG;
        const uint32_t aB = aA + ST_A;

#pragma unroll
        for (int ks = 0; ks < 2; ks++) {
            uint32_t bf[8][2];
#pragma unroll
            for (int p2 = 0; p2 < 4; p2++)
                LDMX4(bf[2 * p2][0], bf[2 * p2][1], bf[2 * p2 + 1][0], bf[2 * p2 + 1][1],
                      aB + b_l[p2] + ks * 32);
#pragma unroll
            for (int mf = 0; mf < 4; mf++) {
                uint32_t a0, a1, a2, a3;
                LDMX4(a0, a1, a2, a3, aA + a_l[mf] + ks * 32);
#pragma unroll
                for (int nf = 0; nf < 8; nf++)
                    mma_fp16(acc[mf][nf], a0, a1, a2, a3, bf[nf][0], bf[nf][1]);
            }
        }
    }
#undef ISSUE

    if (FUSE) {
        // att epilogue: per-row v . tanh(row + hWa[b,:]); rows from sidx
#pragma unroll
        for (int mf = 0; mf < 4; mf++) {
            int l0 = wm + mf * 16 + lq;
            int b0 = sidx[l0] & (Bq - 1);
            int b1 = sidx[l0 + 8] & (Bq - 1);
            float p0 = 0.0f, p1 = 0.0f;
#pragma unroll
            for (int nf = 0; nf < 8; nf++) {
#pragma unroll
                for (int c2 = 0; c2 < 2; c2++) {
                    int col = wn + nf * 8 + lr * 2 + c2;
                    float vv = vvec[col];
                    p0 += tanhf(acc[mf][nf][c2]     + hWa[b0 * Hq + col]) * vv;
                    p1 += tanhf(acc[mf][nf][2 + c2] + hWa[b1 * Hq + col]) * vv;
                }
            }
            p0 += __shfl_xor_sync(0xffffffffu, p0, 1);
            p0 += __shfl_xor_sync(0xffffffffu, p0, 2);
            p1 += __shfl_xor_sync(0xffffffffu, p1, 1);
            p1 += __shfl_xor_sync(0xffffffffu, p1, 2);
            if (lr == 0) {
                atomicAdd(&rowsum[l0], p0);
                atomicAdd(&rowsum[l0 + 8], p1);
            }
        }
        __syncthreads();
        if (tid < 128 && (bm + tid) < cnt_v) {
            int row = sidx[tid];           // = s*Bq + b
            int s = row >> 10;
            int b = row & (Bq - 1);
            att[b * Sq + s] = rowsum[tid];
        }
    } else {
#pragma unroll
        for (int mf = 0; mf < 4; mf++) {
            int r0 = bm + wm + mf * 16 + lq;
#pragma unroll
            for (int nf = 0; nf < 8; nf++) {
                int col = bn + wn + nf * 8 + lr * 2;
                if (col < N) {
                    float b0 = bias ? bias[col] : 0.0f;
                    float b1 = bias ? bias[col + 1] : 0.0f;
                    *(float2*)(C + (size_t)r0 * N + col) =
                        make_float2(acc[mf][nf][0] + b0, acc[mf][nf][1] + b1);
                    *(float2*)(C + (size_t)(r0 + 8) * N + col) =
                        make_float2(acc[mf][nf][2] + b0, acc[mf][nf][3] + b1);
                }
            }
        }
    }
}

// ---------------- zero slice counters ------------------------------------------
__global__ void zero_cnt(int* __restrict__ cnt) {
    if (threadIdx.x < 4) cnt[threadIdx.x] = 0;
}

// ---------------- mask stream-compaction (per s-slice lists) -------------------
// grid 800 x 256; block covers one s (256 consecutive b) -> slice uniform.
// Masked rows get att = -1e6 here (unmasked rows are written by the att GEMM).
__global__ void scan_mask(const int* __restrict__ mask,
                          int* __restrict__ idx, int* __restrict__ cnt,
                          float* __restrict__ att) {
    int i = blockIdx.x * 256 + threadIdx.x;       // row id = s*Bq + b
    int s = i >> 10;
    int b = i & (Bq - 1);
    bool keep = mask[b * Sq + s] != 0;
    if (!keep) att[b * Sq + s] = -1000000.0f;

    int lane = threadIdx.x & 31, w = threadIdx.x >> 5;
    unsigned bal = __ballot_sync(0xffffffffu, keep);
    int wcnt = __popc(bal);

    __shared__ int wbase[8];
    __shared__ int btot;
    __shared__ int bbase;
    if (threadIdx.x == 0) btot = 0;
    __syncthreads();
    if (lane == 0) wbase[w] = atomicAdd(&btot, wcnt);
    __syncthreads();
    if (threadIdx.x == 0) bbase = atomicAdd(&cnt[s / SLICE_S], btot);
    __syncthreads();
    if (keep) {
        int off = bbase + wbase[w] + __popc(bal & ((1u << lane) - 1u));
        idx[(s / SLICE_S) * SLICE_CAP + off] = i;
    }
}

// ---------------- fp32 -> fp16 convert (n % 4 == 0) ----------------------------
__global__ void f32to16(const float* __restrict__ in, __half* __restrict__ out, int n4) {
    int i = blockIdx.x * 256 + threadIdx.x;
    if (i < n4) {
        float4 f = ((const float4*)in)[i];
        uint2 u;
        u.x = f2h2(f.x, f.y);
        u.y = f2h2(f.z, f.w);
        ((uint2*)out)[i] = u;
    }
}

// ---------------- Wa transpose -> half -----------------------------------------
__global__ void transpose_wa(const float* __restrict__ Wa,
                             __half* __restrict__ top, __half* __restrict__ bot) {
    int idx = blockIdx.x * 256 + threadIdx.x;
    if (idx >= 2 * Hq * Hq) return;
    int k = idx / Hq;
    int n = idx - k * Hq;
    __half val = __float2half_rn(Wa[k * Hq + n]);
    if (k < Hq) top[n * Hq + k] = val;
    else        bot[n * Hq + (k - Hq)] = val;
}

// ---------------- fused softmax + weighted sum + emb gather -> rnn_in ----------
__global__ __launch_bounds__(256)
void softmax_weighted(const float* __restrict__ att,
                      const __half* __restrict__ enc_h,
                      const float* __restrict__ emb,
                      const int* __restrict__ loc,
                      __half* __restrict__ rnn_h) {
    int b = blockIdx.x;
    int t = threadIdx.x;
    __shared__ float satt[Sq];
    __shared__ float red[8];
    __shared__ float4 red4[256];

    float x = (t < Sq) ? att[b * Sq + t] : -3.4e38f;
    int lane = t & 31, w = t >> 5;

    float m = x;
    for (int o = 16; o > 0; o >>= 1) m = fmaxf(m, __shfl_down_sync(0xffffffffu, m, o));
    if (lane == 0) red[w] = m;
    __syncthreads();
    if (t == 0) {
        float mm = red[0];
        for (int i = 1; i < 8; i++) mm = fmaxf(mm, red[i]);
        red[0] = mm;
    }
    __syncthreads();
    m = red[0];
    __syncthreads();

    float e = (t < Sq) ? expf(x - m) : 0.0f;
    float s = e;
    for (int o = 16; o > 0; o >>= 1) s += __shfl_down_sync(0xffffffffu, s, o);
    if (lane == 0) red[w] = s;
    __syncthreads();
    if (t == 0) {
        float ss = 0.0f;
        for (int i = 0; i < 8; i++) ss += red[i];
        red[0] = ss;
    }
    __syncthreads();
    float denom = red[0];
    if (t < Sq) satt[t] = e / denom;
    __syncthreads();

    int sp = t >> 6;
    int hq = t & 63;
    const uint2* enc2 = (const uint2*)enc_h;
    float4 acc = make_float4(0.f, 0.f, 0.f, 0.f);
    for (int si = sp; si < Sq; si += 4) {
        float ww = satt[si];
        uint2 u = enc2[((size_t)si * Bq + b) * 64 + hq];
        float2 f0 = __half22float2(*(__half2*)&u.x);
        float2 f1 = __half22float2(*(__half2*)&u.y);
        acc.x += ww * f0.x; acc.y += ww * f0.y; acc.z += ww * f1.x; acc.w += ww * f1.y;
    }
    red4[t] = acc;
    __syncthreads();

    uint2* rnn2 = (uint2*)(rnn_h + (size_t)b * (Eq + Hq));
    if (t < 64) {
        float4 a0 = red4[t], a1 = red4[64 + t], a2 = red4[128 + t], a3 = red4[192 + t];
        uint2 u;
        u.x = f2h2(a0.x + a1.x + a2.x + a3.x, a0.y + a1.y + a2.y + a3.y);
        u.y = f2h2(a0.z + a1.z + a2.z + a3.z, a0.w + a1.w + a2.w + a3.w);
        rnn2[32 + t] = u;
    } else if (t < 96) {
        float4 f = ((const float4*)emb)[(size_t)loc[b] * 32 + (t - 64)];
        uint2 u;
        u.x = f2h2(f.x, f.y);
        u.y = f2h2(f.z, f.w);
        rnn2[t - 64] = u;
    }
}

// ---------------- GRU gates ----------------------------------------------------
__global__ void gru_kernel(const float* __restrict__ gi, const float* __restrict__ gh,
                           const float* __restrict__ h,
                           __half* __restrict__ hnew_h, float* __restrict__ out_h) {
    int b = blockIdx.x;
    int j = threadIdx.x;
    float ir = gi[b * 768 + j];
    float iz = gi[b * 768 + 256 + j];
    float in = gi[b * 768 + 512 + j];
    float hr = gh[b * 768 + j];
    float hz = gh[b * 768 + 256 + j];
    float hn = gh[b * 768 + 512 + j];
    float r = 1.0f / (1.0f + expf(-(ir + hr)));
    float z = 1.0f / (1.0f + expf(-(iz + hz)));
    float n = tanhf(in + r * hn);
    float hv = h[b * Hq + j];
    float hnv = (1.0f - z) * n + z * hv;
    hnew_h[b * Hq + j] = __float2half_rn(hnv);
    out_h[b * Hq + j] = hnv;
}

// ---------------- launch -------------------------------------------------------
extern "C" void kernel_launch(void* const* d_in, const int* in_sizes, int n_in,
                              void* d_out, int out_size) {
    const int*   input_loc = (const int*)d_in[0];
    const float* hidden    = (const float*)d_in[1];
    const float* enc       = (const float*)d_in[2];
    const int*   mask      = (const int*)d_in[3];
    const float* emb       = (const float*)d_in[4];
    const float* Wa        = (const float*)d_in[5];
    const float* ba        = (const float*)d_in[6];
    const float* v         = (const float*)d_in[7];
    const float* W_ih      = (const float*)d_in[8];
    const float* W_hh      = (const float*)d_in[9];
    const float* b_ih      = (const float*)d_in[10];
    const float* b_hh      = (const float*)d_in[11];
    const float* W_out     = (const float*)d_in[12];
    const float* b_out     = (const float*)d_in[13];
    float* out = (float*)d_out;
    float* out_pred = out;
    float* out_h    = out + (size_t)Bq * Vq;

    __half *enc_h, *Wout_h, *WaTtop_h, *WaTbot_h, *h_h, *Wih_h, *Whh_h, *rnnin_h, *hnew_h;
    float  *hWa, *att, *gi, *gh;
    int    *idx, *cnt;
    cudaGetSymbolAddress((void**)&enc_h,    g_enc_h);
    cudaGetSymbolAddress((void**)&Wout_h,   g_Wout_h);
    cudaGetSymbolAddress((void**)&WaTtop_h, g_WaTtop_h);
    cudaGetSymbolAddress((void**)&WaTbot_h, g_WaTbot_h);
    cudaGetSymbolAddress((void**)&h_h,      g_h_h);
    cudaGetSymbolAddress((void**)&Wih_h,    g_Wih_h);
    cudaGetSymbolAddress((void**)&Whh_h,    g_Whh_h);
    cudaGetSymbolAddress((void**)&rnnin_h,  g_rnnin_h);
    cudaGetSymbolAddress((void**)&hnew_h,   g_hnew_h);
    cudaGetSymbolAddress((void**)&hWa,      g_hWa);
    cudaGetSymbolAddress((void**)&att,      g_att);
    cudaGetSymbolAddress((void**)&gi,       g_gi);
    cudaGetSymbolAddress((void**)&gh,       g_gh);
    cudaGetSymbolAddress((void**)&idx,      g_idx);
    cudaGetSymbolAddress((void**)&cnt,      g_cnt);

    cudaFuncSetAttribute(mma_gemm<0>, cudaFuncAttributeMaxDynamicSharedMemorySize, GTOT);
    cudaFuncSetAttribute(mma_gemm<1>, cudaFuncAttributeMaxDynamicSharedMemorySize, GTOT);

    // one-time stream/event resources (same launch sequence every call)
    static cudaStream_t s1 = nullptr, s2 = nullptr;
    static cudaEvent_t evFork = nullptr, evHh = nullptr, evGh = nullptr, evW = nullptr;
    static cudaEvent_t evEnc[4] = {nullptr, nullptr, nullptr, nullptr};
    if (!s1) {
        cudaStreamCreateWithFlags(&s1, cudaStreamNonBlocking);
        cudaStreamCreateWithFlags(&s2, cudaStreamNonBlocking);
        cudaEventCreateWithFlags(&evFork, cudaEventDisableTiming);
        cudaEventCreateWithFlags(&evHh,   cudaEventDisableTiming);
        cudaEventCreateWithFlags(&evGh,   cudaEventDisableTiming);
        cudaEventCreateWithFlags(&evW,    cudaEventDisableTiming);
        for (int i = 0; i < 4; i++)
            cudaEventCreateWithFlags(&evEnc[i], cudaEventDisableTiming);
    }

    // fork
    cudaEventRecord(evFork, 0);
    cudaStreamWaitEvent(s1, evFork, 0);
    cudaStreamWaitEvent(s2, evFork, 0);

    // s1: enc conversion in 4 slices (s-major row slices)
    {
        const int n4s = (Sq * Bq * Hq) / 4 / 4;
        for (int i = 0; i < 4; i++) {
            f32to16<<<(n4s + 255) / 256, 256, 0, s1>>>(
                enc + (size_t)i * n4s * 4, enc_h + (size_t)i * n4s * 4, n4s);
            cudaEventRecord(evEnc[i], s1);
        }
    }

    // s0: counters + mask compaction + hidden conv + transpose + hWa GEMM
    zero_cnt<<<1, 32>>>(cnt);
    scan_mask<<<(Sq * Bq) / 256, 256>>>(mask, idx, cnt, att);
    {
        int n4 = (Bq * Hq) / 4;
        f32to16<<<(n4 + 255) / 256, 256>>>(hidden, h_h, n4);
        cudaEventRecord(evHh, 0);
    }
    transpose_wa<<<512, 256>>>(Wa, WaTtop_h, WaTbot_h);
    mma_gemm<0><<<dim3(Bq / 128, 1), 256, GTOT>>>(
        h_h, WaTtop_h, ba, hWa, Bq, Hq, Hq,
        nullptr, nullptr, nullptr, nullptr, nullptr);

    // s2: GRU weight conversions, early gh GEMM, then W_out conversion
    {
        int n4 = (3 * Hq * (Eq + Hq)) / 4;
        f32to16<<<(n4 + 255) / 256, 256, 0, s2>>>(W_ih, Wih_h, n4);
        n4 = (3 * Hq * Hq) / 4;
        f32to16<<<(n4 + 255) / 256, 256, 0, s2>>>(W_hh, Whh_h, n4);
        cudaStreamWaitEvent(s2, evHh, 0);
        mma_gemm<0><<<dim3(Bq / 128, 3), 256, GTOT, s2>>>(
            h_h, Whh_h, b_hh, gh, Bq, 3 * Hq, Hq,
            nullptr, nullptr, nullptr, nullptr, nullptr);
        cudaEventRecord(evGh, s2);
        n4 = (Vq * Hq) / 4;
        f32to16<<<(n4 + 255) / 256, 256, 0, s2>>>(W_out, Wout_h, n4);
        cudaEventRecord(evW, s2);
    }

    // s0: mask-compacted att GEMM per slice (fixed grid, early-exit on count)
    for (int i = 0; i < 4; i++) {
        cudaStreamWaitEvent(0, evEnc[i], 0);
        mma_gemm<1><<<dim3(SLICE_CAP / 128, 1), 256, GTOT>>>(
            enc_h, WaTbot_h, nullptr, nullptr, SLICE_CAP, Hq, Hq,
            hWa, v, att, idx + i * SLICE_CAP, cnt + i);
    }

    // softmax + weighted context + embedding gather
    softmax_weighted<<<Bq, 256>>>(att, enc_h, emb, input_loc, rnnin_h);

    // gi = rnn_in @ W_ih^T + b_ih
    mma_gemm<0><<<dim3(Bq / 128, 3), 256, GTOT>>>(
        rnnin_h, Wih_h, b_ih, gi, Bq, 3 * Hq, Eq + Hq,
        nullptr, nullptr, nullptr, nullptr, nullptr);

    // GRU gates (join gh)
    cudaStreamWaitEvent(0, evGh, 0);
    gru_kernel<<<Bq, Hq>>>(gi, gh, hidden, hnew_h, out_h);

    // pred = h_new @ W_out^T + b_out (join W_out conversion)
    cudaStreamWaitEvent(0, evW, 0);
    mma_gemm<0><<<dim3(Bq / 128, (Vq + 255) / 256), 256, GTOT>>>(
        hnew_h, Wout_h, b_out, out_pred, Bq, Vq, Hq,
        nullptr, nullptr, nullptr, nullptr, nullptr);
}

// round 16
// speedup vs baseline: 5.2053x; 1.1363x over previous
#include <cuda_runtime.h>
#include <cuda_fp16.h>
#include <cstdint>
#include <cstddef>

// Problem dims
#define Bq 1024
#define Sq 200
#define Hq 256
#define Eq 128
#define Vq 100000

// ---------------- scratch (__device__ globals) ---------------------------------
__device__ __half g_enc_h[(size_t)Sq * Bq * Hq];   // 52.4 MB (zero-init; only
                                                   // unmasked rows ever written)
__device__ __half g_Wout_h[(size_t)Vq * Hq];       // 51.2 MB
__device__ __half g_WaTtop_h[Hq * Hq];
__device__ __half g_WaTbot_h[Hq * Hq];
__device__ __half g_h_h[Bq * Hq];
__device__ __half g_Wih_h[3 * Hq * (Eq + Hq)];
__device__ __half g_Whh_h[3 * Hq * Hq];
__device__ __half g_rnnin_h[Bq * (Eq + Hq)];
__device__ __half g_hnew_h[Bq * Hq];
__device__ float  g_hWa[Bq * Hq];
__device__ float  g_att[Bq * Sq];
__device__ float  g_gi[Bq * 3 * Hq];
__device__ float  g_gh[Bq * 3 * Hq];
__device__ int    g_idx[Sq * Bq];
__device__ int    g_cnt[4];

// ---------------- helpers ------------------------------------------------------
__device__ __forceinline__ uint32_t f2h2(float x, float y) {
    __half2 h = __floats2half2_rn(x, y);
    return *(uint32_t*)&h;
}

__device__ __forceinline__ uint32_t smem_u32(const void* p) {
    uint32_t a;
    asm("{ .reg .u64 t; cvta.to.shared.u64 t, %1; cvt.u32.u64 %0, t; }"
        : "=r"(a) : "l"(p));
    return a;
}

__device__ __forceinline__ void mma_fp16(float* c,
                                         uint32_t a0, uint32_t a1, uint32_t a2, uint32_t a3,
                                         uint32_t b0, uint32_t b1) {
    asm volatile(
        "mma.sync.aligned.m16n8k16.row.col.f32.f16.f16.f32 "
        "{%0,%1,%2,%3}, {%4,%5,%6,%7}, {%8,%9}, {%0,%1,%2,%3};\n"
        : "+f"(c[0]), "+f"(c[1]), "+f"(c[2]), "+f"(c[3])
        : "r"(a0), "r"(a1), "r"(a2), "r"(a3), "r"(b0), "r"(b1));
}

#define LDMX4(r0, r1, r2, r3, a)                                                \
    asm volatile("ldmatrix.sync.aligned.m8n8.x4.shared.b16 {%0,%1,%2,%3}, [%4];" \
                 : "=r"(r0), "=r"(r1), "=r"(r2), "=r"(r3) : "r"(a))

#define CPA16(dst, src, pred)                                                   \
    asm volatile("cp.async.cg.shared.global [%0], [%1], 16, %2;"                \
                 :: "r"(dst), "l"(src), "r"((pred) ? 16 : 0) : "memory")
#define CPA_COMMIT() asm volatile("cp.async.commit_group;" ::: "memory")
#define CPA_WAIT1()  asm volatile("cp.async.wait_group 1;" ::: "memory")
#define CPA_WAIT3()  asm volatile("cp.async.wait_group 3;" ::: "memory")

// ---------------- generic fp16 NT GEMM (unchanged, proven) ---------------------
// C[M,N] = A[M,K] @ B[N,K]^T (+bias). fp16 in, fp32 acc/out. 128x256 block,
// 8 warps of 64x64, K-chunk 32, 5-stage cp.async. 80-byte row stride.
#define ST_A 10240
#define ST_B 20480
#define STG_SZ (ST_A + ST_B)
#define NSTAGE 5
#define GTOT (NSTAGE * STG_SZ)     // 153600

__global__ __launch_bounds__(256, 1)
void mma_gemm(const __half* __restrict__ A, const __half* __restrict__ Bm,
              const float* __restrict__ bias, float* __restrict__ C,
              int M, int N, int K) {
    extern __shared__ char smem[];
    const uint32_t sbase = smem_u32(smem);

    const int tid  = threadIdx.x;
    const int lane = tid & 31;
    const int warp = tid >> 5;
    const int wm = (warp >> 2) * 64;
    const int wn = (warp & 3) * 64;
    const int bm = blockIdx.x * 128;
    const int bn = blockIdx.y * 256;
    const int lq = lane >> 2;
    const int lr = lane & 3;

    const int rin = lane & 7;
    uint32_t a_l[4], b_l[4];
    {
        const int r8   = (lane >> 3) & 1;
        const int kh_a = (lane >> 4) & 1;
        const int n8   = (lane >> 4) & 1;
        const int kh_b = (lane >> 3) & 1;
#pragma unroll
        for (int mf = 0; mf < 4; mf++)
            a_l[mf] = (uint32_t)((wm + mf * 16 + r8 * 8 + rin) * 80 + kh_a * 16);
#pragma unroll
        for (int p2 = 0; p2 < 4; p2++)
            b_l[p2] = (uint32_t)((wn + p2 * 16 + n8 * 8 + rin) * 80 + kh_b * 16);
    }

    float acc[4][8][4];
#pragma unroll
    for (int i = 0; i < 4; i++)
#pragma unroll
        for (int j = 0; j < 8; j++)
#pragma unroll
            for (int k = 0; k < 4; k++) acc[i][j][k] = 0.0f;

    const int nch = K / 32;

#define ISSUE(c)                                                            \
    do {                                                                    \
        const int kc = (c) * 32;                                            \
        const uint32_t sa0 = sbase + ((c) % NSTAGE) * STG_SZ;               \
        const uint32_t sb0 = sa0 + ST_A;                                    \
        _Pragma("unroll")                                                   \
        for (int l = 0; l < 2; l++) {                                       \
            int q = tid + l * 256;                                          \
            int row = q >> 2, seg = q & 3;                                  \
            CPA16(sa0 + row * 80 + seg * 16,                                \
                  A + (size_t)(bm + row) * K + kc + seg * 8, true);         \
        }                                                                   \
        _Pragma("unroll")                                                   \
        for (int l = 0; l < 4; l++) {                                       \
            int q = tid + l * 256;                                          \
            int row = q >> 2, seg = q & 3;                                  \
            CPA16(sb0 + row * 80 + seg * 16,                                \
                  Bm + (size_t)(bn + row) * K + kc + seg * 8,               \
                  (bn + row) < N);                                          \
        }                                                                   \
    } while (0)

#pragma unroll
    for (int i = 0; i < 4; i++) {
        if (i < nch) ISSUE(i);
        CPA_COMMIT();
    }

    for (int c = 0; c < nch; c++) {
        CPA_WAIT3();
        __syncthreads();
        if (c + 4 < nch) ISSUE(c + 4);
        CPA_COMMIT();

        const uint32_t aA = sbase + (c % NSTAGE) * STG_SZ;
        const uint32_t aB = aA + ST_A;

#pragma unroll
        for (int ks = 0; ks < 2; ks++) {
            uint32_t bf[8][2];
#pragma unroll
            for (int p2 = 0; p2 < 4; p2++)
                LDMX4(bf[2 * p2][0], bf[2 * p2][1], bf[2 * p2 + 1][0], bf[2 * p2 + 1][1],
                      aB + b_l[p2] + ks * 32);
#pragma unroll
            for (int mf = 0; mf < 4; mf++) {
                uint32_t a0, a1, a2, a3;
                LDMX4(a0, a1, a2, a3, aA + a_l[mf] + ks * 32);
#pragma unroll
                for (int nf = 0; nf < 8; nf++)
                    mma_fp16(acc[mf][nf], a0, a1, a2, a3, bf[nf][0], bf[nf][1]);
            }
        }
    }
#undef ISSUE

#pragma unroll
    for (int mf = 0; mf < 4; mf++) {
        int r0 = bm + wm + mf * 16 + lq;
#pragma unroll
        for (int nf = 0; nf < 8; nf++) {
            int col = bn + wn + nf * 8 + lr * 2;
            if (col < N) {
                float b0 = bias ? bias[col] : 0.0f;
                float b1 = bias ? bias[col + 1] : 0.0f;
                *(float2*)(C + (size_t)r0 * N + col) =
                    make_float2(acc[mf][nf][0] + b0, acc[mf][nf][1] + b1);
                *(float2*)(C + (size_t)(r0 + 8) * N + col) =
                    make_float2(acc[mf][nf][2] + b0, acc[mf][nf][3] + b1);
            }
        }
    }
}

// ---------------- att GEMM with in-kernel fp32->fp16 conversion ----------------
// A = enc (fp32), rows gathered via compacted index list. B = WaTbot_h (fp16,
// N=256=full width). Per chunk: cp.async fp32 A stage; convert via smem round
// trip into an 80-stride fp16 operand buffer (also STG to enc_h for the later
// weighted-sum kernel); then the standard ldmatrix+mma. Epilogue computes
// att[b,s] = v . tanh(row + hWa[b,:]).
#define A32_STRIDE 144
#define ST_A32 (128 * A32_STRIDE)          // 18432
#define ATT_A16   0
#define ATT_A32_0 10240
#define ATT_B16_0 (ATT_A32_0 + 3 * ST_A32) // 65536
#define ATT_TOT   (ATT_B16_0 + 3 * ST_B)   // 126976

__global__ __launch_bounds__(256, 1)
void att_gemm(const float* __restrict__ Aenc, const __half* __restrict__ Bm,
              __half* __restrict__ enc_h,
              const float* __restrict__ hWa, const float* __restrict__ vvec,
              float* __restrict__ att,
              const int* __restrict__ idxp, const int* __restrict__ cntp) {
    extern __shared__ char smem[];
    const uint32_t sbase = smem_u32(smem);
    const int K = Hq;                       // 256

    const int tid  = threadIdx.x;
    const int lane = tid & 31;
    const int warp = tid >> 5;
    const int wm = (warp >> 2) * 64;
    const int wn = (warp & 3) * 64;
    const int bm = blockIdx.x * 128;
    const int lq = lane >> 2;
    const int lr = lane & 3;

    __shared__ float rowsum[128];
    __shared__ int   sidx[128];

    const int cnt_v = *cntp;
    if (bm >= cnt_v) return;
    if (tid < 128) {
        int g = bm + tid;
        sidx[tid] = (g < cnt_v) ? idxp[g] : idxp[0];
        rowsum[tid] = 0.0f;
    }
    __syncthreads();

    // A cp.async roles: 4/thread; q=tid+l*256 -> row=q>>3 (0..127), seg=q&7
    size_t arow_off[4];
#pragma unroll
    for (int l = 0; l < 4; l++) {
        int q = tid + l * 256;
        arow_off[l] = (size_t)sidx[q >> 3] * K;
    }
    // convert role: row = tid>>1, half = tid&1 (16 floats each)
    const int crow = tid >> 1;
    const int chh  = tid & 1;
    const size_t grow_off = (size_t)sidx[crow] * K;

    // ldmatrix per-lane offsets
    const int rin = lane & 7;
    uint32_t a_l[4], b_l[4];
    {
        const int r8   = (lane >> 3) & 1;
        const int kh_a = (lane >> 4) & 1;
        const int n8   = (lane >> 4) & 1;
        const int kh_b = (lane >> 3) & 1;
#pragma unroll
        for (int mf = 0; mf < 4; mf++)
            a_l[mf] = (uint32_t)((wm + mf * 16 + r8 * 8 + rin) * 80 + kh_a * 16);
#pragma unroll
        for (int p2 = 0; p2 < 4; p2++)
            b_l[p2] = (uint32_t)((wn + p2 * 16 + n8 * 8 + rin) * 80 + kh_b * 16);
    }

    float acc[4][8][4];
#pragma unroll
    for (int i = 0; i < 4; i++)
#pragma unroll
        for (int j = 0; j < 8; j++)
#pragma unroll
            for (int k = 0; k < 4; k++) acc[i][j][k] = 0.0f;

    const int nch = K / 32;                 // 8

#define AISSUE(c)                                                           \
    do {                                                                    \
        const int kc = (c) * 32;                                            \
        const uint32_t a32 = sbase + ATT_A32_0 + ((c) % 3) * ST_A32;        \
        const uint32_t b16 = sbase + ATT_B16_0 + ((c) % 3) * ST_B;          \
        _Pragma("unroll")                                                   \
        for (int l = 0; l < 4; l++) {                                       \
            int q = tid + l * 256;                                          \
            int row = q >> 3, seg = q & 7;                                  \
            CPA16(a32 + row * A32_STRIDE + seg * 16,                        \
                  Aenc + arow_off[l] + kc + seg * 4, true);                 \
        }                                                                   \
        _Pragma("unroll")                                                   \
        for (int l = 0; l < 4; l++) {                                       \
            int q = tid + l * 256;                                          \
            int row = q >> 2, seg = q & 3;                                  \
            CPA16(b16 + row * 80 + seg * 16,                                \
                  Bm + (size_t)row * K + kc + seg * 8, true);               \
        }                                                                   \
    } while (0)

    AISSUE(0); CPA_COMMIT();
    AISSUE(1); CPA_COMMIT();

    for (int c = 0; c < nch; c++) {
        CPA_WAIT1();
        __syncthreads();
        if (c + 2 < nch) AISSUE(c + 2);
        CPA_COMMIT();

        // convert this chunk's A: fp32 stage -> fp16 operand (+ enc_h store)
        {
            const int kc = c * 32;
            const char* src = smem + ATT_A32_0 + (c % 3) * ST_A32
                              + crow * A32_STRIDE + chh * 64;
            float4 f0 = *(const float4*)(src);
            float4 f1 = *(const float4*)(src + 16);
            float4 f2 = *(const float4*)(src + 32);
            float4 f3 = *(const float4*)(src + 48);
            uint4 h0, h1;
            h0.x = f2h2(f0.x, f0.y); h0.y = f2h2(f0.z, f0.w);
            h0.z = f2h2(f1.x, f1.y); h0.w = f2h2(f1.z, f1.w);
            h1.x = f2h2(f2.x, f2.y); h1.y = f2h2(f2.z, f2.w);
            h1.z = f2h2(f3.x, f3.y); h1.w = f2h2(f3.z, f3.w);
            char* dst = smem + ATT_A16 + crow * 80 + chh * 32;
            *(uint4*)(dst) = h0;
            *(uint4*)(dst + 16) = h1;
            __half* gdst = enc_h + grow_off + kc + chh * 16;
            *(uint4*)(gdst) = h0;
            *(uint4*)(gdst + 0) = h0;           // (idempotent)
            *(uint4*)((char*)gdst + 16) = h1;
        }
        __syncthreads();

        const uint32_t aA = sbase + ATT_A16;
        const uint32_t aB = sbase + ATT_B16_0 + (c % 3) * ST_B;

#pragma unroll
        for (int ks = 0; ks < 2; ks++) {
            uint32_t bf[8][2];
#pragma unroll
            for (int p2 = 0; p2 < 4; p2++)
                LDMX4(bf[2 * p2][0], bf[2 * p2][1], bf[2 * p2 + 1][0], bf[2 * p2 + 1][1],
                      aB + b_l[p2] + ks * 32);
#pragma unroll
            for (int mf = 0; mf < 4; mf++) {
                uint32_t a0, a1, a2, a3;
                LDMX4(a0, a1, a2, a3, aA + a_l[mf] + ks * 32);
#pragma unroll
                for (int nf = 0; nf < 8; nf++)
                    mma_fp16(acc[mf][nf], a0, a1, a2, a3, bf[nf][0], bf[nf][1]);
            }
        }
    }
#undef AISSUE

    // epilogue: att[b,s] = v . tanh(row + hWa[b,:])
#pragma unroll
    for (int mf = 0; mf < 4; mf++) {
        int l0 = wm + mf * 16 + lq;
        int b0 = sidx[l0] & (Bq - 1);
        int b1 = sidx[l0 + 8] & (Bq - 1);
        float p0 = 0.0f, p1 = 0.0f;
#pragma unroll
        for (int nf = 0; nf < 8; nf++) {
#pragma unroll
            for (int c2 = 0; c2 < 2; c2++) {
                int col = wn + nf * 8 + lr * 2 + c2;
                float vv = vvec[col];
                p0 += tanhf(acc[mf][nf][c2]     + hWa[b0 * Hq + col]) * vv;
                p1 += tanhf(acc[mf][nf][2 + c2] + hWa[b1 * Hq + col]) * vv;
            }
        }
        p0 += __shfl_xor_sync(0xffffffffu, p0, 1);
        p0 += __shfl_xor_sync(0xffffffffu, p0, 2);
        p1 += __shfl_xor_sync(0xffffffffu, p1, 1);
        p1 += __shfl_xor_sync(0xffffffffu, p1, 2);
        if (lr == 0) {
            atomicAdd(&rowsum[l0], p0);
            atomicAdd(&rowsum[l0 + 8], p1);
        }
    }
    __syncthreads();
    if (tid < 128 && (bm + tid) < cnt_v) {
        int row = sidx[tid];               // = s*Bq + b
        int s = row >> 10;
        int b = row & (Bq - 1);
        att[b * Sq + s] = rowsum[tid];
    }
}

// ---------------- zero counters ------------------------------------------------
__global__ void zero_cnt(int* __restrict__ cnt) {
    if (threadIdx.x < 4) cnt[threadIdx.x] = 0;
}

// ---------------- mask stream-compaction (single list) -------------------------
__global__ void scan_mask(const int* __restrict__ mask,
                          int* __restrict__ idx, int* __restrict__ cnt,
                          float* __restrict__ att) {
    int i = blockIdx.x * 256 + threadIdx.x;       // row id = s*Bq + b
    int s = i >> 10;
    int b = i & (Bq - 1);
    bool keep = mask[b * Sq + s] != 0;
    if (!keep) att[b * Sq + s] = -1000000.0f;

    int lane = threadIdx.x & 31, w = threadIdx.x >> 5;
    unsigned bal = __ballot_sync(0xffffffffu, keep);
    int wcnt = __popc(bal);

    __shared__ int wbase[8];
    __shared__ int btot;
    __shared__ int bbase;
    if (threadIdx.x == 0) btot = 0;
    __syncthreads();
    if (lane == 0) wbase[w] = atomicAdd(&btot, wcnt);
    __syncthreads();
    if (threadIdx.x == 0) bbase = atomicAdd(&cnt[0], btot);
    __syncthreads();
    if (keep) {
        int off = bbase + wbase[w] + __popc(bal & ((1u << lane) - 1u));
        idx[off] = i;
    }
}

// ---------------- fp32 -> fp16 convert (n % 4 == 0) ----------------------------
__global__ void f32to16(const float* __restrict__ in, __half* __restrict__ out, int n4) {
    int i = blockIdx.x * 256 + threadIdx.x;
    if (i < n4) {
        float4 f = ((const float4*)in)[i];
        uint2 u;
        u.x = f2h2(f.x, f.y);
        u.y = f2h2(f.z, f.w);
        ((uint2*)out)[i] = u;
    }
}

// ---------------- Wa transpose -> half -----------------------------------------
__global__ void transpose_wa(const float* __restrict__ Wa,
                             __half* __restrict__ top, __half* __restrict__ bot) {
    int idx = blockIdx.x * 256 + threadIdx.x;
    if (idx >= 2 * Hq * Hq) return;
    int k = idx / Hq;
    int n = idx - k * Hq;
    __half val = __float2half_rn(Wa[k * Hq + n]);
    if (k < Hq) top[n * Hq + k] = val;
    else        bot[n * Hq + (k - Hq)] = val;
}

// ---------------- fused softmax + weighted sum + emb gather -> rnn_in ----------
// Masked s rows of enc_h are all-zero (never written) and their softmax weight
// is exactly 0, so their contribution is exactly 0.
__global__ __launch_bounds__(256)
void softmax_weighted(const float* __restrict__ att,
                      const __half* __restrict__ enc_h,
                      const float* __restrict__ emb,
                      const int* __restrict__ loc,
                      __half* __restrict__ rnn_h) {
    int b = blockIdx.x;
    int t = threadIdx.x;
    __shared__ float satt[Sq];
    __shared__ float red[8];
    __shared__ float4 red4[256];

    float x = (t < Sq) ? att[b * Sq + t] : -3.4e38f;
    int lane = t & 31, w = t >> 5;

    float m = x;
    for (int o = 16; o > 0; o >>= 1) m = fmaxf(m, __shfl_down_sync(0xffffffffu, m, o));
    if (lane == 0) red[w] = m;
    __syncthreads();
    if (t == 0) {
        float mm = red[0];
        for (int i = 1; i < 8; i++) mm = fmaxf(mm, red[i]);
        red[0] = mm;
    }
    __syncthreads();
    m = red[0];
    __syncthreads();

    float e = (t < Sq) ? expf(x - m) : 0.0f;
    float s = e;
    for (int o = 16; o > 0; o >>= 1) s += __shfl_down_sync(0xffffffffu, s, o);
    if (lane == 0) red[w] = s;
    __syncthreads();
    if (t == 0) {
        float ss = 0.0f;
        for (int i = 0; i < 8; i++) ss += red[i];
        red[0] = ss;
    }
    __syncthreads();
    float denom = red[0];
    if (t < Sq) satt[t] = e / denom;
    __syncthreads();

    int sp = t >> 6;
    int hq = t & 63;
    const uint2* enc2 = (const uint2*)enc_h;
    float4 acc = make_float4(0.f, 0.f, 0.f, 0.f);
    for (int si = sp; si < Sq; si += 4) {
        float ww = satt[si];
        uint2 u = enc2[((size_t)si * Bq + b) * 64 + hq];
        float2 f0 = __half22float2(*(__half2*)&u.x);
        float2 f1 = __half22float2(*(__half2*)&u.y);
        acc.x += ww * f0.x; acc.y += ww * f0.y; acc.z += ww * f1.x; acc.w += ww * f1.y;
    }
    red4[t] = acc;
    __syncthreads();

    uint2* rnn2 = (uint2*)(rnn_h + (size_t)b * (Eq + Hq));
    if (t < 64) {
        float4 a0 = red4[t], a1 = red4[64 + t], a2 = red4[128 + t], a3 = red4[192 + t];
        uint2 u;
        u.x = f2h2(a0.x + a1.x + a2.x + a3.x, a0.y + a1.y + a2.y + a3.y);
        u.y = f2h2(a0.z + a1.z + a2.z + a3.z, a0.w + a1.w + a2.w + a3.w);
        rnn2[32 + t] = u;
    } else if (t < 96) {
        float4 f = ((const float4*)emb)[(size_t)loc[b] * 32 + (t - 64)];
        uint2 u;
        u.x = f2h2(f.x, f.y);
        u.y = f2h2(f.z, f.w);
        rnn2[t - 64] = u;
    }
}

// ---------------- GRU gates ----------------------------------------------------
__global__ void gru_kernel(const float* __restrict__ gi, const float* __restrict__ gh,
                           const float* __restrict__ h,
                           __half* __restrict__ hnew_h, float* __restrict__ out_h) {
    int b = blockIdx.x;
    int j = threadIdx.x;
    float ir = gi[b * 768 + j];
    float iz = gi[b * 768 + 256 + j];
    float in = gi[b * 768 + 512 + j];
    float hr = gh[b * 768 + j];
    float hz = gh[b * 768 + 256 + j];
    float hn = gh[b * 768 + 512 + j];
    float r = 1.0f / (1.0f + expf(-(ir + hr)));
    float z = 1.0f / (1.0f + expf(-(iz + hz)));
    float n = tanhf(in + r * hn);
    float hv = h[b * Hq + j];
    float hnv = (1.0f - z) * n + z * hv;
    hnew_h[b * Hq + j] = __float2half_rn(hnv);
    out_h[b * Hq + j] = hnv;
}

// ---------------- launch -------------------------------------------------------
extern "C" void kernel_launch(void* const* d_in, const int* in_sizes, int n_in,
                              void* d_out, int out_size) {
    const int*   input_loc = (const int*)d_in[0];
    const float* hidden    = (const float*)d_in[1];
    const float* enc       = (const float*)d_in[2];
    const int*   mask      = (const int*)d_in[3];
    const float* emb       = (const float*)d_in[4];
    const float* Wa        = (const float*)d_in[5];
    const float* ba        = (const float*)d_in[6];
    const float* v         = (const float*)d_in[7];
    const float* W_ih      = (const float*)d_in[8];
    const float* W_hh      = (const float*)d_in[9];
    const float* b_ih      = (const float*)d_in[10];
    const float* b_hh      = (const float*)d_in[11];
    const float* W_out     = (const float*)d_in[12];
    const float* b_out     = (const float*)d_in[13];
    float* out = (float*)d_out;
    float* out_pred = out;
    float* out_h    = out + (size_t)Bq * Vq;

    __half *enc_h, *Wout_h, *WaTtop_h, *WaTbot_h, *h_h, *Wih_h, *Whh_h, *rnnin_h, *hnew_h;
    float  *hWa, *att, *gi, *gh;
    int    *idx, *cnt;
    cudaGetSymbolAddress((void**)&enc_h,    g_enc_h);
    cudaGetSymbolAddress((void**)&Wout_h,   g_Wout_h);
    cudaGetSymbolAddress((void**)&WaTtop_h, g_WaTtop_h);
    cudaGetSymbolAddress((void**)&WaTbot_h, g_WaTbot_h);
    cudaGetSymbolAddress((void**)&h_h,      g_h_h);
    cudaGetSymbolAddress((void**)&Wih_h,    g_Wih_h);
    cudaGetSymbolAddress((void**)&Whh_h,    g_Whh_h);
    cudaGetSymbolAddress((void**)&rnnin_h,  g_rnnin_h);
    cudaGetSymbolAddress((void**)&hnew_h,   g_hnew_h);
    cudaGetSymbolAddress((void**)&hWa,      g_hWa);
    cudaGetSymbolAddress((void**)&att,      g_att);
    cudaGetSymbolAddress((void**)&gi,       g_gi);
    cudaGetSymbolAddress((void**)&gh,       g_gh);
    cudaGetSymbolAddress((void**)&idx,      g_idx);
    cudaGetSymbolAddress((void**)&cnt,      g_cnt);

    cudaFuncSetAttribute(mma_gemm, cudaFuncAttributeMaxDynamicSharedMemorySize, GTOT);
    cudaFuncSetAttribute(att_gemm, cudaFuncAttributeMaxDynamicSharedMemorySize, ATT_TOT);

    static cudaStream_t s2 = nullptr;
    static cudaEvent_t evFork = nullptr, evPre = nullptr, evHwa = nullptr;
    static cudaEvent_t evGh = nullptr, evW = nullptr;
    if (!s2) {
        cudaStreamCreateWithFlags(&s2, cudaStreamNonBlocking);
        cudaEventCreateWithFlags(&evFork, cudaEventDisableTiming);
        cudaEventCreateWithFlags(&evPre,  cudaEventDisableTiming);
        cudaEventCreateWithFlags(&evHwa,  cudaEventDisableTiming);
        cudaEventCreateWithFlags(&evGh,   cudaEventDisableTiming);
        cudaEventCreateWithFlags(&evW,    cudaEventDisableTiming);
    }

    // fork
    cudaEventRecord(evFork, 0);
    cudaStreamWaitEvent(s2, evFork, 0);

    // s0: h conversion + Wa transpose (prereqs for hWa on s2)
    {
        int n4 = (Bq * Hq) / 4;
        f32to16<<<(n4 + 255) / 256, 256>>>(hidden, h_h, n4);
    }
    transpose_wa<<<512, 256>>>(Wa, WaTtop_h, WaTbot_h);
    cudaEventRecord(evPre, 0);

    // s0: mask compaction (overlaps hWa on s2)
    zero_cnt<<<1, 32>>>(cnt);
    scan_mask<<<(Sq * Bq) / 256, 256>>>(mask, idx, cnt, att);

    // s2: hWa GEMM, then GRU weight conversions, gh GEMM, W_out conversion
    {
        cudaStreamWaitEvent(s2, evPre, 0);
        mma_gemm<<<dim3(Bq / 128, 1), 256, GTOT, s2>>>(
            h_h, WaTtop_h, ba, hWa, Bq, Hq, Hq);
        cudaEventRecord(evHwa, s2);
        int n4 = (3 * Hq * (Eq + Hq)) / 4;
        f32to16<<<(n4 + 255) / 256, 256, 0, s2>>>(W_ih, Wih_h, n4);
        n4 = (3 * Hq * Hq) / 4;
        f32to16<<<(n4 + 255) / 256, 256, 0, s2>>>(W_hh, Whh_h, n4);
        mma_gemm<<<dim3(Bq / 128, 3), 256, GTOT, s2>>>(
            h_h, Whh_h, b_hh, gh, Bq, 3 * Hq, Hq);
        cudaEventRecord(evGh, s2);
        n4 = (Vq * Hq) / 4;
        f32to16<<<(n4 + 255) / 256, 256, 0, s2>>>(W_out, Wout_h, n4);
        cudaEventRecord(evW, s2);
    }

    // s0: fused attention GEMM (fp32 enc in, conversion inside)
    cudaStreamWaitEvent(0, evHwa, 0);
    att_gemm<<<dim3((Sq * Bq) / 128, 1), 256, ATT_TOT>>>(
        enc, WaTbot_h, enc_h, hWa, v, att, idx, cnt);

    // softmax + weighted context + embedding gather
    softmax_weighted<<<Bq, 256>>>(att, enc_h, emb, input_loc, rnnin_h);

    // gi = rnn_in @ W_ih^T + b_ih
    mma_gemm<<<dim3(Bq / 128, 3), 256, GTOT>>>(
        rnnin_h, Wih_h, b_ih, gi, Bq, 3 * Hq, Eq + Hq);

    // GRU gates (join gh)
    cudaStreamWaitEvent(0, evGh, 0);
    gru_kernel<<<Bq, Hq>>>(gi, gh, hidden, hnew_h, out_h);

    // pred = h_new @ W_out^T + b_out (join W_out conversion)
    cudaStreamWaitEvent(0, evW, 0);
    mma_gemm<<<dim3(Bq / 128, (Vq + 255) / 256), 256, GTOT>>>(
        hnew_h, Wout_h, b_out, out_pred, Bq, Vq, Hq);
}